// round 4
// baseline (speedup 1.0000x reference)
#include <cuda_runtime.h>
#include <math.h>
#include <stdint.h>

// Problem constants
#define NB   16
#define NT   512
#define NC   128
#define NDM  512
#define NL   3
#define NKS  25
#define NM   (NB*NC)       // 2048 rows
#define NH   (2*NDM)       // 1024 FFN hidden

// Scratch (device globals: no allocation allowed)
__device__ float g_R  [NM*NT];
__device__ float g_X  [NM*NDM];
__device__ float g_B1 [NM*NH];
__device__ float g_B2 [NM*NDM];
__device__ float g_B3 [NM*NDM];
__device__ float g_S  [NM];
__device__ float g_W  [NB*NC*NC];     // varcor softmax weights
__device__ float g_WQK[NL*NDM*NDM];
__device__ float g_CV [NL*NDM];

// ===========================================================================
// tf32 warp-MMA GEMM: C[m,n] = sum_k A[m,k]*W[n,k] + epilogue
// BM=64, BN=64, BK=32, 128 threads (4 warps 2x2, warp tile 32x32, m16n8k8).
// Grid: 256 blocks (N=512) / 512 blocks (N=1024) -> 4-5 blocks/SM resident.
// ===========================================================================
enum { EPI_NONE = 0, EPI_BIAS, EPI_BIAS_WPOS, EPI_BIAS_GELU, EPI_BIAS_RES, EPI_BIAS_RES_BN };

#define BM 64
#define BN 64
#define BK 32
#define ROWW 36                      // padded row stride (words); banks (4g+tg)%32 distinct
#define A_STG (BM*ROWW)              // 2304 words / stage
#define B_STG (BN*ROWW)

__device__ __forceinline__ float to_tf32(float x) {
    uint32_t u;
    asm("cvt.rna.tf32.f32 %0, %1;" : "=r"(u) : "f"(x));
    return __uint_as_float(u);
}
__device__ __forceinline__ void mma8(float (&d)[4], const uint32_t (&a)[4], const uint32_t (&b)[2]) {
    asm volatile("mma.sync.aligned.m16n8k8.row.col.f32.tf32.tf32.f32 "
                 "{%0,%1,%2,%3}, {%4,%5,%6,%7}, {%8,%9}, {%0,%1,%2,%3};"
                 : "+f"(d[0]), "+f"(d[1]), "+f"(d[2]), "+f"(d[3])
                 : "r"(a[0]), "r"(a[1]), "r"(a[2]), "r"(a[3]), "r"(b[0]), "r"(b[1]));
}

template<int EPI>
__global__ __launch_bounds__(128)
void mma_gemm(const float* __restrict__ A, const float* __restrict__ W,
              const float* __restrict__ bias, const float* __restrict__ extra,
              const float* __restrict__ bng, const float* __restrict__ bnb,
              float* __restrict__ C, int M, int N, int K) {
    extern __shared__ float sm[];
    float* AsB = sm;                 // [2][BM][ROWW]
    float* BsB = sm + 2 * A_STG;     // [2][BN][ROWW]

    int tid = threadIdx.x, wid = tid >> 5, lane = tid & 31;
    int g = lane >> 2, tg = lane & 3;
    int wm = wid & 1, wn = wid >> 1;
    int m0 = blockIdx.y * BM, n0 = blockIdx.x * BN;

    float c[2][4][4];
    #pragma unroll
    for (int i = 0; i < 2; i++)
        #pragma unroll
        for (int j = 0; j < 4; j++)
            #pragma unroll
            for (int q = 0; q < 4; q++) c[i][j][q] = 0.f;

    float4 ra[4], rb[4];
    const int KC = K / BK;

    // ---- LDG chunk 0 ----
    {
        const float* ap = A + (size_t)m0 * K;
        const float* bp = W + (size_t)n0 * K;
        #pragma unroll
        for (int i = 0; i < 4; i++) {
            int f = tid + i * 128;
            ra[i] = *(const float4*)(ap + (size_t)(f >> 3) * K + (f & 7) * 4);
            rb[i] = *(const float4*)(bp + (size_t)(f >> 3) * K + (f & 7) * 4);
        }
    }

    for (int kc = 0; kc < KC; kc++) {
        // ---- STS (rna-rounded) ----
        {
            float* as = AsB + (kc & 1) * A_STG;
            float* bs = BsB + (kc & 1) * B_STG;
            #pragma unroll
            for (int i = 0; i < 4; i++) {
                int f = tid + i * 128;
                float4 v = ra[i];
                *(float4*)(as + (f >> 3) * ROWW + (f & 7) * 4) =
                    make_float4(to_tf32(v.x), to_tf32(v.y), to_tf32(v.z), to_tf32(v.w));
                float4 w4 = rb[i];
                *(float4*)(bs + (f >> 3) * ROWW + (f & 7) * 4) =
                    make_float4(to_tf32(w4.x), to_tf32(w4.y), to_tf32(w4.z), to_tf32(w4.w));
            }
        }
        __syncthreads();

        // ---- prefetch next chunk ----
        if (kc + 1 < KC) {
            const float* ap = A + (size_t)m0 * K + (kc + 1) * BK;
            const float* bp = W + (size_t)n0 * K + (kc + 1) * BK;
            #pragma unroll
            for (int i = 0; i < 4; i++) {
                int f = tid + i * 128;
                ra[i] = *(const float4*)(ap + (size_t)(f >> 3) * K + (f & 7) * 4);
                rb[i] = *(const float4*)(bp + (size_t)(f >> 3) * K + (f & 7) * 4);
            }
        }

        // ---- compute chunk ----
        {
            const float* as = AsB + (kc & 1) * A_STG;
            const float* bs = BsB + (kc & 1) * B_STG;
            #pragma unroll
            for (int ks = 0; ks < 4; ks++) {
                int kb = ks * 8;
                uint32_t af[2][4], bf[4][2];
                #pragma unroll
                for (int mi = 0; mi < 2; mi++) {
                    const float* base = as + (wm * 32 + mi * 16 + g) * ROWW + kb;
                    af[mi][0] = __float_as_uint(base[tg]);
                    af[mi][1] = __float_as_uint(base[8 * ROWW + tg]);
                    af[mi][2] = __float_as_uint(base[tg + 4]);
                    af[mi][3] = __float_as_uint(base[8 * ROWW + tg + 4]);
                }
                #pragma unroll
                for (int nj = 0; nj < 4; nj++) {
                    const float* base = bs + (wn * 32 + nj * 8 + g) * ROWW + kb;
                    bf[nj][0] = __float_as_uint(base[tg]);
                    bf[nj][1] = __float_as_uint(base[tg + 4]);
                }
                #pragma unroll
                for (int mi = 0; mi < 2; mi++)
                    #pragma unroll
                    for (int nj = 0; nj < 4; nj++) mma8(c[mi][nj], af[mi], bf[nj]);
            }
        }
        __syncthreads();
    }

    // ---- epilogue ----
    const float invs = 0.9999950000374997f;   // 1/sqrt(1+1e-5) eval-mode BN
    int mBase = m0 + wm * 32, nBase = n0 + wn * 32;
    #pragma unroll
    for (int mi = 0; mi < 2; mi++) {
        #pragma unroll
        for (int half = 0; half < 2; half++) {
            int m = mBase + mi * 16 + g + half * 8;
            float bsc = 1.f, bof = 0.f;
            if (EPI == EPI_BIAS_RES_BN) { bsc = bng[m & (NC - 1)] * invs; bof = bnb[m & (NC - 1)]; }
            #pragma unroll
            for (int nj = 0; nj < 4; nj++) {
                int n = nBase + nj * 8 + tg * 2;
                float x0 = c[mi][nj][half * 2 + 0];
                float x1 = c[mi][nj][half * 2 + 1];
                if (EPI != EPI_NONE) { x0 += bias[n]; x1 += bias[n + 1]; }
                if (EPI == EPI_BIAS_WPOS) {
                    const float* e = extra + (size_t)(m & (NC - 1)) * N + n;
                    x0 += e[0]; x1 += e[1];
                }
                if (EPI == EPI_BIAS_RES || EPI == EPI_BIAS_RES_BN) {
                    const float* e = extra + (size_t)m * N + n;
                    x0 += e[0]; x1 += e[1];
                }
                if (EPI == EPI_BIAS_GELU) {
                    x0 = 0.5f * x0 * (1.f + erff(x0 * 0.7071067811865475f));
                    x1 = 0.5f * x1 * (1.f + erff(x1 * 0.7071067811865475f));
                }
                if (EPI == EPI_BIAS_RES_BN) { x0 = x0 * bsc + bof; x1 = x1 * bsc + bof; }
                *(float2*)(C + (size_t)m * N + n) = make_float2(x0, x1);
            }
        }
    }
}

// ===========================================================================
// Auto-attn precompute (x-independent):
// Bop[n,k] = sum_j Wk[j,n]*Wq[j,k]  ;  cv[n] = sum_j bq[j]*Wk[j,n]
// ===========================================================================
__global__ void wqk_kernel(const float* __restrict__ Wq, const float* __restrict__ Wk,
                           float* __restrict__ Bop) {
    __shared__ float sk[16][68], sq[16][68];
    int l = blockIdx.z;
    const float* wq = Wq + (size_t)l * NDM * NDM;
    const float* wk = Wk + (size_t)l * NDM * NDM;
    float* bo = Bop + (size_t)l * NDM * NDM;
    int n0 = blockIdx.x * 64, k0 = blockIdx.y * 64;
    int tid = threadIdx.x, tx = tid & 15, ty = tid >> 4;
    float acc[4][4] = {};
    for (int j0 = 0; j0 < NDM; j0 += 16) {
        int jr = tid >> 4, qc = (tid & 15) * 4;
        *(float4*)&sk[jr][qc] = *(const float4*)(wk + (size_t)(j0 + jr) * NDM + n0 + qc);
        *(float4*)&sq[jr][qc] = *(const float4*)(wq + (size_t)(j0 + jr) * NDM + k0 + qc);
        __syncthreads();
        #pragma unroll
        for (int jj = 0; jj < 16; jj++) {
            float a[4], b[4];
            #pragma unroll
            for (int i = 0; i < 4; i++) a[i] = sk[jj][ty * 4 + i];
            #pragma unroll
            for (int j = 0; j < 4; j++) b[j] = sq[jj][tx * 4 + j];
            #pragma unroll
            for (int i = 0; i < 4; i++)
                #pragma unroll
                for (int j = 0; j < 4; j++) acc[i][j] = fmaf(a[i], b[j], acc[i][j]);
        }
        __syncthreads();
    }
    #pragma unroll
    for (int i = 0; i < 4; i++) {
        float4 v = make_float4(acc[i][0], acc[i][1], acc[i][2], acc[i][3]);
        *(float4*)(bo + (size_t)(n0 + ty * 4 + i) * NDM + k0 + tx * 4) = v;
    }
}
__global__ void bqk_kernel(const float* __restrict__ bq, const float* __restrict__ Wk,
                           float* __restrict__ cv) {
    int l = blockIdx.y;
    const float* b  = bq + l * NDM;
    const float* wk = Wk + (size_t)l * NDM * NDM;
    int n = blockIdx.x * 128 + threadIdx.x;
    float s = 0.f;
    for (int j = 0; j < NDM; j++) s = fmaf(b[j], wk[(size_t)j * NDM + n], s);
    cv[l * NDM + n] = s;
}

// ===========================================================================
// trend conv + residual (replicate pad, ks=25) with transpose to (B,C,T)
// ===========================================================================
__global__ void conv_residual_kernel(const float* __restrict__ inp,
                                     const float* __restrict__ w,
                                     const float* __restrict__ ldb,
                                     float* __restrict__ R) {
    __shared__ float s[88][33];
    __shared__ float wk[NKS];
    int b = blockIdx.x, t0 = blockIdx.y * 64, c0 = blockIdx.z * 32;
    int tid = threadIdx.x;
    if (tid < NKS) wk[tid] = w[tid];
    for (int idx = tid; idx < 88 * 32; idx += 256) {
        int r = idx >> 5, c = idx & 31;
        int tg = t0 + r - 12;
        tg = min(max(tg, 0), NT - 1);
        s[r][c] = inp[((size_t)b * NT + tg) * NC + c0 + c];
    }
    __syncthreads();
    float lb = ldb[0];
    int lane = tid & 31, wy = tid >> 5;
    for (int half = 0; half < 2; ++half) {
        int ti = half * 32 + lane;
        for (int cg = 0; cg < 4; ++cg) {
            int ci = cg * 8 + wy;
            float acc = 0.f;
            #pragma unroll
            for (int k = 0; k < NKS; ++k) acc = fmaf(wk[k], s[ti + k][ci], acc);
            float v = s[ti + 12][ci] - (acc + lb);
            R[((size_t)b * NC + c0 + ci) * NT + t0 + ti] = v;
        }
    }
}

// ===========================================================================
// row sums (for varcor rank-1 logits) — only used after the embedding GEMM
// ===========================================================================
__global__ void rowsum_kernel(const float* __restrict__ X, float* __restrict__ S) {
    int row = blockIdx.x * 8 + (threadIdx.x >> 5);
    int lane = threadIdx.x & 31;
    const float* xr = X + (size_t)row * NDM;
    float s = 0.f;
    for (int i = lane; i < NDM; i += 32) s += xr[i];
    #pragma unroll
    for (int o = 16; o; o >>= 1) s += __shfl_xor_sync(0xffffffffu, s, o);
    if (!lane) S[row] = s;
}

// ===========================================================================
// varcor softmax weights: Wt[b,d,e] = softmax_e((S_d*S_e - mx)*VS)
// ===========================================================================
__global__ void varcor_w_kernel(const float* __restrict__ S, float* __restrict__ Wt) {
    __shared__ float ss[NC];
    int b = blockIdx.x, d = threadIdx.x;
    ss[d] = S[b * NC + d];
    __syncthreads();
    const float VS = 8.6316746e-05f;            // 1/(512*sqrt(512))
    float sd = ss[d];
    float mx = -1e30f;
    #pragma unroll 8
    for (int e = 0; e < NC; e++) mx = fmaxf(mx, sd * ss[e]);
    float sum = 0.f;
    #pragma unroll 8
    for (int e = 0; e < NC; e++) sum += __expf((sd * ss[e] - mx) * VS);
    float rs = 1.f / sum;
    float* wr = Wt + ((size_t)b * NC + d) * NC;
    #pragma unroll 8
    for (int e = 0; e < NC; e++) wr[e] = __expf((sd * ss[e] - mx) * VS) * rs;
}

// ===========================================================================
// varcor mix: y[b,d,:] = sum_e Wt[b,d,e] * x[b,e,:]; then (+x)*BN affine.
// grid (B, DM/64), 512 threads: d = tid>>2, 16 cols each.
// ===========================================================================
__global__ __launch_bounds__(512)
void varcor_mix_kernel(const float* __restrict__ X, const float* __restrict__ Wt,
                       const float* __restrict__ bng, const float* __restrict__ bnb,
                       float* __restrict__ Out) {
    __shared__ float xs[NC][64];
    int b = blockIdx.x, j0 = blockIdx.y * 64;
    int tid = threadIdx.x;
    const float* xb = X + (size_t)b * NC * NDM;
    #pragma unroll
    for (int i = 0; i < 4; i++) {
        int f = tid + i * 512;           // 2048 float4 total
        int e = f >> 4, q = f & 15;
        *(float4*)&xs[e][q * 4] = ((const float4*)(xb + (size_t)e * NDM + j0))[q];
    }
    __syncthreads();

    int d = tid >> 2, q = tid & 3, jb = q * 16;
    const float* wr = Wt + ((size_t)b * NC + d) * NC;
    float4 acc[4];
    #pragma unroll
    for (int t = 0; t < 4; t++) acc[t] = make_float4(0.f, 0.f, 0.f, 0.f);
    #pragma unroll 4
    for (int e = 0; e < NC; e++) {
        float w = __ldg(wr + e);
        #pragma unroll
        for (int t = 0; t < 4; t++) {
            float4 xv = *(float4*)&xs[e][jb + t * 4];
            acc[t].x = fmaf(w, xv.x, acc[t].x);
            acc[t].y = fmaf(w, xv.y, acc[t].y);
            acc[t].z = fmaf(w, xv.z, acc[t].z);
            acc[t].w = fmaf(w, xv.w, acc[t].w);
        }
    }
    const float invs = 0.9999950000374997f;
    float bsc = bng[d] * invs, bof = bnb[d];
    float* orow = Out + ((size_t)b * NC + d) * NDM + j0 + jb;
    #pragma unroll
    for (int t = 0; t < 4; t++) {
        float4 xv = *(float4*)&xs[d][jb + t * 4];
        float4 o;
        o.x = (acc[t].x + xv.x) * bsc + bof;
        o.y = (acc[t].y + xv.y) * bsc + bof;
        o.z = (acc[t].z + xv.z) * bsc + bof;
        o.w = (acc[t].w + xv.w) * bsc + bof;
        *(float4*)(orow + t * 4) = o;
    }
}

// ===========================================================================
// auto-attn shift scores + softmax + weighted shift sum
// ===========================================================================
__global__ void autoshift_kernel(const float* __restrict__ X, const float* __restrict__ U,
                                 float* __restrict__ XW) {
    __shared__ float xr[NDM];
    __shared__ float red[8][4];
    int row = blockIdx.x, tid = threadIdx.x;
    const float4 xv = ((const float4*)(X + (size_t)row * NDM))[tid];
    ((float4*)xr)[tid] = xv;
    const float4 uv = ((const float4*)(U + (size_t)row * NDM))[tid];
    __syncthreads();

    float sc[8];
    #pragma unroll
    for (int s = 0; s < 8; s++) {
        float4 x4 = ((float4*)xr)[(tid + 16 * s) & 127];
        sc[s] = uv.x * x4.x + uv.y * x4.y + uv.z * x4.z + uv.w * x4.w;
    }
    int lane = tid & 31, wid = tid >> 5;
    #pragma unroll
    for (int s = 0; s < 8; s++) {
        float v = sc[s];
        #pragma unroll
        for (int o = 16; o; o >>= 1) v += __shfl_xor_sync(0xffffffffu, v, o);
        if (!lane) red[s][wid] = v;
    }
    __syncthreads();
    const float rsq = 0.04419417382415922f;    // DM^-0.5
    float lg[8], mx = -1e30f;
    #pragma unroll
    for (int s = 0; s < 8; s++) {
        lg[s] = (red[s][0] + red[s][1] + red[s][2] + red[s][3]) * rsq;
        mx = fmaxf(mx, lg[s]);
    }
    float w[8], sum = 0.f;
    #pragma unroll
    for (int s = 0; s < 8; s++) { w[s] = __expf(lg[s] - mx); sum += w[s]; }
    float rs = 1.f / sum;
    float4 o = make_float4(0.f, 0.f, 0.f, 0.f);
    #pragma unroll
    for (int s = 0; s < 8; s++) {
        float4 x4 = ((float4*)xr)[(tid + 16 * s) & 127];
        float ws = w[s] * rs;
        o.x = fmaf(ws, x4.x, o.x); o.y = fmaf(ws, x4.y, o.y);
        o.z = fmaf(ws, x4.z, o.z); o.w = fmaf(ws, x4.w, o.w);
    }
    ((float4*)(XW + (size_t)row * NDM))[tid] = o;
}

// ===========================================================================
// LayerNorm over last axis (512); optional fused rowsum of the OUTPUT.
// ===========================================================================
template<bool SUM>
__global__ void layernorm_kernel(const float* __restrict__ In, const float* __restrict__ g,
                                 const float* __restrict__ bb, float* __restrict__ Out,
                                 float* __restrict__ S) {
    int row = blockIdx.x, tid = threadIdx.x;
    const float4 v = ((const float4*)(In + (size_t)row * NDM))[tid];
    float s  = v.x + v.y + v.z + v.w;
    float s2 = v.x * v.x + v.y * v.y + v.z * v.z + v.w * v.w;
    #pragma unroll
    for (int o = 16; o; o >>= 1) {
        s  += __shfl_xor_sync(0xffffffffu, s, o);
        s2 += __shfl_xor_sync(0xffffffffu, s2, o);
    }
    __shared__ float ws[4], ws2[4], wo[4];
    int lane = tid & 31, wid = tid >> 5;
    if (!lane) { ws[wid] = s; ws2[wid] = s2; }
    __syncthreads();
    s  = ws[0] + ws[1] + ws[2] + ws[3];
    s2 = ws2[0] + ws2[1] + ws2[2] + ws2[3];
    float mean = s * (1.f / NDM);
    float var  = s2 * (1.f / NDM) - mean * mean;
    float inv  = rsqrtf(var + 1e-5f);
    float4 gv = ((const float4*)g)[tid], bv = ((const float4*)bb)[tid];
    float4 o;
    o.x = (v.x - mean) * inv * gv.x + bv.x;
    o.y = (v.y - mean) * inv * gv.y + bv.y;
    o.z = (v.z - mean) * inv * gv.z + bv.z;
    o.w = (v.w - mean) * inv * gv.w + bv.w;
    ((float4*)(Out + (size_t)row * NDM))[tid] = o;
    if (SUM) {
        float os = o.x + o.y + o.z + o.w;
        #pragma unroll
        for (int off = 16; off; off >>= 1) os += __shfl_xor_sync(0xffffffffu, os, off);
        if (!lane) wo[wid] = os;
        __syncthreads();
        if (tid == 0) S[row] = wo[0] + wo[1] + wo[2] + wo[3];
    }
}

// ===========================================================================
extern "C" void kernel_launch(void* const* d_in, const int* in_sizes, int n_in,
                              void* d_out, int out_size) {
    (void)in_sizes; (void)n_in; (void)out_size;
    const float* inp     = (const float*)d_in[0];
    const float* ld_w    = (const float*)d_in[1];
    const float* ld_b    = (const float*)d_in[2];
    const float* emb_W   = (const float*)d_in[3];
    const float* emb_b   = (const float*)d_in[4];
    const float* W_pos   = (const float*)d_in[5];
    const float* vc_bn_g = (const float*)d_in[6];
    const float* vc_bn_b = (const float*)d_in[7];
    const float* vc_ln_g = (const float*)d_in[8];
    const float* vc_ln_b = (const float*)d_in[9];
    const float* vc_W1   = (const float*)d_in[10];
    const float* vc_b1   = (const float*)d_in[11];
    const float* vc_W2   = (const float*)d_in[12];
    const float* vc_b2   = (const float*)d_in[13];
    const float* aa_Wq   = (const float*)d_in[14];
    const float* aa_bq   = (const float*)d_in[15];
    const float* aa_Wk   = (const float*)d_in[16];
    // d_in[17] = aa_bk: cancels in the shift-softmax (constant logit offset)
    const float* aa_Wv   = (const float*)d_in[18];
    const float* aa_bv   = (const float*)d_in[19];
    const float* aa_Wo   = (const float*)d_in[20];
    const float* aa_bo   = (const float*)d_in[21];
    const float* aa_bn_g = (const float*)d_in[22];
    const float* aa_bn_b = (const float*)d_in[23];
    const float* aa_ln_g = (const float*)d_in[24];
    const float* aa_ln_b = (const float*)d_in[25];
    const float* aa_W1   = (const float*)d_in[26];
    const float* aa_b1   = (const float*)d_in[27];
    const float* aa_W2   = (const float*)d_in[28];
    const float* aa_b2   = (const float*)d_in[29];

    float *R, *X, *B1, *B2, *B3, *S, *WT, *WQK, *CV;
    cudaGetSymbolAddress((void**)&R,   g_R);
    cudaGetSymbolAddress((void**)&X,   g_X);
    cudaGetSymbolAddress((void**)&B1,  g_B1);
    cudaGetSymbolAddress((void**)&B2,  g_B2);
    cudaGetSymbolAddress((void**)&B3,  g_B3);
    cudaGetSymbolAddress((void**)&S,   g_S);
    cudaGetSymbolAddress((void**)&WT,  g_W);
    cudaGetSymbolAddress((void**)&WQK, g_WQK);
    cudaGetSymbolAddress((void**)&CV,  g_CV);
    float* OUT = (float*)d_out;

    const int SMEM = 2 * (A_STG + B_STG) * 4;    // 36864 bytes (< 48KB default)

    dim3 g512(NDM / BN, NM / BM);    // (8,32)  = 256 blocks
    dim3 g1024(NH / BN, NM / BM);    // (16,32) = 512 blocks

    // trend conv + residual (transposed to (B,C,T))
    conv_residual_kernel<<<dim3(NB, NT / 64, NC / 32), 256>>>(inp, ld_w, ld_b, R);
    // auto-attn precompute (x-independent, all layers)
    wqk_kernel<<<dim3(8, 8, NL), 256>>>(aa_Wq, aa_Wk, WQK);
    bqk_kernel<<<dim3(4, NL), 128>>>(aa_bq, aa_Wk, CV);
    // embedding: X = R @ emb_W.T + emb_b + W_pos
    mma_gemm<EPI_BIAS_WPOS><<<g512, 128, SMEM>>>(R, emb_W, emb_b, W_pos,
                                                 nullptr, nullptr, X, NM, NDM, NT);
    rowsum_kernel<<<NM / 8, 256>>>(X, S);

    for (int l = 0; l < NL; ++l) {
        const size_t SS = (size_t)NDM * NDM, SH = (size_t)NH * NDM;
        // ---- VarCor block ----
        varcor_w_kernel<<<NB, NC>>>(S, WT);
        varcor_mix_kernel<<<dim3(NB, NDM / 64), 512>>>(X, WT, vc_bn_g + l * NC, vc_bn_b + l * NC, B2);
        mma_gemm<EPI_BIAS_GELU><<<g1024, 128, SMEM>>>(B2, vc_W1 + l * SH, vc_b1 + l * NH,
                                                      nullptr, nullptr, nullptr, B1, NM, NH, NDM);
        mma_gemm<EPI_BIAS_RES><<<g512, 128, SMEM>>>(B1, vc_W2 + l * SH, vc_b2 + l * NDM,
                                                    B2, nullptr, nullptr, B3, NM, NDM, NH);
        layernorm_kernel<false><<<NM, 128>>>(B3, vc_ln_g + l * NDM, vc_ln_b + l * NDM, X, nullptr);

        // ---- Auto-attention block ----
        // u = x @ (Wq^T Wk) + bq@Wk   (single fused GEMM, NT layout)
        mma_gemm<EPI_BIAS><<<g512, 128, SMEM>>>(X, WQK + l * SS, CV + l * NDM,
                                                nullptr, nullptr, nullptr, B3, NM, NDM, NDM);
        autoshift_kernel<<<NM, 128>>>(X, B3, B2);
        mma_gemm<EPI_BIAS><<<g512, 128, SMEM>>>(B2, aa_Wv + l * SS, aa_bv + l * NDM,
                                                nullptr, nullptr, nullptr, B3, NM, NDM, NDM);
        mma_gemm<EPI_BIAS_RES_BN><<<g512, 128, SMEM>>>(B3, aa_Wo + l * SS, aa_bo + l * NDM,
                                                       X, aa_bn_g + l * NC, aa_bn_b + l * NC,
                                                       B2, NM, NDM, NDM);
        mma_gemm<EPI_BIAS_GELU><<<g1024, 128, SMEM>>>(B2, aa_W1 + l * SH, aa_b1 + l * NH,
                                                      nullptr, nullptr, nullptr, B1, NM, NH, NDM);
        mma_gemm<EPI_BIAS_RES><<<g512, 128, SMEM>>>(B1, aa_W2 + l * SH, aa_b2 + l * NDM,
                                                    B2, nullptr, nullptr, B3, NM, NDM, NH);
        if (l == NL - 1) {
            layernorm_kernel<false><<<NM, 128>>>(B3, aa_ln_g + l * NDM, aa_ln_b + l * NDM, OUT, nullptr);
        } else {
            layernorm_kernel<true><<<NM, 128>>>(B3, aa_ln_g + l * NDM, aa_ln_b + l * NDM, X, S);
        }
    }
}

// round 5
// speedup vs baseline: 1.0621x; 1.0621x over previous
#include <cuda_runtime.h>
#include <cuda_fp16.h>
#include <math.h>
#include <stdint.h>

// Problem constants
#define NB   16
#define NT   512
#define NC   128
#define NDM  512
#define NL   3
#define NKS  25
#define NM   (NB*NC)       // 2048 rows
#define NH   (2*NDM)       // 1024 FFN hidden

// Scratch (device globals: no allocation allowed)
__device__ float g_R  [NM*NT];
__device__ float g_X  [NM*NDM];
__device__ float g_B1 [NM*NH];
__device__ float g_B2 [NM*NDM];
__device__ float g_B3 [NM*NDM];
__device__ float g_S  [NM];
__device__ float g_W  [NB*NC*NC];     // varcor softmax weights
__device__ float g_WQK[NL*NDM*NDM];
__device__ float g_CV [NL*NDM];

// ===========================================================================
// fp16 warp-MMA GEMM: C[m,n] = sum_k A[m,k]*W[n,k] + epilogue (fp32 accum)
// BM=64, BN=64, BK=32; 128 threads = 4 warps (2x2), warp tile 32x32.
// m16n8k16 mma fed by ldmatrix.x4; smem rows padded to 80B (conflict-free).
// ===========================================================================
enum { EPI_NONE = 0, EPI_BIAS, EPI_BIAS_WPOS, EPI_BIAS_GELU, EPI_BIAS_RES, EPI_BIAS_RES_BN };

#define BMg 64
#define BNg 64
#define BKg 32
#define ROWB 80                       // bytes per smem row (32 halves + pad)
#define TILEB (64*ROWB)               // 5120 bytes per tile
#define STGB  (2*TILEB)               // A+B per stage = 10240 bytes

__device__ __forceinline__ uint32_t smem_u32(const void* p) {
    uint32_t a;
    asm("{ .reg .u64 t; cvta.to.shared.u64 t, %1; cvt.u32.u64 %0, t; }" : "=r"(a) : "l"(p));
    return a;
}
__device__ __forceinline__ uint32_t f2h2(float a, float b) {
    __half2 h = __float22half2_rn(make_float2(a, b));
    uint32_t u;
    __builtin_memcpy(&u, &h, 4);
    return u;
}
__device__ __forceinline__ void ldsm4(uint32_t& r0, uint32_t& r1, uint32_t& r2, uint32_t& r3,
                                      uint32_t addr) {
    asm volatile("ldmatrix.sync.aligned.m8n8.x4.shared.b16 {%0,%1,%2,%3}, [%4];"
                 : "=r"(r0), "=r"(r1), "=r"(r2), "=r"(r3) : "r"(addr));
}
__device__ __forceinline__ void mma16(float (&d)[4], const uint32_t (&a)[4], const uint32_t (&b)[2]) {
    asm volatile("mma.sync.aligned.m16n8k16.row.col.f32.f16.f16.f32 "
                 "{%0,%1,%2,%3}, {%4,%5,%6,%7}, {%8,%9}, {%0,%1,%2,%3};"
                 : "+f"(d[0]), "+f"(d[1]), "+f"(d[2]), "+f"(d[3])
                 : "r"(a[0]), "r"(a[1]), "r"(a[2]), "r"(a[3]), "r"(b[0]), "r"(b[1]));
}

template<int EPI>
__global__ __launch_bounds__(128, 4)
void mma_gemm(const float* __restrict__ A, const float* __restrict__ W,
              const float* __restrict__ bias, const float* __restrict__ extra,
              const float* __restrict__ bng, const float* __restrict__ bnb,
              float* __restrict__ C, int M, int N, int K) {
    __shared__ __align__(16) char sh[2 * STGB];   // 20 KB
    const uint32_t sbase = smem_u32(sh);

    int tid = threadIdx.x, wid = tid >> 5, lane = tid & 31;
    int g = lane >> 2, tg = lane & 3;
    int wm = wid & 1, wn = wid >> 1;
    int m0 = blockIdx.y * BMg, n0 = blockIdx.x * BNg;

    float c[2][4][4];
    #pragma unroll
    for (int i = 0; i < 2; i++)
        #pragma unroll
        for (int j = 0; j < 4; j++)
            #pragma unroll
            for (int q = 0; q < 4; q++) c[i][j][q] = 0.f;

    // per-thread LDG/STS geometry (tile 64 rows x 32 cols, 512 float4 loads)
    const int lr = tid >> 3, lq = tid & 7;          // +i*16 rows per i

    // ldmatrix per-warp lane addressing (byte offsets within a tile)
    const int lt = lane >> 3, lr8 = lane & 7;
    // A frag (mi): row = wm*32 + mi*16 + (lt&1)*8 + lr8 ; col16 = (lt>>1)*8
    const uint32_t aRowOff = (uint32_t)((wm * 32 + (lt & 1) * 8 + lr8) * ROWB + (lt >> 1) * 16);
    // B frag pair (h): row = wn*32 + h*16 + (lt>>1)*8 + lr8 ; col16 = (lt&1)*8
    const uint32_t bRowOff = (uint32_t)((wn * 32 + (lt >> 1) * 8 + lr8) * ROWB + (lt & 1) * 16);

    uint2 ha[4], hb[4];
    const int KC = K / BKg;

    // ---- LDG+convert chunk 0 ----
    {
        const float* ap = A + (size_t)m0 * K;
        const float* bp = W + (size_t)n0 * K;
        #pragma unroll
        for (int i = 0; i < 4; i++) {
            float4 v = *(const float4*)(ap + (size_t)(lr + i * 16) * K + lq * 4);
            ha[i] = make_uint2(f2h2(v.x, v.y), f2h2(v.z, v.w));
            float4 w = *(const float4*)(bp + (size_t)(lr + i * 16) * K + lq * 4);
            hb[i] = make_uint2(f2h2(w.x, w.y), f2h2(w.z, w.w));
        }
    }

    for (int kc = 0; kc < KC; kc++) {
        const uint32_t sOff = (kc & 1) * STGB;
        // ---- STS ----
        {
            char* as = sh + sOff;
            char* bs = as + TILEB;
            #pragma unroll
            for (int i = 0; i < 4; i++) {
                *(uint2*)(as + (lr + i * 16) * ROWB + lq * 8) = ha[i];
                *(uint2*)(bs + (lr + i * 16) * ROWB + lq * 8) = hb[i];
            }
        }
        __syncthreads();

        // ---- prefetch next chunk ----
        if (kc + 1 < KC) {
            const float* ap = A + (size_t)m0 * K + (kc + 1) * BKg;
            const float* bp = W + (size_t)n0 * K + (kc + 1) * BKg;
            #pragma unroll
            for (int i = 0; i < 4; i++) {
                float4 v = *(const float4*)(ap + (size_t)(lr + i * 16) * K + lq * 4);
                ha[i] = make_uint2(f2h2(v.x, v.y), f2h2(v.z, v.w));
                float4 w = *(const float4*)(bp + (size_t)(lr + i * 16) * K + lq * 4);
                hb[i] = make_uint2(f2h2(w.x, w.y), f2h2(w.z, w.w));
            }
        }

        // ---- compute: 2 k16-steps, 8 mma each ----
        {
            const uint32_t sA = sbase + sOff;
            const uint32_t sB = sA + TILEB;
            #pragma unroll
            for (int ks = 0; ks < 2; ks++) {
                uint32_t af[2][4], bf[4][2];
                #pragma unroll
                for (int mi = 0; mi < 2; mi++)
                    ldsm4(af[mi][0], af[mi][1], af[mi][2], af[mi][3],
                          sA + aRowOff + mi * (16 * ROWB) + ks * 32);
                #pragma unroll
                for (int h = 0; h < 2; h++) {
                    uint32_t r0, r1, r2, r3;
                    ldsm4(r0, r1, r2, r3, sB + bRowOff + h * (16 * ROWB) + ks * 32);
                    bf[2 * h][0] = r0; bf[2 * h][1] = r1;
                    bf[2 * h + 1][0] = r2; bf[2 * h + 1][1] = r3;
                }
                #pragma unroll
                for (int mi = 0; mi < 2; mi++)
                    #pragma unroll
                    for (int nj = 0; nj < 4; nj++) mma16(c[mi][nj], af[mi], bf[nj]);
            }
        }
        __syncthreads();
    }

    // ---- epilogue ----
    const float invs = 0.9999950000374997f;   // 1/sqrt(1+1e-5) eval-mode BN
    int mBase = m0 + wm * 32, nBase = n0 + wn * 32;
    #pragma unroll
    for (int mi = 0; mi < 2; mi++) {
        #pragma unroll
        for (int half = 0; half < 2; half++) {
            int m = mBase + mi * 16 + g + half * 8;
            float bsc = 1.f, bof = 0.f;
            if (EPI == EPI_BIAS_RES_BN) { bsc = bng[m & (NC - 1)] * invs; bof = bnb[m & (NC - 1)]; }
            #pragma unroll
            for (int nj = 0; nj < 4; nj++) {
                int n = nBase + nj * 8 + tg * 2;
                float x0 = c[mi][nj][half * 2 + 0];
                float x1 = c[mi][nj][half * 2 + 1];
                if (EPI != EPI_NONE) { x0 += bias[n]; x1 += bias[n + 1]; }
                if (EPI == EPI_BIAS_WPOS) {
                    const float* e = extra + (size_t)(m & (NC - 1)) * N + n;
                    x0 += e[0]; x1 += e[1];
                }
                if (EPI == EPI_BIAS_RES || EPI == EPI_BIAS_RES_BN) {
                    const float* e = extra + (size_t)m * N + n;
                    x0 += e[0]; x1 += e[1];
                }
                if (EPI == EPI_BIAS_GELU) {
                    x0 = 0.5f * x0 * (1.f + erff(x0 * 0.7071067811865475f));
                    x1 = 0.5f * x1 * (1.f + erff(x1 * 0.7071067811865475f));
                }
                if (EPI == EPI_BIAS_RES_BN) { x0 = x0 * bsc + bof; x1 = x1 * bsc + bof; }
                *(float2*)(C + (size_t)m * N + n) = make_float2(x0, x1);
            }
        }
    }
}

// ===========================================================================
// Auto-attn precompute (x-independent):
// Bop[n,k] = sum_j Wk[j,n]*Wq[j,k]  ;  cv[n] = sum_j bq[j]*Wk[j,n]
// ===========================================================================
__global__ void wqk_kernel(const float* __restrict__ Wq, const float* __restrict__ Wk,
                           float* __restrict__ Bop) {
    __shared__ float sk[16][68], sq[16][68];
    int l = blockIdx.z;
    const float* wq = Wq + (size_t)l * NDM * NDM;
    const float* wk = Wk + (size_t)l * NDM * NDM;
    float* bo = Bop + (size_t)l * NDM * NDM;
    int n0 = blockIdx.x * 64, k0 = blockIdx.y * 64;
    int tid = threadIdx.x, tx = tid & 15, ty = tid >> 4;
    float acc[4][4] = {};
    for (int j0 = 0; j0 < NDM; j0 += 16) {
        int jr = tid >> 4, qc = (tid & 15) * 4;
        *(float4*)&sk[jr][qc] = *(const float4*)(wk + (size_t)(j0 + jr) * NDM + n0 + qc);
        *(float4*)&sq[jr][qc] = *(const float4*)(wq + (size_t)(j0 + jr) * NDM + k0 + qc);
        __syncthreads();
        #pragma unroll
        for (int jj = 0; jj < 16; jj++) {
            float a[4], b[4];
            #pragma unroll
            for (int i = 0; i < 4; i++) a[i] = sk[jj][ty * 4 + i];
            #pragma unroll
            for (int j = 0; j < 4; j++) b[j] = sq[jj][tx * 4 + j];
            #pragma unroll
            for (int i = 0; i < 4; i++)
                #pragma unroll
                for (int j = 0; j < 4; j++) acc[i][j] = fmaf(a[i], b[j], acc[i][j]);
        }
        __syncthreads();
    }
    #pragma unroll
    for (int i = 0; i < 4; i++) {
        float4 v = make_float4(acc[i][0], acc[i][1], acc[i][2], acc[i][3]);
        *(float4*)(bo + (size_t)(n0 + ty * 4 + i) * NDM + k0 + tx * 4) = v;
    }
}
__global__ void bqk_kernel(const float* __restrict__ bq, const float* __restrict__ Wk,
                           float* __restrict__ cv) {
    int l = blockIdx.y;
    const float* b  = bq + l * NDM;
    const float* wk = Wk + (size_t)l * NDM * NDM;
    int n = blockIdx.x * 128 + threadIdx.x;
    float s = 0.f;
    for (int j = 0; j < NDM; j++) s = fmaf(b[j], wk[(size_t)j * NDM + n], s);
    cv[l * NDM + n] = s;
}

// ===========================================================================
// trend conv + residual (replicate pad, ks=25) with transpose to (B,C,T)
// ===========================================================================
__global__ void conv_residual_kernel(const float* __restrict__ inp,
                                     const float* __restrict__ w,
                                     const float* __restrict__ ldb,
                                     float* __restrict__ R) {
    __shared__ float s[88][33];
    __shared__ float wk[NKS];
    int b = blockIdx.x, t0 = blockIdx.y * 64, c0 = blockIdx.z * 32;
    int tid = threadIdx.x;
    if (tid < NKS) wk[tid] = w[tid];
    for (int idx = tid; idx < 88 * 32; idx += 256) {
        int r = idx >> 5, c = idx & 31;
        int tg = t0 + r - 12;
        tg = min(max(tg, 0), NT - 1);
        s[r][c] = inp[((size_t)b * NT + tg) * NC + c0 + c];
    }
    __syncthreads();
    float lb = ldb[0];
    int lane = tid & 31, wy = tid >> 5;
    for (int half = 0; half < 2; ++half) {
        int ti = half * 32 + lane;
        for (int cg = 0; cg < 4; ++cg) {
            int ci = cg * 8 + wy;
            float acc = 0.f;
            #pragma unroll
            for (int k = 0; k < NKS; ++k) acc = fmaf(wk[k], s[ti + k][ci], acc);
            float v = s[ti + 12][ci] - (acc + lb);
            R[((size_t)b * NC + c0 + ci) * NT + t0 + ti] = v;
        }
    }
}

// ===========================================================================
// row sums (varcor rank-1 logits) — used once after the embedding GEMM
// ===========================================================================
__global__ void rowsum_kernel(const float* __restrict__ X, float* __restrict__ S) {
    int row = blockIdx.x * 8 + (threadIdx.x >> 5);
    int lane = threadIdx.x & 31;
    const float* xr = X + (size_t)row * NDM;
    float s = 0.f;
    for (int i = lane; i < NDM; i += 32) s += xr[i];
    #pragma unroll
    for (int o = 16; o; o >>= 1) s += __shfl_xor_sync(0xffffffffu, s, o);
    if (!lane) S[row] = s;
}

// ===========================================================================
// varcor softmax weights: Wt[b,d,e] = softmax_e((S_d*S_e)*VS)
// ===========================================================================
__global__ void varcor_w_kernel(const float* __restrict__ S, float* __restrict__ Wt) {
    __shared__ float ss[NC];
    int b = blockIdx.x, d = threadIdx.x;
    ss[d] = S[b * NC + d];
    __syncthreads();
    const float VS = 8.6316746e-05f;            // 1/(512*sqrt(512))
    float sd = ss[d];
    float mx = -1e30f;
    #pragma unroll 8
    for (int e = 0; e < NC; e++) mx = fmaxf(mx, sd * ss[e]);
    float sum = 0.f;
    #pragma unroll 8
    for (int e = 0; e < NC; e++) sum += __expf((sd * ss[e] - mx) * VS);
    float rs = 1.f / sum;
    float* wr = Wt + ((size_t)b * NC + d) * NC;
    #pragma unroll 8
    for (int e = 0; e < NC; e++) wr[e] = __expf((sd * ss[e] - mx) * VS) * rs;
}

// ===========================================================================
// varcor mix: y[b,d,:] = sum_e Wt[b,d,e]*x[b,e,:]; then (+x)*BN affine.
// ===========================================================================
__global__ __launch_bounds__(512)
void varcor_mix_kernel(const float* __restrict__ X, const float* __restrict__ Wt,
                       const float* __restrict__ bng, const float* __restrict__ bnb,
                       float* __restrict__ Out) {
    __shared__ float xs[NC][64];
    int b = blockIdx.x, j0 = blockIdx.y * 64;
    int tid = threadIdx.x;
    const float* xb = X + (size_t)b * NC * NDM;
    #pragma unroll
    for (int i = 0; i < 4; i++) {
        int f = tid + i * 512;           // 2048 float4 total
        int e = f >> 4, q = f & 15;
        *(float4*)&xs[e][q * 4] = ((const float4*)(xb + (size_t)e * NDM + j0))[q];
    }
    __syncthreads();

    int d = tid >> 2, q = tid & 3, jb = q * 16;
    const float* wr = Wt + ((size_t)b * NC + d) * NC;
    float4 acc[4];
    #pragma unroll
    for (int t = 0; t < 4; t++) acc[t] = make_float4(0.f, 0.f, 0.f, 0.f);
    #pragma unroll 4
    for (int e = 0; e < NC; e++) {
        float w = __ldg(wr + e);
        #pragma unroll
        for (int t = 0; t < 4; t++) {
            float4 xv = *(float4*)&xs[e][jb + t * 4];
            acc[t].x = fmaf(w, xv.x, acc[t].x);
            acc[t].y = fmaf(w, xv.y, acc[t].y);
            acc[t].z = fmaf(w, xv.z, acc[t].z);
            acc[t].w = fmaf(w, xv.w, acc[t].w);
        }
    }
    const float invs = 0.9999950000374997f;
    float bsc = bng[d] * invs, bof = bnb[d];
    float* orow = Out + ((size_t)b * NC + d) * NDM + j0 + jb;
    #pragma unroll
    for (int t = 0; t < 4; t++) {
        float4 xv = *(float4*)&xs[d][jb + t * 4];
        float4 o;
        o.x = (acc[t].x + xv.x) * bsc + bof;
        o.y = (acc[t].y + xv.y) * bsc + bof;
        o.z = (acc[t].z + xv.z) * bsc + bof;
        o.w = (acc[t].w + xv.w) * bsc + bof;
        *(float4*)(orow + t * 4) = o;
    }
}

// ===========================================================================
// auto-attn shift scores + softmax + weighted shift sum
// ===========================================================================
__global__ void autoshift_kernel(const float* __restrict__ X, const float* __restrict__ U,
                                 float* __restrict__ XW) {
    __shared__ float xr[NDM];
    __shared__ float red[8][4];
    int row = blockIdx.x, tid = threadIdx.x;
    const float4 xv = ((const float4*)(X + (size_t)row * NDM))[tid];
    ((float4*)xr)[tid] = xv;
    const float4 uv = ((const float4*)(U + (size_t)row * NDM))[tid];
    __syncthreads();

    float sc[8];
    #pragma unroll
    for (int s = 0; s < 8; s++) {
        float4 x4 = ((float4*)xr)[(tid + 16 * s) & 127];
        sc[s] = uv.x * x4.x + uv.y * x4.y + uv.z * x4.z + uv.w * x4.w;
    }
    int lane = tid & 31, wid = tid >> 5;
    #pragma unroll
    for (int s = 0; s < 8; s++) {
        float v = sc[s];
        #pragma unroll
        for (int o = 16; o; o >>= 1) v += __shfl_xor_sync(0xffffffffu, v, o);
        if (!lane) red[s][wid] = v;
    }
    __syncthreads();
    const float rsq = 0.04419417382415922f;    // DM^-0.5
    float lg[8], mx = -1e30f;
    #pragma unroll
    for (int s = 0; s < 8; s++) {
        lg[s] = (red[s][0] + red[s][1] + red[s][2] + red[s][3]) * rsq;
        mx = fmaxf(mx, lg[s]);
    }
    float w[8], sum = 0.f;
    #pragma unroll
    for (int s = 0; s < 8; s++) { w[s] = __expf(lg[s] - mx); sum += w[s]; }
    float rs = 1.f / sum;
    float4 o = make_float4(0.f, 0.f, 0.f, 0.f);
    #pragma unroll
    for (int s = 0; s < 8; s++) {
        float4 x4 = ((float4*)xr)[(tid + 16 * s) & 127];
        float ws = w[s] * rs;
        o.x = fmaf(ws, x4.x, o.x); o.y = fmaf(ws, x4.y, o.y);
        o.z = fmaf(ws, x4.z, o.z); o.w = fmaf(ws, x4.w, o.w);
    }
    ((float4*)(XW + (size_t)row * NDM))[tid] = o;
}

// ===========================================================================
// LayerNorm over last axis (512); optional fused rowsum of the OUTPUT.
// ===========================================================================
template<bool SUM>
__global__ void layernorm_kernel(const float* __restrict__ In, const float* __restrict__ g,
                                 const float* __restrict__ bb, float* __restrict__ Out,
                                 float* __restrict__ S) {
    int row = blockIdx.x, tid = threadIdx.x;
    const float4 v = ((const float4*)(In + (size_t)row * NDM))[tid];
    float s  = v.x + v.y + v.z + v.w;
    float s2 = v.x * v.x + v.y * v.y + v.z * v.z + v.w * v.w;
    #pragma unroll
    for (int o = 16; o; o >>= 1) {
        s  += __shfl_xor_sync(0xffffffffu, s, o);
        s2 += __shfl_xor_sync(0xffffffffu, s2, o);
    }
    __shared__ float ws[4], ws2[4], wo[4];
    int lane = tid & 31, wid = tid >> 5;
    if (!lane) { ws[wid] = s; ws2[wid] = s2; }
    __syncthreads();
    s  = ws[0] + ws[1] + ws[2] + ws[3];
    s2 = ws2[0] + ws2[1] + ws2[2] + ws2[3];
    float mean = s * (1.f / NDM);
    float var  = s2 * (1.f / NDM) - mean * mean;
    float inv  = rsqrtf(var + 1e-5f);
    float4 gv = ((const float4*)g)[tid], bv = ((const float4*)bb)[tid];
    float4 o;
    o.x = (v.x - mean) * inv * gv.x + bv.x;
    o.y = (v.y - mean) * inv * gv.y + bv.y;
    o.z = (v.z - mean) * inv * gv.z + bv.z;
    o.w = (v.w - mean) * inv * gv.w + bv.w;
    ((float4*)(Out + (size_t)row * NDM))[tid] = o;
    if (SUM) {
        float os = o.x + o.y + o.z + o.w;
        #pragma unroll
        for (int off = 16; off; off >>= 1) os += __shfl_xor_sync(0xffffffffu, os, off);
        if (!lane) wo[wid] = os;
        __syncthreads();
        if (tid == 0) S[row] = wo[0] + wo[1] + wo[2] + wo[3];
    }
}

// ===========================================================================
extern "C" void kernel_launch(void* const* d_in, const int* in_sizes, int n_in,
                              void* d_out, int out_size) {
    (void)in_sizes; (void)n_in; (void)out_size;
    const float* inp     = (const float*)d_in[0];
    const float* ld_w    = (const float*)d_in[1];
    const float* ld_b    = (const float*)d_in[2];
    const float* emb_W   = (const float*)d_in[3];
    const float* emb_b   = (const float*)d_in[4];
    const float* W_pos   = (const float*)d_in[5];
    const float* vc_bn_g = (const float*)d_in[6];
    const float* vc_bn_b = (const float*)d_in[7];
    const float* vc_ln_g = (const float*)d_in[8];
    const float* vc_ln_b = (const float*)d_in[9];
    const float* vc_W1   = (const float*)d_in[10];
    const float* vc_b1   = (const float*)d_in[11];
    const float* vc_W2   = (const float*)d_in[12];
    const float* vc_b2   = (const float*)d_in[13];
    const float* aa_Wq   = (const float*)d_in[14];
    const float* aa_bq   = (const float*)d_in[15];
    const float* aa_Wk   = (const float*)d_in[16];
    // d_in[17] = aa_bk: cancels in the shift-softmax (constant logit offset)
    const float* aa_Wv   = (const float*)d_in[18];
    const float* aa_bv   = (const float*)d_in[19];
    const float* aa_Wo   = (const float*)d_in[20];
    const float* aa_bo   = (const float*)d_in[21];
    const float* aa_bn_g = (const float*)d_in[22];
    const float* aa_bn_b = (const float*)d_in[23];
    const float* aa_ln_g = (const float*)d_in[24];
    const float* aa_ln_b = (const float*)d_in[25];
    const float* aa_W1   = (const float*)d_in[26];
    const float* aa_b1   = (const float*)d_in[27];
    const float* aa_W2   = (const float*)d_in[28];
    const float* aa_b2   = (const float*)d_in[29];

    float *R, *X, *B1, *B2, *B3, *S, *WT, *WQK, *CV;
    cudaGetSymbolAddress((void**)&R,   g_R);
    cudaGetSymbolAddress((void**)&X,   g_X);
    cudaGetSymbolAddress((void**)&B1,  g_B1);
    cudaGetSymbolAddress((void**)&B2,  g_B2);
    cudaGetSymbolAddress((void**)&B3,  g_B3);
    cudaGetSymbolAddress((void**)&S,   g_S);
    cudaGetSymbolAddress((void**)&WT,  g_W);
    cudaGetSymbolAddress((void**)&WQK, g_WQK);
    cudaGetSymbolAddress((void**)&CV,  g_CV);
    float* OUT = (float*)d_out;

    dim3 g512(NDM / BNg, NM / BMg);    // (8,32)  = 256 blocks
    dim3 g1024(NH / BNg, NM / BMg);    // (16,32) = 512 blocks

    // trend conv + residual (transposed to (B,C,T))
    conv_residual_kernel<<<dim3(NB, NT / 64, NC / 32), 256>>>(inp, ld_w, ld_b, R);
    // auto-attn precompute (x-independent, all layers)
    wqk_kernel<<<dim3(8, 8, NL), 256>>>(aa_Wq, aa_Wk, WQK);
    bqk_kernel<<<dim3(4, NL), 128>>>(aa_bq, aa_Wk, CV);
    // embedding: X = R @ emb_W.T + emb_b + W_pos
    mma_gemm<EPI_BIAS_WPOS><<<g512, 128>>>(R, emb_W, emb_b, W_pos,
                                           nullptr, nullptr, X, NM, NDM, NT);
    rowsum_kernel<<<NM / 8, 256>>>(X, S);

    for (int l = 0; l < NL; ++l) {
        const size_t SS = (size_t)NDM * NDM, SH = (size_t)NH * NDM;
        // ---- VarCor block ----
        varcor_w_kernel<<<NB, NC>>>(S, WT);
        varcor_mix_kernel<<<dim3(NB, NDM / 64), 512>>>(X, WT, vc_bn_g + l * NC, vc_bn_b + l * NC, B2);
        mma_gemm<EPI_BIAS_GELU><<<g1024, 128>>>(B2, vc_W1 + l * SH, vc_b1 + l * NH,
                                                nullptr, nullptr, nullptr, B1, NM, NH, NDM);
        mma_gemm<EPI_BIAS_RES><<<g512, 128>>>(B1, vc_W2 + l * SH, vc_b2 + l * NDM,
                                              B2, nullptr, nullptr, B3, NM, NDM, NH);
        layernorm_kernel<false><<<NM, 128>>>(B3, vc_ln_g + l * NDM, vc_ln_b + l * NDM, X, nullptr);

        // ---- Auto-attention block ----
        // u = x @ (Wq^T Wk) + bq@Wk   (single fused GEMM, NT layout)
        mma_gemm<EPI_BIAS><<<g512, 128>>>(X, WQK + l * SS, CV + l * NDM,
                                          nullptr, nullptr, nullptr, B3, NM, NDM, NDM);
        autoshift_kernel<<<NM, 128>>>(X, B3, B2);
        mma_gemm<EPI_BIAS><<<g512, 128>>>(B2, aa_Wv + l * SS, aa_bv + l * NDM,
                                          nullptr, nullptr, nullptr, B3, NM, NDM, NDM);
        mma_gemm<EPI_BIAS_RES_BN><<<g512, 128>>>(B3, aa_Wo + l * SS, aa_bo + l * NDM,
                                                 X, aa_bn_g + l * NC, aa_bn_b + l * NC,
                                                 B2, NM, NDM, NDM);
        mma_gemm<EPI_BIAS_GELU><<<g1024, 128>>>(B2, aa_W1 + l * SH, aa_b1 + l * NH,
                                                nullptr, nullptr, nullptr, B1, NM, NH, NDM);
        mma_gemm<EPI_BIAS_RES><<<g512, 128>>>(B1, aa_W2 + l * SH, aa_b2 + l * NDM,
                                              B2, nullptr, nullptr, B3, NM, NDM, NH);
        if (l == NL - 1) {
            layernorm_kernel<false><<<NM, 128>>>(B3, aa_ln_g + l * NDM, aa_ln_b + l * NDM, OUT, nullptr);
        } else {
            layernorm_kernel<true><<<NM, 128>>>(B3, aa_ln_g + l * NDM, aa_ln_b + l * NDM, X, S);
        }
    }
}

// round 7
// speedup vs baseline: 1.2755x; 1.2009x over previous
#include <cuda_runtime.h>
#include <cuda_fp16.h>
#include <math.h>
#include <stdint.h>

// Problem constants
#define NB   16
#define NT   512
#define NC   128
#define NDM  512
#define NL   3
#define NKS  25
#define NM   (NB*NC)       // 2048 rows
#define NH   (2*NDM)       // 1024 FFN hidden

// fp32 scratch
__device__ float g_X  [NM*NDM];
__device__ float g_B2 [NM*NDM];
__device__ float g_B3 [NM*NDM];
__device__ float g_S  [NM];
__device__ float g_W  [NB*NC*NC];
__device__ float g_CV [NL*NDM];
// fp16 scratch (GEMM operands)
__device__ __align__(256) __half g_hR  [NM*NT];
__device__ __align__(256) __half g_hX  [NM*NDM];
__device__ __align__(256) __half g_hB1 [NM*NH];
__device__ __align__(256) __half g_hB2 [NM*NDM];
__device__ __align__(256) __half g_hB3 [NM*NDM];
__device__ __align__(256) __half g_hEmb [NDM*NT];
__device__ __align__(256) __half g_hVcW1[NL*NH*NDM];
__device__ __align__(256) __half g_hVcW2[NL*NDM*NH];
__device__ __align__(256) __half g_hWQK [NL*NDM*NDM];
__device__ __align__(256) __half g_hWv  [NL*NDM*NDM];
__device__ __align__(256) __half g_hWo  [NL*NDM*NDM];
__device__ __align__(256) __half g_hAaW1[NL*NH*NDM];
__device__ __align__(256) __half g_hAaW2[NL*NDM*NH];

// ===========================================================================
// helpers
// ===========================================================================
__device__ __forceinline__ uint32_t smem_u32(const void* p) {
    uint32_t a;
    asm("{ .reg .u64 t; cvta.to.shared.u64 t, %1; cvt.u32.u64 %0, t; }" : "=r"(a) : "l"(p));
    return a;
}
__device__ __forceinline__ void cpa16(uint32_t dst, const void* src) {
    asm volatile("cp.async.cg.shared.global [%0], [%1], 16;" :: "r"(dst), "l"(src));
}
#define CPA_COMMIT() asm volatile("cp.async.commit_group;" ::: "memory")
#define CPA_WAIT(n)  asm volatile("cp.async.wait_group %0;" :: "n"(n) : "memory")

__device__ __forceinline__ void ldsm4(uint32_t& r0, uint32_t& r1, uint32_t& r2, uint32_t& r3,
                                      uint32_t addr) {
    asm volatile("ldmatrix.sync.aligned.m8n8.x4.shared.b16 {%0,%1,%2,%3}, [%4];"
                 : "=r"(r0), "=r"(r1), "=r"(r2), "=r"(r3) : "r"(addr));
}
__device__ __forceinline__ void mma16(float (&d)[4], const uint32_t (&a)[4], const uint32_t (&b)[2]) {
    asm volatile("mma.sync.aligned.m16n8k16.row.col.f32.f16.f16.f32 "
                 "{%0,%1,%2,%3}, {%4,%5,%6,%7}, {%8,%9}, {%0,%1,%2,%3};"
                 : "+f"(d[0]), "+f"(d[1]), "+f"(d[2]), "+f"(d[3])
                 : "r"(a[0]), "r"(a[1]), "r"(a[2]), "r"(a[3]), "r"(b[0]), "r"(b[1]));
}
__device__ __forceinline__ __half2 h2(float a, float b) {
    return __float22half2_rn(make_float2(a, b));
}

// ===========================================================================
// fp16 cp.async GEMM: C[m,n] = sum_k A[m,k]*W[n,k] + epilogue (fp32 accum)
// BM=BN=64, BK=32, 4-stage cp.async ring, 256 threads = 8 warps (2Mx4N).
// ===========================================================================
enum { EPI_NONE = 0, EPI_BIAS, EPI_BIAS_WPOS, EPI_BIAS_GELU, EPI_BIAS_RES, EPI_BIAS_RES_BN };
enum { OUT_F32 = 0, OUT_F16 = 1, OUT_BOTH = 2 };

#define STAGES 4
#define ROWB  80                       // bytes/row: 64 data + 16 pad (16B-aligned, conflict-free)
#define TILEB (64*ROWB)                // 5120 B
#define STGB  (2*TILEB)                // 10240 B per stage

template<int EPI, int OUTM>
__global__ __launch_bounds__(256, 3)
void cg_gemm(const __half* __restrict__ A, const __half* __restrict__ W,
             const float* __restrict__ bias, const float* __restrict__ extra,
             const float* __restrict__ bng, const float* __restrict__ bnb,
             float* __restrict__ C, __half* __restrict__ Ch, int M, int N, int K) {
    __shared__ __align__(128) char sh[STAGES * STGB];   // 40 KB
    const uint32_t sbase = smem_u32(sh);

    int tid = threadIdx.x, wid = tid >> 5, lane = tid & 31;
    int g = lane >> 2, tg = lane & 3;
    int wm = wid & 1, wn = wid >> 1;                      // 2 x 4 warps
    int m0 = blockIdx.y * 64, n0 = blockIdx.x * 64;

    float c[2][2][4];
    #pragma unroll
    for (int i = 0; i < 2; i++)
        #pragma unroll
        for (int j = 0; j < 2; j++)
            #pragma unroll
            for (int q = 0; q < 4; q++) c[i][j][q] = 0.f;

    // cp.async geometry: 64 rows x 4 16B-chunks per tile; one A + one B op/thread/stage
    const int r = tid >> 2, cc = tid & 3;
    const uint32_t dOff = (uint32_t)(r * ROWB + cc * 16);
    const __half* ag = A + (size_t)(m0 + r) * K + cc * 8;
    const __half* bg = W + (size_t)(n0 + r) * K + cc * 8;

    // ldmatrix lane addressing
    const int lt = lane >> 3, lr8 = lane & 7;
    const uint32_t aRowOff = (uint32_t)((wm * 32 + (lt & 1) * 8 + lr8) * ROWB + (lt >> 1) * 16);
    const uint32_t bRowOff = (uint32_t)((wn * 16 + (lt >> 1) * 8 + lr8) * ROWB + (lt & 1) * 16);

    const int KC = K >> 5;

    #pragma unroll
    for (int s = 0; s < STAGES - 1; s++) {
        cpa16(sbase + s * STGB + dOff, ag + s * 32);
        cpa16(sbase + s * STGB + TILEB + dOff, bg + s * 32);
        CPA_COMMIT();
    }

    for (int kc = 0; kc < KC; kc++) {
        int pf = kc + STAGES - 1;
        if (pf < KC) {
            uint32_t sb = sbase + (pf % STAGES) * STGB;
            cpa16(sb + dOff, ag + pf * 32);
            cpa16(sb + TILEB + dOff, bg + pf * 32);
        }
        CPA_COMMIT();
        CPA_WAIT(STAGES - 1);
        __syncthreads();

        const uint32_t sA = sbase + (kc % STAGES) * STGB;
        const uint32_t sB = sA + TILEB;
        #pragma unroll
        for (int ks = 0; ks < 2; ks++) {
            uint32_t af[2][4], bf[2][2];
            #pragma unroll
            for (int mi = 0; mi < 2; mi++)
                ldsm4(af[mi][0], af[mi][1], af[mi][2], af[mi][3],
                      sA + aRowOff + mi * (16 * ROWB) + ks * 32);
            {
                uint32_t r0, r1, r2, r3;
                ldsm4(r0, r1, r2, r3, sB + bRowOff + ks * 32);
                bf[0][0] = r0; bf[0][1] = r1; bf[1][0] = r2; bf[1][1] = r3;
            }
            #pragma unroll
            for (int mi = 0; mi < 2; mi++)
                #pragma unroll
                for (int nj = 0; nj < 2; nj++) mma16(c[mi][nj], af[mi], bf[nj]);
        }
        __syncthreads();
    }

    // ---- epilogue ----
    const float invs = 0.9999950000374997f;   // 1/sqrt(1+1e-5) eval-mode BN
    int mBase = m0 + wm * 32, nBase = n0 + wn * 16;
    #pragma unroll
    for (int mi = 0; mi < 2; mi++) {
        #pragma unroll
        for (int half = 0; half < 2; half++) {
            int m = mBase + mi * 16 + g + half * 8;
            float bsc = 1.f, bof = 0.f;
            if (EPI == EPI_BIAS_RES_BN) { bsc = bng[m & (NC - 1)] * invs; bof = bnb[m & (NC - 1)]; }
            #pragma unroll
            for (int nj = 0; nj < 2; nj++) {
                int n = nBase + nj * 8 + tg * 2;
                float x0 = c[mi][nj][half * 2 + 0];
                float x1 = c[mi][nj][half * 2 + 1];
                if (EPI != EPI_NONE) { x0 += bias[n]; x1 += bias[n + 1]; }
                if (EPI == EPI_BIAS_WPOS) {
                    const float* e = extra + (size_t)(m & (NC - 1)) * N + n;
                    x0 += e[0]; x1 += e[1];
                }
                if (EPI == EPI_BIAS_RES || EPI == EPI_BIAS_RES_BN) {
                    const float* e = extra + (size_t)m * N + n;
                    x0 += e[0]; x1 += e[1];
                }
                if (EPI == EPI_BIAS_GELU) {
                    x0 = 0.5f * x0 * (1.f + erff(x0 * 0.7071067811865475f));
                    x1 = 0.5f * x1 * (1.f + erff(x1 * 0.7071067811865475f));
                }
                if (EPI == EPI_BIAS_RES_BN) { x0 = x0 * bsc + bof; x1 = x1 * bsc + bof; }
                if (OUTM == OUT_F32 || OUTM == OUT_BOTH)
                    *(float2*)(C + (size_t)m * N + n) = make_float2(x0, x1);
                if (OUTM == OUT_F16 || OUTM == OUT_BOTH)
                    *(__half2*)(Ch + (size_t)m * N + n) = h2(x0, x1);
            }
        }
    }
}

// ===========================================================================
// fp32 -> fp16 conversion (weights), 4 elems/thread
// ===========================================================================
__global__ void f2h_kernel(const float* __restrict__ src, __half* __restrict__ dst, int n) {
    int i = (blockIdx.x * blockDim.x + threadIdx.x) * 4;
    if (i < n) {
        float4 v = *(const float4*)(src + i);
        __half2* d = (__half2*)(dst + i);
        d[0] = h2(v.x, v.y);
        d[1] = h2(v.z, v.w);
    }
}

// ===========================================================================
// Bop[n,k] = sum_j Wk[j,n]*Wq[j,k] (fp16 out) ;  cv[n] = sum_j bq[j]*Wk[j,n]
// ===========================================================================
__global__ void wqk_kernel(const float* __restrict__ Wq, const float* __restrict__ Wk,
                           __half* __restrict__ Bop) {
    __shared__ float sk[16][68], sq[16][68];
    int l = blockIdx.z;
    const float* wq = Wq + (size_t)l * NDM * NDM;
    const float* wk = Wk + (size_t)l * NDM * NDM;
    __half* bo = Bop + (size_t)l * NDM * NDM;
    int n0 = blockIdx.x * 64, k0 = blockIdx.y * 64;
    int tid = threadIdx.x, tx = tid & 15, ty = tid >> 4;
    float acc[4][4] = {};
    for (int j0 = 0; j0 < NDM; j0 += 16) {
        int jr = tid >> 4, qc = (tid & 15) * 4;
        *(float4*)&sk[jr][qc] = *(const float4*)(wk + (size_t)(j0 + jr) * NDM + n0 + qc);
        *(float4*)&sq[jr][qc] = *(const float4*)(wq + (size_t)(j0 + jr) * NDM + k0 + qc);
        __syncthreads();
        #pragma unroll
        for (int jj = 0; jj < 16; jj++) {
            float a[4], b[4];
            #pragma unroll
            for (int i = 0; i < 4; i++) a[i] = sk[jj][ty * 4 + i];
            #pragma unroll
            for (int j = 0; j < 4; j++) b[j] = sq[jj][tx * 4 + j];
            #pragma unroll
            for (int i = 0; i < 4; i++)
                #pragma unroll
                for (int j = 0; j < 4; j++) acc[i][j] = fmaf(a[i], b[j], acc[i][j]);
        }
        __syncthreads();
    }
    #pragma unroll
    for (int i = 0; i < 4; i++) {
        __half* p = bo + (size_t)(n0 + ty * 4 + i) * NDM + k0 + tx * 4;
        *(__half2*)(p)     = h2(acc[i][0], acc[i][1]);
        *(__half2*)(p + 2) = h2(acc[i][2], acc[i][3]);
    }
}
__global__ void bqk_kernel(const float* __restrict__ bq, const float* __restrict__ Wk,
                           float* __restrict__ cv) {
    int l = blockIdx.y;
    const float* b  = bq + l * NDM;
    const float* wk = Wk + (size_t)l * NDM * NDM;
    int n = blockIdx.x * 128 + threadIdx.x;
    float s = 0.f;
    for (int j = 0; j < NDM; j++) s = fmaf(b[j], wk[(size_t)j * NDM + n], s);
    cv[l * NDM + n] = s;
}

// ===========================================================================
// trend conv + residual -> fp16 (B,C,T)
// ===========================================================================
__global__ void conv_residual_kernel(const float* __restrict__ inp,
                                     const float* __restrict__ w,
                                     const float* __restrict__ ldb,
                                     __half* __restrict__ R) {
    __shared__ float s[88][33];
    __shared__ float wk[NKS];
    int b = blockIdx.x, t0 = blockIdx.y * 64, c0 = blockIdx.z * 32;
    int tid = threadIdx.x;
    if (tid < NKS) wk[tid] = w[tid];
    for (int idx = tid; idx < 88 * 32; idx += 256) {
        int r = idx >> 5, c = idx & 31;
        int tg = t0 + r - 12;
        tg = min(max(tg, 0), NT - 1);
        s[r][c] = inp[((size_t)b * NT + tg) * NC + c0 + c];
    }
    __syncthreads();
    float lb = ldb[0];
    int lane = tid & 31, wy = tid >> 5;
    for (int half = 0; half < 2; ++half) {
        int ti = half * 32 + lane;
        for (int cg = 0; cg < 4; ++cg) {
            int ci = cg * 8 + wy;
            float acc = 0.f;
            #pragma unroll
            for (int k = 0; k < NKS; ++k) acc = fmaf(wk[k], s[ti + k][ci], acc);
            float v = s[ti + 12][ci] - (acc + lb);
            R[((size_t)b * NC + c0 + ci) * NT + t0 + ti] = __float2half(v);
        }
    }
}

// ===========================================================================
// row sums of X (varcor logits)
// ===========================================================================
__global__ void rowsum_kernel(const float* __restrict__ X, float* __restrict__ S) {
    int row = blockIdx.x * 8 + (threadIdx.x >> 5);
    int lane = threadIdx.x & 31;
    const float* xr = X + (size_t)row * NDM;
    float s = 0.f;
    for (int i = lane; i < NDM; i += 32) s += xr[i];
    #pragma unroll
    for (int o = 16; o; o >>= 1) s += __shfl_xor_sync(0xffffffffu, s, o);
    if (!lane) S[row] = s;
}

// ===========================================================================
// varcor softmax weights
// ===========================================================================
__global__ void varcor_w_kernel(const float* __restrict__ S, float* __restrict__ Wt) {
    __shared__ float ss[NC];
    int b = blockIdx.x, d = threadIdx.x;
    ss[d] = S[b * NC + d];
    __syncthreads();
    const float VS = 8.6316746e-05f;            // 1/(512*sqrt(512))
    float sd = ss[d];
    float mx = -1e30f;
    #pragma unroll 8
    for (int e = 0; e < NC; e++) mx = fmaxf(mx, sd * ss[e]);
    float sum = 0.f;
    #pragma unroll 8
    for (int e = 0; e < NC; e++) sum += __expf((sd * ss[e] - mx) * VS);
    float rs = 1.f / sum;
    float* wr = Wt + ((size_t)b * NC + d) * NC;
    #pragma unroll 8
    for (int e = 0; e < NC; e++) wr[e] = __expf((sd * ss[e] - mx) * VS) * rs;
}

// ===========================================================================
// varcor mix + residual + BN -> fp32 + fp16
// ===========================================================================
__global__ __launch_bounds__(512)
void varcor_mix_kernel(const float* __restrict__ X, const float* __restrict__ Wt,
                       const float* __restrict__ bng, const float* __restrict__ bnb,
                       float* __restrict__ Out, __half* __restrict__ hOut) {
    __shared__ float xs[NC][64];
    int b = blockIdx.x, j0 = blockIdx.y * 64;
    int tid = threadIdx.x;
    const float* xb = X + (size_t)b * NC * NDM;
    #pragma unroll
    for (int i = 0; i < 4; i++) {
        int f = tid + i * 512;
        int e = f >> 4, q = f & 15;
        *(float4*)&xs[e][q * 4] = ((const float4*)(xb + (size_t)e * NDM + j0))[q];
    }
    __syncthreads();

    int d = tid >> 2, q = tid & 3, jb = q * 16;
    const float* wr = Wt + ((size_t)b * NC + d) * NC;
    float4 acc[4];
    #pragma unroll
    for (int t = 0; t < 4; t++) acc[t] = make_float4(0.f, 0.f, 0.f, 0.f);
    #pragma unroll 4
    for (int e = 0; e < NC; e++) {
        float w = __ldg(wr + e);
        #pragma unroll
        for (int t = 0; t < 4; t++) {
            float4 xv = *(float4*)&xs[e][jb + t * 4];
            acc[t].x = fmaf(w, xv.x, acc[t].x);
            acc[t].y = fmaf(w, xv.y, acc[t].y);
            acc[t].z = fmaf(w, xv.z, acc[t].z);
            acc[t].w = fmaf(w, xv.w, acc[t].w);
        }
    }
    const float invs = 0.9999950000374997f;
    float bsc = bng[d] * invs, bof = bnb[d];
    size_t base = ((size_t)b * NC + d) * NDM + j0 + jb;
    #pragma unroll
    for (int t = 0; t < 4; t++) {
        float4 xv = *(float4*)&xs[d][jb + t * 4];
        float4 o;
        o.x = (acc[t].x + xv.x) * bsc + bof;
        o.y = (acc[t].y + xv.y) * bsc + bof;
        o.z = (acc[t].z + xv.z) * bsc + bof;
        o.w = (acc[t].w + xv.w) * bsc + bof;
        *(float4*)(Out + base + t * 4) = o;
        *(__half2*)(hOut + base + t * 4)     = h2(o.x, o.y);
        *(__half2*)(hOut + base + t * 4 + 2) = h2(o.z, o.w);
    }
}

// ===========================================================================
// auto-attn shift scores + softmax + weighted shift sum -> fp16
// ===========================================================================
__global__ void autoshift_kernel(const float* __restrict__ X, const float* __restrict__ U,
                                 __half* __restrict__ XW) {
    __shared__ float xr[NDM];
    __shared__ float red[8][4];
    int row = blockIdx.x, tid = threadIdx.x;
    const float4 xv = ((const float4*)(X + (size_t)row * NDM))[tid];
    ((float4*)xr)[tid] = xv;
    const float4 uv = ((const float4*)(U + (size_t)row * NDM))[tid];
    __syncthreads();

    float sc[8];
    #pragma unroll
    for (int s = 0; s < 8; s++) {
        float4 x4 = ((float4*)xr)[(tid + 16 * s) & 127];
        sc[s] = uv.x * x4.x + uv.y * x4.y + uv.z * x4.z + uv.w * x4.w;
    }
    int lane = tid & 31, wid = tid >> 5;
    #pragma unroll
    for (int s = 0; s < 8; s++) {
        float v = sc[s];
        #pragma unroll
        for (int o = 16; o; o >>= 1) v += __shfl_xor_sync(0xffffffffu, v, o);
        if (!lane) red[s][wid] = v;
    }
    __syncthreads();
    const float rsq = 0.04419417382415922f;    // DM^-0.5
    float lg[8], mx = -1e30f;
    #pragma unroll
    for (int s = 0; s < 8; s++) {
        lg[s] = (red[s][0] + red[s][1] + red[s][2] + red[s][3]) * rsq;
        mx = fmaxf(mx, lg[s]);
    }
    float w[8], sum = 0.f;
    #pragma unroll
    for (int s = 0; s < 8; s++) { w[s] = __expf(lg[s] - mx); sum += w[s]; }
    float rs = 1.f / sum;
    float4 o = make_float4(0.f, 0.f, 0.f, 0.f);
    #pragma unroll
    for (int s = 0; s < 8; s++) {
        float4 x4 = ((float4*)xr)[(tid + 16 * s) & 127];
        float ws = w[s] * rs;
        o.x = fmaf(ws, x4.x, o.x); o.y = fmaf(ws, x4.y, o.y);
        o.z = fmaf(ws, x4.z, o.z); o.w = fmaf(ws, x4.w, o.w);
    }
    __half2* op = (__half2*)(XW + (size_t)row * NDM) + tid * 2;
    op[0] = h2(o.x, o.y);
    op[1] = h2(o.z, o.w);
}

// ===========================================================================
// LayerNorm; optional fp16 twin + fused rowsum of output
// ===========================================================================
template<bool SUM, bool H16>
__global__ void layernorm_kernel(const float* __restrict__ In, const float* __restrict__ g,
                                 const float* __restrict__ bb, float* __restrict__ Out,
                                 __half* __restrict__ hOut, float* __restrict__ S) {
    int row = blockIdx.x, tid = threadIdx.x;
    const float4 v = ((const float4*)(In + (size_t)row * NDM))[tid];
    float s  = v.x + v.y + v.z + v.w;
    float s2 = v.x * v.x + v.y * v.y + v.z * v.z + v.w * v.w;
    #pragma unroll
    for (int o = 16; o; o >>= 1) {
        s  += __shfl_xor_sync(0xffffffffu, s, o);
        s2 += __shfl_xor_sync(0xffffffffu, s2, o);
    }
    __shared__ float ws[4], ws2[4], wo[4];
    int lane = tid & 31, wid = tid >> 5;
    if (!lane) { ws[wid] = s; ws2[wid] = s2; }
    __syncthreads();
    s  = ws[0] + ws[1] + ws[2] + ws[3];
    s2 = ws2[0] + ws2[1] + ws2[2] + ws2[3];
    float mean = s * (1.f / NDM);
    float var  = s2 * (1.f / NDM) - mean * mean;
    float inv  = rsqrtf(var + 1e-5f);
    float4 gv = ((const float4*)g)[tid], bv = ((const float4*)bb)[tid];
    float4 o;
    o.x = (v.x - mean) * inv * gv.x + bv.x;
    o.y = (v.y - mean) * inv * gv.y + bv.y;
    o.z = (v.z - mean) * inv * gv.z + bv.z;
    o.w = (v.w - mean) * inv * gv.w + bv.w;
    ((float4*)(Out + (size_t)row * NDM))[tid] = o;
    if (H16) {
        __half2* op = (__half2*)(hOut + (size_t)row * NDM) + tid * 2;
        op[0] = h2(o.x, o.y);
        op[1] = h2(o.z, o.w);
    }
    if (SUM) {
        float os = o.x + o.y + o.z + o.w;
        #pragma unroll
        for (int off = 16; off; off >>= 1) os += __shfl_xor_sync(0xffffffffu, os, off);
        if (!lane) wo[wid] = os;
        __syncthreads();
        if (tid == 0) S[row] = wo[0] + wo[1] + wo[2] + wo[3];
    }
}

// ===========================================================================
extern "C" void kernel_launch(void* const* d_in, const int* in_sizes, int n_in,
                              void* d_out, int out_size) {
    (void)in_sizes; (void)n_in; (void)out_size;
    const float* inp     = (const float*)d_in[0];
    const float* ld_w    = (const float*)d_in[1];
    const float* ld_b    = (const float*)d_in[2];
    const float* emb_W   = (const float*)d_in[3];
    const float* emb_b   = (const float*)d_in[4];
    const float* W_pos   = (const float*)d_in[5];
    const float* vc_bn_g = (const float*)d_in[6];
    const float* vc_bn_b = (const float*)d_in[7];
    const float* vc_ln_g = (const float*)d_in[8];
    const float* vc_ln_b = (const float*)d_in[9];
    const float* vc_W1   = (const float*)d_in[10];
    const float* vc_b1   = (const float*)d_in[11];
    const float* vc_W2   = (const float*)d_in[12];
    const float* vc_b2   = (const float*)d_in[13];
    const float* aa_Wq   = (const float*)d_in[14];
    const float* aa_bq   = (const float*)d_in[15];
    const float* aa_Wk   = (const float*)d_in[16];
    // d_in[17] = aa_bk: cancels in the shift-softmax (constant logit offset)
    const float* aa_Wv   = (const float*)d_in[18];
    const float* aa_bv   = (const float*)d_in[19];
    const float* aa_Wo   = (const float*)d_in[20];
    const float* aa_bo   = (const float*)d_in[21];
    const float* aa_bn_g = (const float*)d_in[22];
    const float* aa_bn_b = (const float*)d_in[23];
    const float* aa_ln_g = (const float*)d_in[24];
    const float* aa_ln_b = (const float*)d_in[25];
    const float* aa_W1   = (const float*)d_in[26];
    const float* aa_b1   = (const float*)d_in[27];
    const float* aa_W2   = (const float*)d_in[28];
    const float* aa_b2   = (const float*)d_in[29];

    float *X, *B2, *B3, *S, *WT, *CV;
    __half *hR, *hX, *hB1, *hB2, *hB3;
    __half *hEmb, *hVcW1, *hVcW2, *hWQK, *hWv, *hWo, *hAaW1, *hAaW2;
    cudaGetSymbolAddress((void**)&X,    g_X);
    cudaGetSymbolAddress((void**)&B2,   g_B2);
    cudaGetSymbolAddress((void**)&B3,   g_B3);
    cudaGetSymbolAddress((void**)&S,    g_S);
    cudaGetSymbolAddress((void**)&WT,   g_W);
    cudaGetSymbolAddress((void**)&CV,   g_CV);
    cudaGetSymbolAddress((void**)&hR,   g_hR);
    cudaGetSymbolAddress((void**)&hX,   g_hX);
    cudaGetSymbolAddress((void**)&hB1,  g_hB1);
    cudaGetSymbolAddress((void**)&hB2,  g_hB2);
    cudaGetSymbolAddress((void**)&hB3,  g_hB3);
    cudaGetSymbolAddress((void**)&hEmb, g_hEmb);
    cudaGetSymbolAddress((void**)&hVcW1,g_hVcW1);
    cudaGetSymbolAddress((void**)&hVcW2,g_hVcW2);
    cudaGetSymbolAddress((void**)&hWQK, g_hWQK);
    cudaGetSymbolAddress((void**)&hWv,  g_hWv);
    cudaGetSymbolAddress((void**)&hWo,  g_hWo);
    cudaGetSymbolAddress((void**)&hAaW1,g_hAaW1);
    cudaGetSymbolAddress((void**)&hAaW2,g_hAaW2);
    float* OUT = (float*)d_out;

    dim3 g512(8, 32);    // N=512: 256 blocks
    dim3 g1024(16, 32);  // N=1024: 512 blocks

    // weight conversions (per-run; ~50MB traffic total)
    auto cvt = [](const float* s, __half* d, int n) {
        f2h_kernel<<<(n / 4 + 255) / 256, 256>>>(s, d, n);
    };
    cvt(emb_W, hEmb,  NDM * NT);
    cvt(vc_W1, hVcW1, NL * NH * NDM);
    cvt(vc_W2, hVcW2, NL * NDM * NH);
    cvt(aa_Wv, hWv,   NL * NDM * NDM);
    cvt(aa_Wo, hWo,   NL * NDM * NDM);
    cvt(aa_W1, hAaW1, NL * NH * NDM);
    cvt(aa_W2, hAaW2, NL * NDM * NH);

    // trend conv + residual (fp16, transposed to (B,C,T))
    conv_residual_kernel<<<dim3(NB, NT / 64, NC / 32), 256>>>(inp, ld_w, ld_b, hR);
    // auto-attn precompute
    wqk_kernel<<<dim3(8, 8, NL), 256>>>(aa_Wq, aa_Wk, hWQK);
    bqk_kernel<<<dim3(4, NL), 128>>>(aa_bq, aa_Wk, CV);
    // embedding: X = R @ emb_W.T + emb_b + W_pos
    cg_gemm<EPI_BIAS_WPOS, OUT_F32><<<g512, 256>>>(hR, hEmb, emb_b, W_pos,
                                                   nullptr, nullptr, X, nullptr, NM, NDM, NT);
    rowsum_kernel<<<NM / 8, 256>>>(X, S);

    for (int l = 0; l < NL; ++l) {
        const size_t SS = (size_t)NDM * NDM, SH = (size_t)NH * NDM;
        // ---- VarCor block ----
        varcor_w_kernel<<<NB, NC>>>(S, WT);
        varcor_mix_kernel<<<dim3(NB, NDM / 64), 512>>>(X, WT, vc_bn_g + l * NC, vc_bn_b + l * NC,
                                                       B2, hB2);
        cg_gemm<EPI_BIAS_GELU, OUT_F16><<<g1024, 256>>>(hB2, hVcW1 + l * SH, vc_b1 + l * NH,
                                                        nullptr, nullptr, nullptr,
                                                        nullptr, hB1, NM, NH, NDM);
        cg_gemm<EPI_BIAS_RES, OUT_F32><<<g512, 256>>>(hB1, hVcW2 + l * SH, vc_b2 + l * NDM,
                                                      B2, nullptr, nullptr,
                                                      B3, nullptr, NM, NDM, NH);
        layernorm_kernel<false, true><<<NM, 128>>>(B3, vc_ln_g + l * NDM, vc_ln_b + l * NDM,
                                                   X, hX, nullptr);

        // ---- Auto-attention block ----
        cg_gemm<EPI_BIAS, OUT_F32><<<g512, 256>>>(hX, hWQK + l * SS, CV + l * NDM,
                                                  nullptr, nullptr, nullptr,
                                                  B3, nullptr, NM, NDM, NDM);
        autoshift_kernel<<<NM, 128>>>(X, B3, hB2);
        cg_gemm<EPI_BIAS, OUT_F16><<<g512, 256>>>(hB2, hWv + l * SS, aa_bv + l * NDM,
                                                  nullptr, nullptr, nullptr,
                                                  nullptr, hB3, NM, NDM, NDM);
        cg_gemm<EPI_BIAS_RES_BN, OUT_BOTH><<<g512, 256>>>(hB3, hWo + l * SS, aa_bo + l * NDM,
                                                          X, aa_bn_g + l * NC, aa_bn_b + l * NC,
                                                          B2, hB2, NM, NDM, NDM);
        cg_gemm<EPI_BIAS_GELU, OUT_F16><<<g1024, 256>>>(hB2, hAaW1 + l * SH, aa_b1 + l * NH,
                                                        nullptr, nullptr, nullptr,
                                                        nullptr, hB1, NM, NH, NDM);
        cg_gemm<EPI_BIAS_RES, OUT_F32><<<g512, 256>>>(hB1, hAaW2 + l * SH, aa_b2 + l * NDM,
                                                      B2, nullptr, nullptr,
                                                      B3, nullptr, NM, NDM, NH);
        if (l == NL - 1) {
            layernorm_kernel<false, false><<<NM, 128>>>(B3, aa_ln_g + l * NDM, aa_ln_b + l * NDM,
                                                        OUT, nullptr, nullptr);
        } else {
            layernorm_kernel<true, true><<<NM, 128>>>(B3, aa_ln_g + l * NDM, aa_ln_b + l * NDM,
                                                      X, hX, S);
        }
    }
}

// round 8
// speedup vs baseline: 1.4302x; 1.1213x over previous
#include <cuda_runtime.h>
#include <cuda_fp16.h>
#include <math.h>
#include <stdint.h>

// Problem constants
#define NB   16
#define NT   512
#define NC   128
#define NDM  512
#define NL   3
#define NKS  25
#define NM   (NB*NC)       // 2048 rows
#define NH   (2*NDM)       // 1024 FFN hidden
#define SSQ  (NDM*NDM)     // 262144

// fp32 scratch
__device__ float g_X  [NM*NDM];
__device__ float g_B2 [NM*NDM];
__device__ float g_B3 [NM*NDM];
__device__ float g_S  [NM];
__device__ float g_W  [NB*NC*NC];
__device__ float g_CV [NL*NDM];
__device__ float g_BVO[NL*NDM];
// fp16 scratch
__device__ __align__(256) __half g_hR  [NM*NT];
__device__ __align__(256) __half g_hX  [NM*NDM];
__device__ __align__(256) __half g_hB1 [NM*NH];
__device__ __align__(256) __half g_hB2 [NM*NDM];
__device__ __align__(256) __half g_hB3 [NM*NDM];
__device__ __align__(256) __half g_hEmb [NDM*NT];
__device__ __align__(256) __half g_hVcW1[NL*NH*NDM];
__device__ __align__(256) __half g_hVcW2[NL*NDM*NH];
__device__ __align__(256) __half g_hAaW1[NL*NH*NDM];
__device__ __align__(256) __half g_hAaW2[NL*NDM*NH];
__device__ __align__(256) __half g_hWo  [NL*SSQ];
__device__ __align__(256) __half g_hT   [9*SSQ];     // WkT(l0..2), WqT, WvT
__device__ __align__(256) __half g_hWQK [NL*SSQ];
__device__ __align__(256) __half g_hWvo [NL*SSQ];

// ===========================================================================
// helpers
// ===========================================================================
__device__ __forceinline__ uint32_t smem_u32(const void* p) {
    uint32_t a;
    asm("{ .reg .u64 t; cvta.to.shared.u64 t, %1; cvt.u32.u64 %0, t; }" : "=r"(a) : "l"(p));
    return a;
}
__device__ __forceinline__ void cpa16(uint32_t dst, const void* src) {
    asm volatile("cp.async.cg.shared.global [%0], [%1], 16;" :: "r"(dst), "l"(src));
}
#define CPA_COMMIT() asm volatile("cp.async.commit_group;" ::: "memory")
#define CPA_WAIT(n)  asm volatile("cp.async.wait_group %0;" :: "n"(n) : "memory")

__device__ __forceinline__ void ldsm4(uint32_t& r0, uint32_t& r1, uint32_t& r2, uint32_t& r3,
                                      uint32_t addr) {
    asm volatile("ldmatrix.sync.aligned.m8n8.x4.shared.b16 {%0,%1,%2,%3}, [%4];"
                 : "=r"(r0), "=r"(r1), "=r"(r2), "=r"(r3) : "r"(addr));
}
__device__ __forceinline__ void mma16(float (&d)[4], const uint32_t (&a)[4], const uint32_t (&b)[2]) {
    asm volatile("mma.sync.aligned.m16n8k16.row.col.f32.f16.f16.f32 "
                 "{%0,%1,%2,%3}, {%4,%5,%6,%7}, {%8,%9}, {%0,%1,%2,%3};"
                 : "+f"(d[0]), "+f"(d[1]), "+f"(d[2]), "+f"(d[3])
                 : "r"(a[0]), "r"(a[1]), "r"(a[2]), "r"(a[3]), "r"(b[0]), "r"(b[1]));
}
__device__ __forceinline__ __half2 h2(float a, float b) {
    return __float22half2_rn(make_float2(a, b));
}

// ===========================================================================
// fp16 cp.async GEMM, z-batched: C[z;m,n] = sum_k A[z;m,k]*W[z;n,k] + epilogue
// BM=BN=64, BK=32, 4-stage ring, single sync/iter, 256 threads (2Mx4N warps).
// ===========================================================================
enum { EPI_NONE = 0, EPI_BIAS, EPI_BIAS_WPOS, EPI_BIAS_GELU, EPI_BIAS_RES, EPI_BIAS_RES_BN };
enum { OUT_F32 = 0, OUT_F16 = 1, OUT_BOTH = 2 };

#define STAGES 4
#define ROWB  80
#define TILEB (64*ROWB)                // 5120 B
#define STGB  (2*TILEB)                // 10240 B

template<int EPI, int OUTM>
__global__ __launch_bounds__(256, 3)
void cg_gemm(const __half* __restrict__ A, const __half* __restrict__ W,
             const float* __restrict__ bias, const float* __restrict__ extra,
             const float* __restrict__ bng, const float* __restrict__ bnb,
             float* __restrict__ C, __half* __restrict__ Ch,
             int M, int N, int K, int azs, int wzs, int czs) {
    __shared__ __align__(128) char sh[STAGES * STGB];   // 40 KB
    const uint32_t sbase = smem_u32(sh);

    A += (size_t)blockIdx.z * azs;
    W += (size_t)blockIdx.z * wzs;
    if (OUTM == OUT_F32 || OUTM == OUT_BOTH) C  += (size_t)blockIdx.z * czs;
    if (OUTM == OUT_F16 || OUTM == OUT_BOTH) Ch += (size_t)blockIdx.z * czs;

    int tid = threadIdx.x, wid = tid >> 5, lane = tid & 31;
    int g = lane >> 2, tg = lane & 3;
    int wm = wid & 1, wn = wid >> 1;
    int m0 = blockIdx.y * 64, n0 = blockIdx.x * 64;

    float c[2][2][4];
    #pragma unroll
    for (int i = 0; i < 2; i++)
        #pragma unroll
        for (int j = 0; j < 2; j++)
            #pragma unroll
            for (int q = 0; q < 4; q++) c[i][j][q] = 0.f;

    const int r = tid >> 2, cc = tid & 3;
    const uint32_t dOff = (uint32_t)(r * ROWB + cc * 16);
    const __half* ag = A + (size_t)(m0 + r) * K + cc * 8;
    const __half* bg = W + (size_t)(n0 + r) * K + cc * 8;

    const int lt = lane >> 3, lr8 = lane & 7;
    const uint32_t aRowOff = (uint32_t)((wm * 32 + (lt & 1) * 8 + lr8) * ROWB + (lt >> 1) * 16);
    const uint32_t bRowOff = (uint32_t)((wn * 16 + (lt >> 1) * 8 + lr8) * ROWB + (lt & 1) * 16);

    const int KC = K >> 5;

    #pragma unroll
    for (int s = 0; s < STAGES - 1; s++) {
        cpa16(sbase + s * STGB + dOff, ag + s * 32);
        cpa16(sbase + s * STGB + TILEB + dOff, bg + s * 32);
        CPA_COMMIT();
    }

    for (int kc = 0; kc < KC; kc++) {
        CPA_WAIT(STAGES - 2);          // stage kc ready
        __syncthreads();               // all readers of stage (kc-1) done -> safe to refill
        int pf = kc + STAGES - 1;
        if (pf < KC) {
            uint32_t sb = sbase + (pf % STAGES) * STGB;
            cpa16(sb + dOff, ag + (size_t)pf * 32);
            cpa16(sb + TILEB + dOff, bg + (size_t)pf * 32);
        }
        CPA_COMMIT();

        const uint32_t sA = sbase + (kc % STAGES) * STGB;
        const uint32_t sB = sA + TILEB;
        #pragma unroll
        for (int ks = 0; ks < 2; ks++) {
            uint32_t af[2][4], bf[2][2];
            #pragma unroll
            for (int mi = 0; mi < 2; mi++)
                ldsm4(af[mi][0], af[mi][1], af[mi][2], af[mi][3],
                      sA + aRowOff + mi * (16 * ROWB) + ks * 32);
            {
                uint32_t r0, r1, r2, r3;
                ldsm4(r0, r1, r2, r3, sB + bRowOff + ks * 32);
                bf[0][0] = r0; bf[0][1] = r1; bf[1][0] = r2; bf[1][1] = r3;
            }
            #pragma unroll
            for (int mi = 0; mi < 2; mi++)
                #pragma unroll
                for (int nj = 0; nj < 2; nj++) mma16(c[mi][nj], af[mi], bf[nj]);
        }
    }

    // ---- epilogue ----
    const float invs = 0.9999950000374997f;   // 1/sqrt(1+1e-5) eval-mode BN
    int mBase = m0 + wm * 32, nBase = n0 + wn * 16;
    #pragma unroll
    for (int mi = 0; mi < 2; mi++) {
        #pragma unroll
        for (int half = 0; half < 2; half++) {
            int m = mBase + mi * 16 + g + half * 8;
            float bsc = 1.f, bof = 0.f;
            if (EPI == EPI_BIAS_RES_BN) { bsc = bng[m & (NC - 1)] * invs; bof = bnb[m & (NC - 1)]; }
            #pragma unroll
            for (int nj = 0; nj < 2; nj++) {
                int n = nBase + nj * 8 + tg * 2;
                float x0 = c[mi][nj][half * 2 + 0];
                float x1 = c[mi][nj][half * 2 + 1];
                if (EPI != EPI_NONE) { x0 += bias[n]; x1 += bias[n + 1]; }
                if (EPI == EPI_BIAS_WPOS) {
                    const float* e = extra + (size_t)(m & (NC - 1)) * N + n;
                    x0 += e[0]; x1 += e[1];
                }
                if (EPI == EPI_BIAS_RES || EPI == EPI_BIAS_RES_BN) {
                    const float* e = extra + (size_t)m * N + n;
                    x0 += e[0]; x1 += e[1];
                }
                if (EPI == EPI_BIAS_GELU) {
                    x0 = 0.5f * x0 * (1.f + erff(x0 * 0.7071067811865475f));
                    x1 = 0.5f * x1 * (1.f + erff(x1 * 0.7071067811865475f));
                }
                if (EPI == EPI_BIAS_RES_BN) { x0 = x0 * bsc + bof; x1 = x1 * bsc + bof; }
                if (OUTM == OUT_F32 || OUTM == OUT_BOTH)
                    *(float2*)(C + (size_t)m * N + n) = make_float2(x0, x1);
                if (OUTM == OUT_F16 || OUTM == OUT_BOTH)
                    *(__half2*)(Ch + (size_t)m * N + n) = h2(x0, x1);
            }
        }
    }
}

// ===========================================================================
// all weight fp32->fp16 conversions, one launch (segment table, 4 elems/thread)
// ===========================================================================
__global__ void f2h_all(const float* __restrict__ emb, const float* __restrict__ vw1,
                        const float* __restrict__ vw2, const float* __restrict__ aw1,
                        const float* __restrict__ aw2, const float* __restrict__ wo,
                        __half* __restrict__ hEmb, __half* __restrict__ hVw1,
                        __half* __restrict__ hVw2, __half* __restrict__ hAw1,
                        __half* __restrict__ hAw2, __half* __restrict__ hWo) {
    long i = ((long)blockIdx.x * 256 + threadIdx.x) * 4;
    const float* s; __half* d; long off;
    if      (i < 262144L)  { s = emb; d = hEmb; off = i; }
    else if (i < 1835008L) { s = vw1; d = hVw1; off = i - 262144L; }
    else if (i < 3407872L) { s = vw2; d = hVw2; off = i - 1835008L; }
    else if (i < 4980736L) { s = aw1; d = hAw1; off = i - 3407872L; }
    else if (i < 6553600L) { s = aw2; d = hAw2; off = i - 4980736L; }
    else                   { s = wo;  d = hWo;  off = i - 6553600L; }
    float4 v = *(const float4*)(s + off);
    __half2* p = (__half2*)(d + off);
    p[0] = h2(v.x, v.y);
    p[1] = h2(v.z, v.w);
}

// ===========================================================================
// transpose + fp16: hT[z] = transpose(src_z), z: 0..2 Wk(l), 3..5 Wq(l), 6..8 Wv(l)
// ===========================================================================
__global__ void trans_f2h(const float* __restrict__ Wk, const float* __restrict__ Wq,
                          const float* __restrict__ Wv, __half* __restrict__ hT) {
    __shared__ float t[32][33];
    int z = blockIdx.z;
    const float* src = (z < 3) ? Wk + (size_t)z * SSQ
                     : (z < 6) ? Wq + (size_t)(z - 3) * SSQ
                               : Wv + (size_t)(z - 6) * SSQ;
    __half* dst = hT + (size_t)z * SSQ;
    int c0 = blockIdx.x * 32, r0 = blockIdx.y * 32;
    int tx = threadIdx.x, ty = threadIdx.y;
    #pragma unroll
    for (int i = 0; i < 4; i++)
        t[ty + i * 8][tx] = src[(size_t)(r0 + ty + i * 8) * NDM + c0 + tx];
    __syncthreads();
    #pragma unroll
    for (int i = 0; i < 4; i++)
        dst[(size_t)(c0 + ty + i * 8) * NDM + r0 + tx] = __float2half(t[tx][ty + i * 8]);
}

// ===========================================================================
// bias precompute: cv[l,n]=sum_j bq[j]Wk[j,n] ; bvo[l,n]=sum_j Wo[n,j]bv[j]+bo[n]
// ===========================================================================
__global__ void bias_pre(const float* __restrict__ bq, const float* __restrict__ Wk,
                         const float* __restrict__ bv, const float* __restrict__ bo,
                         const float* __restrict__ Wo,
                         float* __restrict__ cv, float* __restrict__ bvo) {
    int l = blockIdx.y, which = blockIdx.z;
    int n = blockIdx.x * 128 + threadIdx.x;
    if (which == 0) {
        const float* b  = bq + l * NDM;
        const float* wk = Wk + (size_t)l * SSQ;
        float s = 0.f;
        for (int j = 0; j < NDM; j++) s = fmaf(b[j], wk[(size_t)j * NDM + n], s);
        cv[l * NDM + n] = s;
    } else {
        const float* b  = bv + l * NDM;
        const float* wo = Wo + (size_t)l * SSQ + (size_t)n * NDM;
        float s = bo[l * NDM + n];
        for (int j = 0; j < NDM; j++) s = fmaf(wo[j], b[j], s);
        bvo[l * NDM + n] = s;
    }
}

// ===========================================================================
// trend conv + residual -> fp16 (B,C,T)
// ===========================================================================
__global__ void conv_residual_kernel(const float* __restrict__ inp,
                                     const float* __restrict__ w,
                                     const float* __restrict__ ldb,
                                     __half* __restrict__ R) {
    __shared__ float s[88][33];
    __shared__ float wk[NKS];
    int b = blockIdx.x, t0 = blockIdx.y * 64, c0 = blockIdx.z * 32;
    int tid = threadIdx.x;
    if (tid < NKS) wk[tid] = w[tid];
    for (int idx = tid; idx < 88 * 32; idx += 256) {
        int r = idx >> 5, c = idx & 31;
        int tg = t0 + r - 12;
        tg = min(max(tg, 0), NT - 1);
        s[r][c] = inp[((size_t)b * NT + tg) * NC + c0 + c];
    }
    __syncthreads();
    float lb = ldb[0];
    int lane = tid & 31, wy = tid >> 5;
    for (int half = 0; half < 2; ++half) {
        int ti = half * 32 + lane;
        for (int cg = 0; cg < 4; ++cg) {
            int ci = cg * 8 + wy;
            float acc = 0.f;
            #pragma unroll
            for (int k = 0; k < NKS; ++k) acc = fmaf(wk[k], s[ti + k][ci], acc);
            float v = s[ti + 12][ci] - (acc + lb);
            R[((size_t)b * NC + c0 + ci) * NT + t0 + ti] = __float2half(v);
        }
    }
}

// ===========================================================================
// row sums of X (varcor logits)
// ===========================================================================
__global__ void rowsum_kernel(const float* __restrict__ X, float* __restrict__ S) {
    int row = blockIdx.x * 8 + (threadIdx.x >> 5);
    int lane = threadIdx.x & 31;
    const float* xr = X + (size_t)row * NDM;
    float s = 0.f;
    for (int i = lane; i < NDM; i += 32) s += xr[i];
    #pragma unroll
    for (int o = 16; o; o >>= 1) s += __shfl_xor_sync(0xffffffffu, s, o);
    if (!lane) S[row] = s;
}

// ===========================================================================
// varcor softmax weights
// ===========================================================================
__global__ void varcor_w_kernel(const float* __restrict__ S, float* __restrict__ Wt) {
    __shared__ float ss[NC];
    int b = blockIdx.x, d = threadIdx.x;
    ss[d] = S[b * NC + d];
    __syncthreads();
    const float VS = 8.6316746e-05f;            // 1/(512*sqrt(512))
    float sd = ss[d];
    float mx = -1e30f;
    #pragma unroll 8
    for (int e = 0; e < NC; e++) mx = fmaxf(mx, sd * ss[e]);
    float sum = 0.f;
    #pragma unroll 8
    for (int e = 0; e < NC; e++) sum += __expf((sd * ss[e] - mx) * VS);
    float rs = 1.f / sum;
    float* wr = Wt + ((size_t)b * NC + d) * NC;
    #pragma unroll 8
    for (int e = 0; e < NC; e++) wr[e] = __expf((sd * ss[e] - mx) * VS) * rs;
}

// ===========================================================================
// varcor mix + residual + BN -> fp32 + fp16
// ===========================================================================
__global__ __launch_bounds__(512)
void varcor_mix_kernel(const float* __restrict__ X, const float* __restrict__ Wt,
                       const float* __restrict__ bng, const float* __restrict__ bnb,
                       float* __restrict__ Out, __half* __restrict__ hOut) {
    __shared__ float xs[NC][64];
    int b = blockIdx.x, j0 = blockIdx.y * 64;
    int tid = threadIdx.x;
    const float* xb = X + (size_t)b * NC * NDM;
    #pragma unroll
    for (int i = 0; i < 4; i++) {
        int f = tid + i * 512;
        int e = f >> 4, q = f & 15;
        *(float4*)&xs[e][q * 4] = ((const float4*)(xb + (size_t)e * NDM + j0))[q];
    }
    __syncthreads();

    int d = tid >> 2, q = tid & 3, jb = q * 16;
    const float* wr = Wt + ((size_t)b * NC + d) * NC;
    float4 acc[4];
    #pragma unroll
    for (int t = 0; t < 4; t++) acc[t] = make_float4(0.f, 0.f, 0.f, 0.f);
    #pragma unroll 4
    for (int e = 0; e < NC; e++) {
        float w = __ldg(wr + e);
        #pragma unroll
        for (int t = 0; t < 4; t++) {
            float4 xv = *(float4*)&xs[e][jb + t * 4];
            acc[t].x = fmaf(w, xv.x, acc[t].x);
            acc[t].y = fmaf(w, xv.y, acc[t].y);
            acc[t].z = fmaf(w, xv.z, acc[t].z);
            acc[t].w = fmaf(w, xv.w, acc[t].w);
        }
    }
    const float invs = 0.9999950000374997f;
    float bsc = bng[d] * invs, bof = bnb[d];
    size_t base = ((size_t)b * NC + d) * NDM + j0 + jb;
    #pragma unroll
    for (int t = 0; t < 4; t++) {
        float4 xv = *(float4*)&xs[d][jb + t * 4];
        float4 o;
        o.x = (acc[t].x + xv.x) * bsc + bof;
        o.y = (acc[t].y + xv.y) * bsc + bof;
        o.z = (acc[t].z + xv.z) * bsc + bof;
        o.w = (acc[t].w + xv.w) * bsc + bof;
        *(float4*)(Out + base + t * 4) = o;
        *(__half2*)(hOut + base + t * 4)     = h2(o.x, o.y);
        *(__half2*)(hOut + base + t * 4 + 2) = h2(o.z, o.w);
    }
}

// ===========================================================================
// auto-attn shift scores + softmax + weighted shift sum -> fp16
// ===========================================================================
__global__ void autoshift_kernel(const float* __restrict__ X, const float* __restrict__ U,
                                 __half* __restrict__ XW) {
    __shared__ float xr[NDM];
    __shared__ float red[8][4];
    int row = blockIdx.x, tid = threadIdx.x;
    const float4 xv = ((const float4*)(X + (size_t)row * NDM))[tid];
    ((float4*)xr)[tid] = xv;
    const float4 uv = ((const float4*)(U + (size_t)row * NDM))[tid];
    __syncthreads();

    float sc[8];
    #pragma unroll
    for (int s = 0; s < 8; s++) {
        float4 x4 = ((float4*)xr)[(tid + 16 * s) & 127];
        sc[s] = uv.x * x4.x + uv.y * x4.y + uv.z * x4.z + uv.w * x4.w;
    }
    int lane = tid & 31, wid = tid >> 5;
    #pragma unroll
    for (int s = 0; s < 8; s++) {
        float v = sc[s];
        #pragma unroll
        for (int o = 16; o; o >>= 1) v += __shfl_xor_sync(0xffffffffu, v, o);
        if (!lane) red[s][wid] = v;
    }
    __syncthreads();
    const float rsq = 0.04419417382415922f;    // DM^-0.5
    float lg[8], mx = -1e30f;
    #pragma unroll
    for (int s = 0; s < 8; s++) {
        lg[s] = (red[s][0] + red[s][1] + red[s][2] + red[s][3]) * rsq;
        mx = fmaxf(mx, lg[s]);
    }
    float w[8], sum = 0.f;
    #pragma unroll
    for (int s = 0; s < 8; s++) { w[s] = __expf(lg[s] - mx); sum += w[s]; }
    float rs = 1.f / sum;
    float4 o = make_float4(0.f, 0.f, 0.f, 0.f);
    #pragma unroll
    for (int s = 0; s < 8; s++) {
        float4 x4 = ((float4*)xr)[(tid + 16 * s) & 127];
        float ws = w[s] * rs;
        o.x = fmaf(ws, x4.x, o.x); o.y = fmaf(ws, x4.y, o.y);
        o.z = fmaf(ws, x4.z, o.z); o.w = fmaf(ws, x4.w, o.w);
    }
    __half2* op = (__half2*)(XW + (size_t)row * NDM) + tid * 2;
    op[0] = h2(o.x, o.y);
    op[1] = h2(o.z, o.w);
}

// ===========================================================================
// LayerNorm; optional fp16 twin + fused rowsum of output
// ===========================================================================
template<bool SUM, bool H16>
__global__ void layernorm_kernel(const float* __restrict__ In, const float* __restrict__ g,
                                 const float* __restrict__ bb, float* __restrict__ Out,
                                 __half* __restrict__ hOut, float* __restrict__ S) {
    int row = blockIdx.x, tid = threadIdx.x;
    const float4 v = ((const float4*)(In + (size_t)row * NDM))[tid];
    float s  = v.x + v.y + v.z + v.w;
    float s2 = v.x * v.x + v.y * v.y + v.z * v.z + v.w * v.w;
    #pragma unroll
    for (int o = 16; o; o >>= 1) {
        s  += __shfl_xor_sync(0xffffffffu, s, o);
        s2 += __shfl_xor_sync(0xffffffffu, s2, o);
    }
    __shared__ float ws[4], ws2[4], wo[4];
    int lane = tid & 31, wid = tid >> 5;
    if (!lane) { ws[wid] = s; ws2[wid] = s2; }
    __syncthreads();
    s  = ws[0] + ws[1] + ws[2] + ws[3];
    s2 = ws2[0] + ws2[1] + ws2[2] + ws2[3];
    float mean = s * (1.f / NDM);
    float var  = s2 * (1.f / NDM) - mean * mean;
    float inv  = rsqrtf(var + 1e-5f);
    float4 gv = ((const float4*)g)[tid], bv = ((const float4*)bb)[tid];
    float4 o;
    o.x = (v.x - mean) * inv * gv.x + bv.x;
    o.y = (v.y - mean) * inv * gv.y + bv.y;
    o.z = (v.z - mean) * inv * gv.z + bv.z;
    o.w = (v.w - mean) * inv * gv.w + bv.w;
    ((float4*)(Out + (size_t)row * NDM))[tid] = o;
    if (H16) {
        __half2* op = (__half2*)(hOut + (size_t)row * NDM) + tid * 2;
        op[0] = h2(o.x, o.y);
        op[1] = h2(o.z, o.w);
    }
    if (SUM) {
        float os = o.x + o.y + o.z + o.w;
        #pragma unroll
        for (int off = 16; off; off >>= 1) os += __shfl_xor_sync(0xffffffffu, os, off);
        if (!lane) wo[wid] = os;
        __syncthreads();
        if (tid == 0) S[row] = wo[0] + wo[1] + wo[2] + wo[3];
    }
}

// ===========================================================================
extern "C" void kernel_launch(void* const* d_in, const int* in_sizes, int n_in,
                              void* d_out, int out_size) {
    (void)in_sizes; (void)n_in; (void)out_size;
    const float* inp     = (const float*)d_in[0];
    const float* ld_w    = (const float*)d_in[1];
    const float* ld_b    = (const float*)d_in[2];
    const float* emb_W   = (const float*)d_in[3];
    const float* emb_b   = (const float*)d_in[4];
    const float* W_pos   = (const float*)d_in[5];
    const float* vc_bn_g = (const float*)d_in[6];
    const float* vc_bn_b = (const float*)d_in[7];
    const float* vc_ln_g = (const float*)d_in[8];
    const float* vc_ln_b = (const float*)d_in[9];
    const float* vc_W1   = (const float*)d_in[10];
    const float* vc_b1   = (const float*)d_in[11];
    const float* vc_W2   = (const float*)d_in[12];
    const float* vc_b2   = (const float*)d_in[13];
    const float* aa_Wq   = (const float*)d_in[14];
    const float* aa_bq   = (const float*)d_in[15];
    const float* aa_Wk   = (const float*)d_in[16];
    // d_in[17] = aa_bk: cancels in the shift-softmax (constant logit offset)
    const float* aa_Wv   = (const float*)d_in[18];
    const float* aa_bv   = (const float*)d_in[19];
    const float* aa_Wo   = (const float*)d_in[20];
    const float* aa_bo   = (const float*)d_in[21];
    const float* aa_bn_g = (const float*)d_in[22];
    const float* aa_bn_b = (const float*)d_in[23];
    const float* aa_ln_g = (const float*)d_in[24];
    const float* aa_ln_b = (const float*)d_in[25];
    const float* aa_W1   = (const float*)d_in[26];
    const float* aa_b1   = (const float*)d_in[27];
    const float* aa_W2   = (const float*)d_in[28];
    const float* aa_b2   = (const float*)d_in[29];

    float *X, *B2, *B3, *S, *WT, *CV, *BVO;
    __half *hR, *hX, *hB1, *hB2, *hB3;
    __half *hEmb, *hVcW1, *hVcW2, *hAaW1, *hAaW2, *hWo, *hT, *hWQK, *hWvo;
    cudaGetSymbolAddress((void**)&X,    g_X);
    cudaGetSymbolAddress((void**)&B2,   g_B2);
    cudaGetSymbolAddress((void**)&B3,   g_B3);
    cudaGetSymbolAddress((void**)&S,    g_S);
    cudaGetSymbolAddress((void**)&WT,   g_W);
    cudaGetSymbolAddress((void**)&CV,   g_CV);
    cudaGetSymbolAddress((void**)&BVO,  g_BVO);
    cudaGetSymbolAddress((void**)&hR,   g_hR);
    cudaGetSymbolAddress((void**)&hX,   g_hX);
    cudaGetSymbolAddress((void**)&hB1,  g_hB1);
    cudaGetSymbolAddress((void**)&hB2,  g_hB2);
    cudaGetSymbolAddress((void**)&hB3,  g_hB3);
    cudaGetSymbolAddress((void**)&hEmb, g_hEmb);
    cudaGetSymbolAddress((void**)&hVcW1,g_hVcW1);
    cudaGetSymbolAddress((void**)&hVcW2,g_hVcW2);
    cudaGetSymbolAddress((void**)&hAaW1,g_hAaW1);
    cudaGetSymbolAddress((void**)&hAaW2,g_hAaW2);
    cudaGetSymbolAddress((void**)&hWo,  g_hWo);
    cudaGetSymbolAddress((void**)&hT,   g_hT);
    cudaGetSymbolAddress((void**)&hWQK, g_hWQK);
    cudaGetSymbolAddress((void**)&hWvo, g_hWvo);
    float* OUT = (float*)d_out;

    dim3 g512(8, 32);    // N=512 GEMM: 256 blocks
    dim3 g1024(16, 32);  // N=1024 GEMM: 512 blocks
    dim3 gpre(8, 8, 3);  // 512x512x512 precompute, z = layer

    // ---- preamble (x-independent precompute + conversions) ----
    f2h_all<<<7168, 256>>>(emb_W, vc_W1, vc_W2, aa_W1, aa_W2, aa_Wo,
                           hEmb, hVcW1, hVcW2, hAaW1, hAaW2, hWo);
    trans_f2h<<<dim3(16, 16, 9), dim3(32, 8)>>>(aa_Wk, aa_Wq, aa_Wv, hT);
    conv_residual_kernel<<<dim3(NB, NT / 64, NC / 32), 256>>>(inp, ld_w, ld_b, hR);
    bias_pre<<<dim3(4, NL, 2), 128>>>(aa_bq, aa_Wk, aa_bv, aa_bo, aa_Wo, CV, BVO);
    // WQK[l] = WkT[l] x WqT[l] ;  Wvo[l] = Wo[l] x WvT[l]
    cg_gemm<EPI_NONE, OUT_F16><<<gpre, 256>>>(hT, hT + 3 * SSQ, nullptr, nullptr,
                                              nullptr, nullptr, nullptr, hWQK,
                                              NDM, NDM, NDM, SSQ, SSQ, SSQ);
    cg_gemm<EPI_NONE, OUT_F16><<<gpre, 256>>>(hWo, hT + 6 * SSQ, nullptr, nullptr,
                                              nullptr, nullptr, nullptr, hWvo,
                                              NDM, NDM, NDM, SSQ, SSQ, SSQ);
    // embedding: X = R @ emb_W.T + emb_b + W_pos
    cg_gemm<EPI_BIAS_WPOS, OUT_F32><<<g512, 256>>>(hR, hEmb, emb_b, W_pos,
                                                   nullptr, nullptr, X, nullptr,
                                                   NM, NDM, NT, 0, 0, 0);
    rowsum_kernel<<<NM / 8, 256>>>(X, S);

    for (int l = 0; l < NL; ++l) {
        const size_t SH = (size_t)NH * NDM;
        // ---- VarCor block ----
        varcor_w_kernel<<<NB, NC>>>(S, WT);
        varcor_mix_kernel<<<dim3(NB, NDM / 64), 512>>>(X, WT, vc_bn_g + l * NC, vc_bn_b + l * NC,
                                                       B2, hB2);
        cg_gemm<EPI_BIAS_GELU, OUT_F16><<<g1024, 256>>>(hB2, hVcW1 + l * SH, vc_b1 + l * NH,
                                                        nullptr, nullptr, nullptr,
                                                        nullptr, hB1, NM, NH, NDM, 0, 0, 0);
        cg_gemm<EPI_BIAS_RES, OUT_F32><<<g512, 256>>>(hB1, hVcW2 + l * SH, vc_b2 + l * NDM,
                                                      B2, nullptr, nullptr,
                                                      B3, nullptr, NM, NDM, NH, 0, 0, 0);
        layernorm_kernel<false, true><<<NM, 128>>>(B3, vc_ln_g + l * NDM, vc_ln_b + l * NDM,
                                                   X, hX, nullptr);

        // ---- Auto-attention block ----
        cg_gemm<EPI_BIAS, OUT_F32><<<g512, 256>>>(hX, hWQK + (size_t)l * SSQ, CV + l * NDM,
                                                  nullptr, nullptr, nullptr,
                                                  B3, nullptr, NM, NDM, NDM, 0, 0, 0);
        autoshift_kernel<<<NM, 128>>>(X, B3, hB2);
        // fused V+O projection: out = xw @ Wvo^T + bvo ; + x residual ; BN
        cg_gemm<EPI_BIAS_RES_BN, OUT_BOTH><<<g512, 256>>>(hB2, hWvo + (size_t)l * SSQ,
                                                          BVO + l * NDM, X,
                                                          aa_bn_g + l * NC, aa_bn_b + l * NC,
                                                          B2, hB3, NM, NDM, NDM, 0, 0, 0);
        cg_gemm<EPI_BIAS_GELU, OUT_F16><<<g1024, 256>>>(hB3, hAaW1 + l * SH, aa_b1 + l * NH,
                                                        nullptr, nullptr, nullptr,
                                                        nullptr, hB1, NM, NH, NDM, 0, 0, 0);
        cg_gemm<EPI_BIAS_RES, OUT_F32><<<g512, 256>>>(hB1, hAaW2 + l * SH, aa_b2 + l * NDM,
                                                      B2, nullptr, nullptr,
                                                      B3, nullptr, NM, NDM, NH, 0, 0, 0);
        if (l == NL - 1) {
            layernorm_kernel<false, false><<<NM, 128>>>(B3, aa_ln_g + l * NDM, aa_ln_b + l * NDM,
                                                        OUT, nullptr, nullptr);
        } else {
            layernorm_kernel<true, true><<<NM, 128>>>(B3, aa_ln_g + l * NDM, aa_ln_b + l * NDM,
                                                      X, hX, S);
        }
    }
}

// round 11
// speedup vs baseline: 1.4560x; 1.0180x over previous
#include <cuda_runtime.h>
#include <cuda_fp16.h>
#include <math.h>
#include <stdint.h>

// Problem constants
#define NB   16
#define NT   512
#define NC   128
#define NDM  512
#define NL   3
#define NKS  25
#define NM   (NB*NC)       // 2048 rows
#define NH   (2*NDM)       // 1024 FFN hidden
#define SSQ  (NDM*NDM)     // 262144

// fp32 scratch
__device__ float g_X  [NM*NDM];
__device__ float g_B2 [NM*NDM];
__device__ float g_B3 [NM*NDM];
__device__ float g_S  [NM];
__device__ float g_W  [NB*NC*NC];
__device__ float g_CV [NL*NDM];
__device__ float g_BVO[NL*NDM];
// fp16 scratch
__device__ __align__(256) __half g_hR  [NM*NT];
__device__ __align__(256) __half g_hX  [NM*NDM];
__device__ __align__(256) __half g_hB1 [NM*NH];
__device__ __align__(256) __half g_hB2 [NM*NDM];
__device__ __align__(256) __half g_hB3 [NM*NDM];
__device__ __align__(256) __half g_hEmb [NDM*NT];
__device__ __align__(256) __half g_hVcW1[NL*NH*NDM];
__device__ __align__(256) __half g_hVcW2[NL*NDM*NH];
__device__ __align__(256) __half g_hAaW1[NL*NH*NDM];
__device__ __align__(256) __half g_hAaW2[NL*NDM*NH];
__device__ __align__(256) __half g_hWo  [NL*SSQ];
__device__ __align__(256) __half g_hT   [9*SSQ];     // WkT(l0..2), WqT, WvT
__device__ __align__(256) __half g_hWQK [NL*SSQ];
__device__ __align__(256) __half g_hWvo [NL*SSQ];

// ===========================================================================
// helpers
// ===========================================================================
__device__ __forceinline__ uint32_t smem_u32(const void* p) {
    uint32_t a;
    asm("{ .reg .u64 t; cvta.to.shared.u64 t, %1; cvt.u32.u64 %0, t; }" : "=r"(a) : "l"(p));
    return a;
}
__device__ __forceinline__ void cpa16(uint32_t dst, const void* src) {
    asm volatile("cp.async.cg.shared.global [%0], [%1], 16;" :: "r"(dst), "l"(src));
}
#define CPA_COMMIT() asm volatile("cp.async.commit_group;" ::: "memory")
#define CPA_WAIT(n)  asm volatile("cp.async.wait_group %0;" :: "n"(n) : "memory")

__device__ __forceinline__ void ldsm4(uint32_t& r0, uint32_t& r1, uint32_t& r2, uint32_t& r3,
                                      uint32_t addr) {
    asm volatile("ldmatrix.sync.aligned.m8n8.x4.shared.b16 {%0,%1,%2,%3}, [%4];"
                 : "=r"(r0), "=r"(r1), "=r"(r2), "=r"(r3) : "r"(addr));
}
__device__ __forceinline__ void mma16(float (&d)[4], const uint32_t (&a)[4], const uint32_t (&b)[2]) {
    asm volatile("mma.sync.aligned.m16n8k16.row.col.f32.f16.f16.f32 "
                 "{%0,%1,%2,%3}, {%4,%5,%6,%7}, {%8,%9}, {%0,%1,%2,%3};"
                 : "+f"(d[0]), "+f"(d[1]), "+f"(d[2]), "+f"(d[3])
                 : "r"(a[0]), "r"(a[1]), "r"(a[2]), "r"(a[3]), "r"(b[0]), "r"(b[1]));
}
__device__ __forceinline__ __half2 h2(float a, float b) {
    return __float22half2_rn(make_float2(a, b));
}

// ===========================================================================
// fp16 cp.async GEMM, z-batched: C[z;m,n] = sum_k A[z;m,k]*W[z;n,k] + epilogue
// BM=BN=64, BK=32, 4-stage ring, single sync/iter, 256 threads (2Mx4N warps).
// (identical to the R8 passing kernel)
// ===========================================================================
enum { EPI_NONE = 0, EPI_BIAS, EPI_BIAS_WPOS, EPI_BIAS_GELU, EPI_BIAS_RES, EPI_BIAS_RES_BN };
enum { OUT_F32 = 0, OUT_F16 = 1, OUT_BOTH = 2 };

#define STAGES 4
#define ROWB  80
#define TILEB (64*ROWB)                // 5120 B
#define STGB  (2*TILEB)                // 10240 B

template<int EPI, int OUTM>
__global__ __launch_bounds__(256, 3)
void cg_gemm(const __half* __restrict__ A, const __half* __restrict__ W,
             const float* __restrict__ bias, const float* __restrict__ extra,
             const float* __restrict__ bng, const float* __restrict__ bnb,
             float* __restrict__ C, __half* __restrict__ Ch,
             int M, int N, int K, int azs, int wzs, int czs) {
    __shared__ __align__(128) char sh[STAGES * STGB];   // 40 KB
    const uint32_t sbase = smem_u32(sh);

    A += (size_t)blockIdx.z * azs;
    W += (size_t)blockIdx.z * wzs;
    if (OUTM == OUT_F32 || OUTM == OUT_BOTH) C  += (size_t)blockIdx.z * czs;
    if (OUTM == OUT_F16 || OUTM == OUT_BOTH) Ch += (size_t)blockIdx.z * czs;

    int tid = threadIdx.x, wid = tid >> 5, lane = tid & 31;
    int g = lane >> 2, tg = lane & 3;
    int wm = wid & 1, wn = wid >> 1;                      // 2 x 4 warps
    int m0 = blockIdx.y * 64, n0 = blockIdx.x * 64;

    float c[2][2][4];
    #pragma unroll
    for (int i = 0; i < 2; i++)
        #pragma unroll
        for (int j = 0; j < 2; j++)
            #pragma unroll
            for (int q = 0; q < 4; q++) c[i][j][q] = 0.f;

    const int r = tid >> 2, cc = tid & 3;
    const uint32_t dOff = (uint32_t)(r * ROWB + cc * 16);
    const __half* ag = A + (size_t)(m0 + r) * K + cc * 8;
    const __half* bg = W + (size_t)(n0 + r) * K + cc * 8;

    const int lt = lane >> 3, lr8 = lane & 7;
    const uint32_t aRowOff = (uint32_t)((wm * 32 + (lt & 1) * 8 + lr8) * ROWB + (lt >> 1) * 16);
    const uint32_t bRowOff = (uint32_t)((wn * 16 + (lt >> 1) * 8 + lr8) * ROWB + (lt & 1) * 16);

    const int KC = K >> 5;

    #pragma unroll
    for (int s = 0; s < STAGES - 1; s++) {
        cpa16(sbase + s * STGB + dOff, ag + s * 32);
        cpa16(sbase + s * STGB + TILEB + dOff, bg + s * 32);
        CPA_COMMIT();
    }

    for (int kc = 0; kc < KC; kc++) {
        CPA_WAIT(STAGES - 2);          // stage kc ready
        __syncthreads();               // all readers of stage (kc-1) done -> safe to refill
        int pf = kc + STAGES - 1;
        if (pf < KC) {
            uint32_t sb = sbase + (pf % STAGES) * STGB;
            cpa16(sb + dOff, ag + (size_t)pf * 32);
            cpa16(sb + TILEB + dOff, bg + (size_t)pf * 32);
        }
        CPA_COMMIT();

        const uint32_t sA = sbase + (kc % STAGES) * STGB;
        const uint32_t sB = sA + TILEB;
        #pragma unroll
        for (int ks = 0; ks < 2; ks++) {
            uint32_t af[2][4], bf[2][2];
            #pragma unroll
            for (int mi = 0; mi < 2; mi++)
                ldsm4(af[mi][0], af[mi][1], af[mi][2], af[mi][3],
                      sA + aRowOff + mi * (16 * ROWB) + ks * 32);
            {
                uint32_t r0, r1, r2, r3;
                ldsm4(r0, r1, r2, r3, sB + bRowOff + ks * 32);
                bf[0][0] = r0; bf[0][1] = r1; bf[1][0] = r2; bf[1][1] = r3;
            }
            #pragma unroll
            for (int mi = 0; mi < 2; mi++)
                #pragma unroll
                for (int nj = 0; nj < 2; nj++) mma16(c[mi][nj], af[mi], bf[nj]);
        }
    }

    // ---- epilogue ----
    const float invs = 0.9999950000374997f;   // 1/sqrt(1+1e-5) eval-mode BN
    int mBase = m0 + wm * 32, nBase = n0 + wn * 16;
    #pragma unroll
    for (int mi = 0; mi < 2; mi++) {
        #pragma unroll
        for (int half = 0; half < 2; half++) {
            int m = mBase + mi * 16 + g + half * 8;
            float bsc = 1.f, bof = 0.f;
            if (EPI == EPI_BIAS_RES_BN) { bsc = bng[m & (NC - 1)] * invs; bof = bnb[m & (NC - 1)]; }
            #pragma unroll
            for (int nj = 0; nj < 2; nj++) {
                int n = nBase + nj * 8 + tg * 2;
                float x0 = c[mi][nj][half * 2 + 0];
                float x1 = c[mi][nj][half * 2 + 1];
                if (EPI != EPI_NONE) { x0 += bias[n]; x1 += bias[n + 1]; }
                if (EPI == EPI_BIAS_WPOS) {
                    const float* e = extra + (size_t)(m & (NC - 1)) * N + n;
                    x0 += e[0]; x1 += e[1];
                }
                if (EPI == EPI_BIAS_RES || EPI == EPI_BIAS_RES_BN) {
                    const float* e = extra + (size_t)m * N + n;
                    x0 += e[0]; x1 += e[1];
                }
                if (EPI == EPI_BIAS_GELU) {
                    x0 = 0.5f * x0 * (1.f + erff(x0 * 0.7071067811865475f));
                    x1 = 0.5f * x1 * (1.f + erff(x1 * 0.7071067811865475f));
                }
                if (EPI == EPI_BIAS_RES_BN) { x0 = x0 * bsc + bof; x1 = x1 * bsc + bof; }
                if (OUTM == OUT_F32 || OUTM == OUT_BOTH)
                    *(float2*)(C + (size_t)m * N + n) = make_float2(x0, x1);
                if (OUTM == OUT_F16 || OUTM == OUT_BOTH)
                    *(__half2*)(Ch + (size_t)m * N + n) = h2(x0, x1);
            }
        }
    }
}

// ===========================================================================
// all weight fp32->fp16 conversions, one launch (segment table, 4 elems/thread)
// ===========================================================================
__global__ void f2h_all(const float* __restrict__ emb, const float* __restrict__ vw1,
                        const float* __restrict__ vw2, const float* __restrict__ aw1,
                        const float* __restrict__ aw2, const float* __restrict__ wo,
                        __half* __restrict__ hEmb, __half* __restrict__ hVw1,
                        __half* __restrict__ hVw2, __half* __restrict__ hAw1,
                        __half* __restrict__ hAw2, __half* __restrict__ hWo) {
    long i = ((long)blockIdx.x * 256 + threadIdx.x) * 4;
    const float* s; __half* d; long off;
    if      (i < 262144L)  { s = emb; d = hEmb; off = i; }
    else if (i < 1835008L) { s = vw1; d = hVw1; off = i - 262144L; }
    else if (i < 3407872L) { s = vw2; d = hVw2; off = i - 1835008L; }
    else if (i < 4980736L) { s = aw1; d = hAw1; off = i - 3407872L; }
    else if (i < 6553600L) { s = aw2; d = hAw2; off = i - 4980736L; }
    else                   { s = wo;  d = hWo;  off = i - 6553600L; }
    float4 v = *(const float4*)(s + off);
    __half2* p = (__half2*)(d + off);
    p[0] = h2(v.x, v.y);
    p[1] = h2(v.z, v.w);
}

// ===========================================================================
// transpose + fp16: hT[z] = transpose(src_z), z: 0..2 Wk(l), 3..5 Wq(l), 6..8 Wv(l)
// ===========================================================================
__global__ void trans_f2h(const float* __restrict__ Wk, const float* __restrict__ Wq,
                          const float* __restrict__ Wv, __half* __restrict__ hT) {
    __shared__ float t[32][33];
    int z = blockIdx.z;
    const float* src = (z < 3) ? Wk + (size_t)z * SSQ
                     : (z < 6) ? Wq + (size_t)(z - 3) * SSQ
                               : Wv + (size_t)(z - 6) * SSQ;
    __half* dst = hT + (size_t)z * SSQ;
    int c0 = blockIdx.x * 32, r0 = blockIdx.y * 32;
    int tx = threadIdx.x, ty = threadIdx.y;
    #pragma unroll
    for (int i = 0; i < 4; i++)
        t[ty + i * 8][tx] = src[(size_t)(r0 + ty + i * 8) * NDM + c0 + tx];
    __syncthreads();
    #pragma unroll
    for (int i = 0; i < 4; i++)
        dst[(size_t)(c0 + ty + i * 8) * NDM + r0 + tx] = __float2half(t[tx][ty + i * 8]);
}

// ===========================================================================
// cv[l,n] = sum_j bq[j]*Wk[j,n]       (coalesced across n)
// ===========================================================================
__global__ void cv_pre(const float* __restrict__ bq, const float* __restrict__ Wk,
                       float* __restrict__ cv) {
    int l = blockIdx.y;
    const float* b  = bq + l * NDM;
    const float* wk = Wk + (size_t)l * SSQ;
    int n = blockIdx.x * 128 + threadIdx.x;
    float s = 0.f;
    for (int j = 0; j < NDM; j++) s = fmaf(b[j], wk[(size_t)j * NDM + n], s);
    cv[l * NDM + n] = s;
}
// ===========================================================================
// bvo[l,n] = Wo[n,:].bv + bo[n]       (warp per n; lanes stride the row)
// ===========================================================================
__global__ void bvo_pre(const float* __restrict__ bv, const float* __restrict__ bo,
                        const float* __restrict__ Wo, float* __restrict__ bvo) {
    int l = blockIdx.y;
    int w = threadIdx.x >> 5, lane = threadIdx.x & 31;
    int n = blockIdx.x * 8 + w;
    const float* wo = Wo + (size_t)l * SSQ + (size_t)n * NDM;
    const float* b  = bv + l * NDM;
    float s = 0.f;
    for (int j = lane; j < NDM; j += 32) s = fmaf(wo[j], b[j], s);
    #pragma unroll
    for (int o = 16; o; o >>= 1) s += __shfl_xor_sync(0xffffffffu, s, o);
    if (!lane) bvo[l * NDM + n] = s + bo[l * NDM + n];
}

// ===========================================================================
// trend conv + residual -> fp16 (B,C,T)
// ===========================================================================
__global__ void conv_residual_kernel(const float* __restrict__ inp,
                                     const float* __restrict__ w,
                                     const float* __restrict__ ldb,
                                     __half* __restrict__ R) {
    __shared__ float s[88][33];
    __shared__ float wk[NKS];
    int b = blockIdx.x, t0 = blockIdx.y * 64, c0 = blockIdx.z * 32;
    int tid = threadIdx.x;
    if (tid < NKS) wk[tid] = w[tid];
    for (int idx = tid; idx < 88 * 32; idx += 256) {
        int r = idx >> 5, c = idx & 31;
        int tg = t0 + r - 12;
        tg = min(max(tg, 0), NT - 1);
        s[r][c] = inp[((size_t)b * NT + tg) * NC + c0 + c];
    }
    __syncthreads();
    float lb = ldb[0];
    int lane = tid & 31, wy = tid >> 5;
    for (int half = 0; half < 2; ++half) {
        int ti = half * 32 + lane;
        for (int cg = 0; cg < 4; ++cg) {
            int ci = cg * 8 + wy;
            float acc = 0.f;
            #pragma unroll
            for (int k = 0; k < NKS; ++k) acc = fmaf(wk[k], s[ti + k][ci], acc);
            float v = s[ti + 12][ci] - (acc + lb);
            R[((size_t)b * NC + c0 + ci) * NT + t0 + ti] = __float2half(v);
        }
    }
}

// ===========================================================================
// row sums of X (varcor logits)
// ===========================================================================
__global__ void rowsum_kernel(const float* __restrict__ X, float* __restrict__ S) {
    int row = blockIdx.x * 8 + (threadIdx.x >> 5);
    int lane = threadIdx.x & 31;
    const float* xr = X + (size_t)row * NDM;
    float s = 0.f;
    for (int i = lane; i < NDM; i += 32) s += xr[i];
    #pragma unroll
    for (int o = 16; o; o >>= 1) s += __shfl_xor_sync(0xffffffffu, s, o);
    if (!lane) S[row] = s;
}

// ===========================================================================
// varcor softmax weights
// ===========================================================================
__global__ void varcor_w_kernel(const float* __restrict__ S, float* __restrict__ Wt) {
    __shared__ float ss[NC];
    int b = blockIdx.x, d = threadIdx.x;
    ss[d] = S[b * NC + d];
    __syncthreads();
    const float VS = 8.6316746e-05f;            // 1/(512*sqrt(512))
    float sd = ss[d];
    float mx = -1e30f;
    #pragma unroll 8
    for (int e = 0; e < NC; e++) mx = fmaxf(mx, sd * ss[e]);
    float sum = 0.f;
    #pragma unroll 8
    for (int e = 0; e < NC; e++) sum += __expf((sd * ss[e] - mx) * VS);
    float rs = 1.f / sum;
    float* wr = Wt + ((size_t)b * NC + d) * NC;
    #pragma unroll 8
    for (int e = 0; e < NC; e++) wr[e] = __expf((sd * ss[e] - mx) * VS) * rs;
}

// ===========================================================================
// varcor mix + residual + BN -> fp32 + fp16
// ===========================================================================
__global__ __launch_bounds__(512)
void varcor_mix_kernel(const float* __restrict__ X, const float* __restrict__ Wt,
                       const float* __restrict__ bng, const float* __restrict__ bnb,
                       float* __restrict__ Out, __half* __restrict__ hOut) {
    __shared__ float xs[NC][64];
    int b = blockIdx.x, j0 = blockIdx.y * 64;
    int tid = threadIdx.x;
    const float* xb = X + (size_t)b * NC * NDM;
    #pragma unroll
    for (int i = 0; i < 4; i++) {
        int f = tid + i * 512;
        int e = f >> 4, q = f & 15;
        *(float4*)&xs[e][q * 4] = ((const float4*)(xb + (size_t)e * NDM + j0))[q];
    }
    __syncthreads();

    int d = tid >> 2, q = tid & 3, jb = q * 16;
    const float* wr = Wt + ((size_t)b * NC + d) * NC;
    float4 acc[4];
    #pragma unroll
    for (int t = 0; t < 4; t++) acc[t] = make_float4(0.f, 0.f, 0.f, 0.f);
    #pragma unroll 4
    for (int e = 0; e < NC; e++) {
        float w = __ldg(wr + e);
        #pragma unroll
        for (int t = 0; t < 4; t++) {
            float4 xv = *(float4*)&xs[e][jb + t * 4];
            acc[t].x = fmaf(w, xv.x, acc[t].x);
            acc[t].y = fmaf(w, xv.y, acc[t].y);
            acc[t].z = fmaf(w, xv.z, acc[t].z);
            acc[t].w = fmaf(w, xv.w, acc[t].w);
        }
    }
    const float invs = 0.9999950000374997f;
    float bsc = bng[d] * invs, bof = bnb[d];
    size_t base = ((size_t)b * NC + d) * NDM + j0 + jb;
    #pragma unroll
    for (int t = 0; t < 4; t++) {
        float4 xv = *(float4*)&xs[d][jb + t * 4];
        float4 o;
        o.x = (acc[t].x + xv.x) * bsc + bof;
        o.y = (acc[t].y + xv.y) * bsc + bof;
        o.z = (acc[t].z + xv.z) * bsc + bof;
        o.w = (acc[t].w + xv.w) * bsc + bof;
        *(float4*)(Out + base + t * 4) = o;
        *(__half2*)(hOut + base + t * 4)     = h2(o.x, o.y);
        *(__half2*)(hOut + base + t * 4 + 2) = h2(o.z, o.w);
    }
}

// ===========================================================================
// auto-attn shift scores + softmax + weighted shift sum -> fp16
// ===========================================================================
__global__ void autoshift_kernel(const float* __restrict__ X, const float* __restrict__ U,
                                 __half* __restrict__ XW) {
    __shared__ float xr[NDM];
    __shared__ float red[8][4];
    int row = blockIdx.x, tid = threadIdx.x;
    const float4 xv = ((const float4*)(X + (size_t)row * NDM))[tid];
    ((float4*)xr)[tid] = xv;
    const float4 uv = ((const float4*)(U + (size_t)row * NDM))[tid];
    __syncthreads();

    float sc[8];
    #pragma unroll
    for (int s = 0; s < 8; s++) {
        float4 x4 = ((float4*)xr)[(tid + 16 * s) & 127];
        sc[s] = uv.x * x4.x + uv.y * x4.y + uv.z * x4.z + uv.w * x4.w;
    }
    int lane = tid & 31, wid = tid >> 5;
    #pragma unroll
    for (int s = 0; s < 8; s++) {
        float v = sc[s];
        #pragma unroll
        for (int o = 16; o; o >>= 1) v += __shfl_xor_sync(0xffffffffu, v, o);
        if (!lane) red[s][wid] = v;
    }
    __syncthreads();
    const float rsq = 0.04419417382415922f;    // DM^-0.5
    float lg[8], mx = -1e30f;
    #pragma unroll
    for (int s = 0; s < 8; s++) {
        lg[s] = (red[s][0] + red[s][1] + red[s][2] + red[s][3]) * rsq;
        mx = fmaxf(mx, lg[s]);
    }
    float w[8], sum = 0.f;
    #pragma unroll
    for (int s = 0; s < 8; s++) { w[s] = __expf(lg[s] - mx); sum += w[s]; }
    float rs = 1.f / sum;
    float4 o = make_float4(0.f, 0.f, 0.f, 0.f);
    #pragma unroll
    for (int s = 0; s < 8; s++) {
        float4 x4 = ((float4*)xr)[(tid + 16 * s) & 127];
        float ws = w[s] * rs;
        o.x = fmaf(ws, x4.x, o.x); o.y = fmaf(ws, x4.y, o.y);
        o.z = fmaf(ws, x4.z, o.z); o.w = fmaf(ws, x4.w, o.w);
    }
    __half2* op = (__half2*)(XW + (size_t)row * NDM) + tid * 2;
    op[0] = h2(o.x, o.y);
    op[1] = h2(o.z, o.w);
}

// ===========================================================================
// LayerNorm; optional fp16 twin + fused rowsum of output
// ===========================================================================
template<bool SUM, bool H16>
__global__ void layernorm_kernel(const float* __restrict__ In, const float* __restrict__ g,
                                 const float* __restrict__ bb, float* __restrict__ Out,
                                 __half* __restrict__ hOut, float* __restrict__ S) {
    int row = blockIdx.x, tid = threadIdx.x;
    const float4 v = ((const float4*)(In + (size_t)row * NDM))[tid];
    float s  = v.x + v.y + v.z + v.w;
    float s2 = v.x * v.x + v.y * v.y + v.z * v.z + v.w * v.w;
    #pragma unroll
    for (int o = 16; o; o >>= 1) {
        s  += __shfl_xor_sync(0xffffffffu, s, o);
        s2 += __shfl_xor_sync(0xffffffffu, s2, o);
    }
    __shared__ float ws[4], ws2[4], wo[4];
    int lane = tid & 31, wid = tid >> 5;
    if (!lane) { ws[wid] = s; ws2[wid] = s2; }
    __syncthreads();
    s  = ws[0] + ws[1] + ws[2] + ws[3];
    s2 = ws2[0] + ws2[1] + ws2[2] + ws2[3];
    float mean = s * (1.f / NDM);
    float var  = s2 * (1.f / NDM) - mean * mean;
    float inv  = rsqrtf(var + 1e-5f);
    float4 gv = ((const float4*)g)[tid], bv = ((const float4*)bb)[tid];
    float4 o;
    o.x = (v.x - mean) * inv * gv.x + bv.x;
    o.y = (v.y - mean) * inv * gv.y + bv.y;
    o.z = (v.z - mean) * inv * gv.z + bv.z;
    o.w = (v.w - mean) * inv * gv.w + bv.w;
    ((float4*)(Out + (size_t)row * NDM))[tid] = o;
    if (H16) {
        __half2* op = (__half2*)(hOut + (size_t)row * NDM) + tid * 2;
        op[0] = h2(o.x, o.y);
        op[1] = h2(o.z, o.w);
    }
    if (SUM) {
        float os = o.x + o.y + o.z + o.w;
        #pragma unroll
        for (int off = 16; off; off >>= 1) os += __shfl_xor_sync(0xffffffffu, os, off);
        if (!lane) wo[wid] = os;
        __syncthreads();
        if (tid == 0) S[row] = wo[0] + wo[1] + wo[2] + wo[3];
    }
}

// ===========================================================================
extern "C" void kernel_launch(void* const* d_in, const int* in_sizes, int n_in,
                              void* d_out, int out_size) {
    (void)in_sizes; (void)n_in; (void)out_size;
    const float* inp     = (const float*)d_in[0];
    const float* ld_w    = (const float*)d_in[1];
    const float* ld_b    = (const float*)d_in[2];
    const float* emb_W   = (const float*)d_in[3];
    const float* emb_b   = (const float*)d_in[4];
    const float* W_pos   = (const float*)d_in[5];
    const float* vc_bn_g = (const float*)d_in[6];
    const float* vc_bn_b = (const float*)d_in[7];
    const float* vc_ln_g = (const float*)d_in[8];
    const float* vc_ln_b = (const float*)d_in[9];
    const float* vc_W1   = (const float*)d_in[10];
    const float* vc_b1   = (const float*)d_in[11];
    const float* vc_W2   = (const float*)d_in[12];
    const float* vc_b2   = (const float*)d_in[13];
    const float* aa_Wq   = (const float*)d_in[14];
    const float* aa_bq   = (const float*)d_in[15];
    const float* aa_Wk   = (const float*)d_in[16];
    // d_in[17] = aa_bk: cancels in the shift-softmax (constant logit offset)
    const float* aa_Wv   = (const float*)d_in[18];
    const float* aa_bv   = (const float*)d_in[19];
    const float* aa_Wo   = (const float*)d_in[20];
    const float* aa_bo   = (const float*)d_in[21];
    const float* aa_bn_g = (const float*)d_in[22];
    const float* aa_bn_b = (const float*)d_in[23];
    const float* aa_ln_g = (const float*)d_in[24];
    const float* aa_ln_b = (const float*)d_in[25];
    const float* aa_W1   = (const float*)d_in[26];
    const float* aa_b1   = (const float*)d_in[27];
    const float* aa_W2   = (const float*)d_in[28];
    const float* aa_b2   = (const float*)d_in[29];

    float *X, *B2, *B3, *S, *WT, *CV, *BVO;
    __half *hR, *hX, *hB1, *hB2, *hB3;
    __half *hEmb, *hVcW1, *hVcW2, *hAaW1, *hAaW2, *hWo, *hT, *hWQK, *hWvo;
    cudaGetSymbolAddress((void**)&X,    g_X);
    cudaGetSymbolAddress((void**)&B2,   g_B2);
    cudaGetSymbolAddress((void**)&B3,   g_B3);
    cudaGetSymbolAddress((void**)&S,    g_S);
    cudaGetSymbolAddress((void**)&WT,   g_W);
    cudaGetSymbolAddress((void**)&CV,   g_CV);
    cudaGetSymbolAddress((void**)&BVO,  g_BVO);
    cudaGetSymbolAddress((void**)&hR,   g_hR);
    cudaGetSymbolAddress((void**)&hX,   g_hX);
    cudaGetSymbolAddress((void**)&hB1,  g_hB1);
    cudaGetSymbolAddress((void**)&hB2,  g_hB2);
    cudaGetSymbolAddress((void**)&hB3,  g_hB3);
    cudaGetSymbolAddress((void**)&hEmb, g_hEmb);
    cudaGetSymbolAddress((void**)&hVcW1,g_hVcW1);
    cudaGetSymbolAddress((void**)&hVcW2,g_hVcW2);
    cudaGetSymbolAddress((void**)&hAaW1,g_hAaW1);
    cudaGetSymbolAddress((void**)&hAaW2,g_hAaW2);
    cudaGetSymbolAddress((void**)&hWo,  g_hWo);
    cudaGetSymbolAddress((void**)&hT,   g_hT);
    cudaGetSymbolAddress((void**)&hWQK, g_hWQK);
    cudaGetSymbolAddress((void**)&hWvo, g_hWvo);
    float* OUT = (float*)d_out;

    dim3 g512(8, 32);    // N=512 GEMM: 256 blocks
    dim3 g1024(16, 32);  // N=1024 GEMM: 512 blocks
    dim3 gpre(8, 8, 3);  // 512x512x512 precompute, z = layer

    // ---- preamble (x-independent precompute + conversions) ----
    f2h_all<<<7168, 256>>>(emb_W, vc_W1, vc_W2, aa_W1, aa_W2, aa_Wo,
                           hEmb, hVcW1, hVcW2, hAaW1, hAaW2, hWo);
    trans_f2h<<<dim3(16, 16, 9), dim3(32, 8)>>>(aa_Wk, aa_Wq, aa_Wv, hT);
    conv_residual_kernel<<<dim3(NB, NT / 64, NC / 32), 256>>>(inp, ld_w, ld_b, hR);
    cv_pre<<<dim3(4, NL), 128>>>(aa_bq, aa_Wk, CV);
    bvo_pre<<<dim3(NDM / 8, NL), 256>>>(aa_bv, aa_bo, aa_Wo, BVO);
    // WQK[l] = WkT[l] x WqT[l] ;  Wvo[l] = Wo[l] x WvT[l]
    cg_gemm<EPI_NONE, OUT_F16><<<gpre, 256>>>(hT, hT + 3 * SSQ, nullptr, nullptr,
                                              nullptr, nullptr, nullptr, hWQK,
                                              NDM, NDM, NDM, SSQ, SSQ, SSQ);
    cg_gemm<EPI_NONE, OUT_F16><<<gpre, 256>>>(hWo, hT + 6 * SSQ, nullptr, nullptr,
                                              nullptr, nullptr, nullptr, hWvo,
                                              NDM, NDM, NDM, SSQ, SSQ, SSQ);
    // embedding: X = R @ emb_W.T + emb_b + W_pos
    cg_gemm<EPI_BIAS_WPOS, OUT_F32><<<g512, 256>>>(hR, hEmb, emb_b, W_pos,
                                                   nullptr, nullptr, X, nullptr,
                                                   NM, NDM, NT, 0, 0, 0);
    rowsum_kernel<<<NM / 8, 256>>>(X, S);

    for (int l = 0; l < NL; ++l) {
        const size_t SH = (size_t)NH * NDM;
        // ---- VarCor block ----
        varcor_w_kernel<<<NB, NC>>>(S, WT);
        varcor_mix_kernel<<<dim3(NB, NDM / 64), 512>>>(X, WT, vc_bn_g + l * NC, vc_bn_b + l * NC,
                                                       B2, hB2);
        cg_gemm<EPI_BIAS_GELU, OUT_F16><<<g1024, 256>>>(hB2, hVcW1 + l * SH, vc_b1 + l * NH,
                                                        nullptr, nullptr, nullptr,
                                                        nullptr, hB1, NM, NH, NDM, 0, 0, 0);
        cg_gemm<EPI_BIAS_RES, OUT_F32><<<g512, 256>>>(hB1, hVcW2 + l * SH, vc_b2 + l * NDM,
                                                      B2, nullptr, nullptr,
                                                      B3, nullptr, NM, NDM, NH, 0, 0, 0);
        layernorm_kernel<false, true><<<NM, 128>>>(B3, vc_ln_g + l * NDM, vc_ln_b + l * NDM,
                                                   X, hX, nullptr);

        // ---- Auto-attention block ----
        cg_gemm<EPI_BIAS, OUT_F32><<<g512, 256>>>(hX, hWQK + (size_t)l * SSQ, CV + l * NDM,
                                                  nullptr, nullptr, nullptr,
                                                  B3, nullptr, NM, NDM, NDM, 0, 0, 0);
        autoshift_kernel<<<NM, 128>>>(X, B3, hB2);
        // fused V+O projection: out = xw @ Wvo^T + bvo ; + x residual ; BN
        cg_gemm<EPI_BIAS_RES_BN, OUT_BOTH><<<g512, 256>>>(hB2, hWvo + (size_t)l * SSQ,
                                                          BVO + l * NDM, X,
                                                          aa_bn_g + l * NC, aa_bn_b + l * NC,
                                                          B2, hB3, NM, NDM, NDM, 0, 0, 0);
        cg_gemm<EPI_BIAS_GELU, OUT_F16><<<g1024, 256>>>(hB3, hAaW1 + l * SH, aa_b1 + l * NH,
                                                        nullptr, nullptr, nullptr,
                                                        nullptr, hB1, NM, NH, NDM, 0, 0, 0);
        cg_gemm<EPI_BIAS_RES, OUT_F32><<<g512, 256>>>(hB1, hAaW2 + l * SH, aa_b2 + l * NDM,
                                                      B2, nullptr, nullptr,
                                                      B3, nullptr, NM, NDM, NH, 0, 0, 0);
        if (l == NL - 1) {
            layernorm_kernel<false, false><<<NM, 128>>>(B3, aa_ln_g + l * NDM, aa_ln_b + l * NDM,
                                                        OUT, nullptr, nullptr);
        } else {
            layernorm_kernel<true, true><<<NM, 128>>>(B3, aa_ln_g + l * NDM, aa_ln_b + l * NDM,
                                                      X, hX, S);
        }
    }
}

// round 12
// speedup vs baseline: 1.5057x; 1.0341x over previous
#include <cuda_runtime.h>
#include <cuda_fp16.h>
#include <math.h>
#include <stdint.h>

// Problem constants
#define NB   16
#define NT   512
#define NC   128
#define NDM  512
#define NL   3
#define NKS  25
#define NM   (NB*NC)       // 2048 rows
#define NH   (2*NDM)       // 1024 FFN hidden
#define SSQ  (NDM*NDM)     // 262144

// fp32 scratch
__device__ float g_X  [NM*NDM];
__device__ float g_B2 [NM*NDM];
__device__ float g_B3 [NM*NDM];
__device__ float g_S  [NM];
__device__ float g_W  [NB*NC*NC];
__device__ float g_CV [NL*NDM];
__device__ float g_BVO[NL*NDM];
// fp16 scratch
__device__ __align__(256) __half g_hR  [NM*NT];
__device__ __align__(256) __half g_hX  [NM*NDM];
__device__ __align__(256) __half g_hB1 [NM*NH];
__device__ __align__(256) __half g_hB2 [NM*NDM];
__device__ __align__(256) __half g_hB3 [NM*NDM];
__device__ __align__(256) __half g_hEmb [NDM*NT];
__device__ __align__(256) __half g_hVcW1[NL*NH*NDM];
__device__ __align__(256) __half g_hVcW2[NL*NDM*NH];
__device__ __align__(256) __half g_hAaW1[NL*NH*NDM];
__device__ __align__(256) __half g_hAaW2[NL*NDM*NH];
__device__ __align__(256) __half g_hWo  [NL*SSQ];
__device__ __align__(256) __half g_hT   [9*SSQ];     // WkT(l0..2), WqT, WvT
__device__ __align__(256) __half g_hWQK [NL*SSQ];
__device__ __align__(256) __half g_hWvo [NL*SSQ];

// ===========================================================================
// helpers
// ===========================================================================
__device__ __forceinline__ uint32_t smem_u32(const void* p) {
    uint32_t a;
    asm("{ .reg .u64 t; cvta.to.shared.u64 t, %1; cvt.u32.u64 %0, t; }" : "=r"(a) : "l"(p));
    return a;
}
__device__ __forceinline__ void cpa16(uint32_t dst, const void* src) {
    asm volatile("cp.async.cg.shared.global [%0], [%1], 16;" :: "r"(dst), "l"(src));
}
#define CPA_COMMIT() asm volatile("cp.async.commit_group;" ::: "memory")
#define CPA_WAIT(n)  asm volatile("cp.async.wait_group %0;" :: "n"(n) : "memory")

__device__ __forceinline__ void ldsm4(uint32_t& r0, uint32_t& r1, uint32_t& r2, uint32_t& r3,
                                      uint32_t addr) {
    asm volatile("ldmatrix.sync.aligned.m8n8.x4.shared.b16 {%0,%1,%2,%3}, [%4];"
                 : "=r"(r0), "=r"(r1), "=r"(r2), "=r"(r3) : "r"(addr));
}
__device__ __forceinline__ void mma16(float (&d)[4], const uint32_t (&a)[4], const uint32_t (&b)[2]) {
    asm volatile("mma.sync.aligned.m16n8k16.row.col.f32.f16.f16.f32 "
                 "{%0,%1,%2,%3}, {%4,%5,%6,%7}, {%8,%9}, {%0,%1,%2,%3};"
                 : "+f"(d[0]), "+f"(d[1]), "+f"(d[2]), "+f"(d[3])
                 : "r"(a[0]), "r"(a[1]), "r"(a[2]), "r"(a[3]), "r"(b[0]), "r"(b[1]));
}
__device__ __forceinline__ __half2 h2(float a, float b) {
    return __float22half2_rn(make_float2(a, b));
}

// ===========================================================================
// fp16 cp.async GEMM, z-batched: C[z;m,n] = sum_k A[z;m,k]*W[z;n,k] + epilogue
// BM=BN=64, BK=32, 4-stage ring, single sync/iter, 256 threads (2Mx4N warps).
// ===========================================================================
enum { EPI_NONE = 0, EPI_BIAS, EPI_BIAS_WPOS, EPI_BIAS_GELU, EPI_BIAS_RES, EPI_BIAS_RES_BN };
enum { OUT_F32 = 0, OUT_F16 = 1, OUT_BOTH = 2 };

#define STAGES 4
#define ROWB  80
#define TILEB (64*ROWB)                // 5120 B
#define STGB  (2*TILEB)                // 10240 B

template<int EPI, int OUTM>
__global__ __launch_bounds__(256, 3)
void cg_gemm(const __half* __restrict__ A, const __half* __restrict__ W,
             const float* __restrict__ bias, const float* __restrict__ extra,
             const float* __restrict__ bng, const float* __restrict__ bnb,
             float* __restrict__ C, __half* __restrict__ Ch,
             int M, int N, int K, int azs, int wzs, int czs) {
    __shared__ __align__(128) char sh[STAGES * STGB];   // 40 KB
    const uint32_t sbase = smem_u32(sh);

    A += (size_t)blockIdx.z * azs;
    W += (size_t)blockIdx.z * wzs;
    if (OUTM == OUT_F32 || OUTM == OUT_BOTH) C  += (size_t)blockIdx.z * czs;
    if (OUTM == OUT_F16 || OUTM == OUT_BOTH) Ch += (size_t)blockIdx.z * czs;

    int tid = threadIdx.x, wid = tid >> 5, lane = tid & 31;
    int g = lane >> 2, tg = lane & 3;
    int wm = wid & 1, wn = wid >> 1;                      // 2 x 4 warps
    int m0 = blockIdx.y * 64, n0 = blockIdx.x * 64;

    float c[2][2][4];
    #pragma unroll
    for (int i = 0; i < 2; i++)
        #pragma unroll
        for (int j = 0; j < 2; j++)
            #pragma unroll
            for (int q = 0; q < 4; q++) c[i][j][q] = 0.f;

    const int r = tid >> 2, cc = tid & 3;
    const uint32_t dOff = (uint32_t)(r * ROWB + cc * 16);
    const __half* ag = A + (size_t)(m0 + r) * K + cc * 8;
    const __half* bg = W + (size_t)(n0 + r) * K + cc * 8;

    const int lt = lane >> 3, lr8 = lane & 7;
    const uint32_t aRowOff = (uint32_t)((wm * 32 + (lt & 1) * 8 + lr8) * ROWB + (lt >> 1) * 16);
    const uint32_t bRowOff = (uint32_t)((wn * 16 + (lt >> 1) * 8 + lr8) * ROWB + (lt & 1) * 16);

    const int KC = K >> 5;

    #pragma unroll
    for (int s = 0; s < STAGES - 1; s++) {
        cpa16(sbase + s * STGB + dOff, ag + s * 32);
        cpa16(sbase + s * STGB + TILEB + dOff, bg + s * 32);
        CPA_COMMIT();
    }

    for (int kc = 0; kc < KC; kc++) {
        CPA_WAIT(STAGES - 2);          // stage kc ready
        __syncthreads();               // all readers of stage (kc-1) done -> safe to refill
        int pf = kc + STAGES - 1;
        if (pf < KC) {
            uint32_t sb = sbase + (pf % STAGES) * STGB;
            cpa16(sb + dOff, ag + (size_t)pf * 32);
            cpa16(sb + TILEB + dOff, bg + (size_t)pf * 32);
        }
        CPA_COMMIT();

        const uint32_t sA = sbase + (kc % STAGES) * STGB;
        const uint32_t sB = sA + TILEB;
        #pragma unroll
        for (int ks = 0; ks < 2; ks++) {
            uint32_t af[2][4], bf[2][2];
            #pragma unroll
            for (int mi = 0; mi < 2; mi++)
                ldsm4(af[mi][0], af[mi][1], af[mi][2], af[mi][3],
                      sA + aRowOff + mi * (16 * ROWB) + ks * 32);
            {
                uint32_t r0, r1, r2, r3;
                ldsm4(r0, r1, r2, r3, sB + bRowOff + ks * 32);
                bf[0][0] = r0; bf[0][1] = r1; bf[1][0] = r2; bf[1][1] = r3;
            }
            #pragma unroll
            for (int mi = 0; mi < 2; mi++)
                #pragma unroll
                for (int nj = 0; nj < 2; nj++) mma16(c[mi][nj], af[mi], bf[nj]);
        }
    }

    // ---- epilogue ----
    const float invs = 0.9999950000374997f;   // 1/sqrt(1+1e-5) eval-mode BN
    int mBase = m0 + wm * 32, nBase = n0 + wn * 16;
    #pragma unroll
    for (int mi = 0; mi < 2; mi++) {
        #pragma unroll
        for (int half = 0; half < 2; half++) {
            int m = mBase + mi * 16 + g + half * 8;
            float bsc = 1.f, bof = 0.f;
            if (EPI == EPI_BIAS_RES_BN) { bsc = bng[m & (NC - 1)] * invs; bof = bnb[m & (NC - 1)]; }
            #pragma unroll
            for (int nj = 0; nj < 2; nj++) {
                int n = nBase + nj * 8 + tg * 2;
                float x0 = c[mi][nj][half * 2 + 0];
                float x1 = c[mi][nj][half * 2 + 1];
                if (EPI != EPI_NONE) { x0 += bias[n]; x1 += bias[n + 1]; }
                if (EPI == EPI_BIAS_WPOS) {
                    const float* e = extra + (size_t)(m & (NC - 1)) * N + n;
                    x0 += e[0]; x1 += e[1];
                }
                if (EPI == EPI_BIAS_RES || EPI == EPI_BIAS_RES_BN) {
                    const float* e = extra + (size_t)m * N + n;
                    x0 += e[0]; x1 += e[1];
                }
                if (EPI == EPI_BIAS_GELU) {
                    x0 = 0.5f * x0 * (1.f + erff(x0 * 0.7071067811865475f));
                    x1 = 0.5f * x1 * (1.f + erff(x1 * 0.7071067811865475f));
                }
                if (EPI == EPI_BIAS_RES_BN) { x0 = x0 * bsc + bof; x1 = x1 * bsc + bof; }
                if (OUTM == OUT_F32 || OUTM == OUT_BOTH)
                    *(float2*)(C + (size_t)m * N + n) = make_float2(x0, x1);
                if (OUTM == OUT_F16 || OUTM == OUT_BOTH)
                    *(__half2*)(Ch + (size_t)m * N + n) = h2(x0, x1);
            }
        }
    }
}

// ===========================================================================
// all weight fp32->fp16 conversions, one launch (segment table, 4 elems/thread)
// ===========================================================================
__global__ void f2h_all(const float* __restrict__ emb, const float* __restrict__ vw1,
                        const float* __restrict__ vw2, const float* __restrict__ aw1,
                        const float* __restrict__ aw2, const float* __restrict__ wo,
                        __half* __restrict__ hEmb, __half* __restrict__ hVw1,
                        __half* __restrict__ hVw2, __half* __restrict__ hAw1,
                        __half* __restrict__ hAw2, __half* __restrict__ hWo) {
    long i = ((long)blockIdx.x * 256 + threadIdx.x) * 4;
    const float* s; __half* d; long off;
    if      (i < 262144L)  { s = emb; d = hEmb; off = i; }
    else if (i < 1835008L) { s = vw1; d = hVw1; off = i - 262144L; }
    else if (i < 3407872L) { s = vw2; d = hVw2; off = i - 1835008L; }
    else if (i < 4980736L) { s = aw1; d = hAw1; off = i - 3407872L; }
    else if (i < 6553600L) { s = aw2; d = hAw2; off = i - 4980736L; }
    else                   { s = wo;  d = hWo;  off = i - 6553600L; }
    float4 v = *(const float4*)(s + off);
    __half2* p = (__half2*)(d + off);
    p[0] = h2(v.x, v.y);
    p[1] = h2(v.z, v.w);
}

// ===========================================================================
// transpose + fp16: hT[z] = transpose(src_z), z: 0..2 Wk(l), 3..5 Wq(l), 6..8 Wv(l)
// ===========================================================================
__global__ void trans_f2h(const float* __restrict__ Wk, const float* __restrict__ Wq,
                          const float* __restrict__ Wv, __half* __restrict__ hT) {
    __shared__ float t[32][33];
    int z = blockIdx.z;
    const float* src = (z < 3) ? Wk + (size_t)z * SSQ
                     : (z < 6) ? Wq + (size_t)(z - 3) * SSQ
                               : Wv + (size_t)(z - 6) * SSQ;
    __half* dst = hT + (size_t)z * SSQ;
    int c0 = blockIdx.x * 32, r0 = blockIdx.y * 32;
    int tx = threadIdx.x, ty = threadIdx.y;
    #pragma unroll
    for (int i = 0; i < 4; i++)
        t[ty + i * 8][tx] = src[(size_t)(r0 + ty + i * 8) * NDM + c0 + tx];
    __syncthreads();
    #pragma unroll
    for (int i = 0; i < 4; i++)
        dst[(size_t)(c0 + ty + i * 8) * NDM + r0 + tx] = __float2half(t[tx][ty + i * 8]);
}

// ===========================================================================
// cv[l,n] = sum_j bq[l,j]*WkT[l; n,j]  (warp per n over contiguous fp16 row)
// uses hT (WkT) produced by trans_f2h — must run after it.
// ===========================================================================
__global__ void cv_pre(const float* __restrict__ bq, const __half* __restrict__ hT,
                       float* __restrict__ cv) {
    int l = blockIdx.y;
    int w = threadIdx.x >> 5, lane = threadIdx.x & 31;
    int n = blockIdx.x * 8 + w;
    const __half* wk = hT + (size_t)l * SSQ + (size_t)n * NDM;   // WkT row: contiguous over j
    const float* b = bq + l * NDM;
    float s = 0.f;
    #pragma unroll 4
    for (int j = lane; j < NDM; j += 32) s = fmaf(__half2float(wk[j]), b[j], s);
    #pragma unroll
    for (int o = 16; o; o >>= 1) s += __shfl_xor_sync(0xffffffffu, s, o);
    if (!lane) cv[l * NDM + n] = s;
}
// ===========================================================================
// bvo[l,n] = Wo[n,:].bv + bo[n]       (warp per n; lanes stride the row)
// ===========================================================================
__global__ void bvo_pre(const float* __restrict__ bv, const float* __restrict__ bo,
                        const float* __restrict__ Wo, float* __restrict__ bvo) {
    int l = blockIdx.y;
    int w = threadIdx.x >> 5, lane = threadIdx.x & 31;
    int n = blockIdx.x * 8 + w;
    const float* wo = Wo + (size_t)l * SSQ + (size_t)n * NDM;
    const float* b  = bv + l * NDM;
    float s = 0.f;
    for (int j = lane; j < NDM; j += 32) s = fmaf(wo[j], b[j], s);
    #pragma unroll
    for (int o = 16; o; o >>= 1) s += __shfl_xor_sync(0xffffffffu, s, o);
    if (!lane) bvo[l * NDM + n] = s + bo[l * NDM + n];
}

// ===========================================================================
// trend conv + residual -> fp16 (B,C,T)
// ===========================================================================
__global__ void conv_residual_kernel(const float* __restrict__ inp,
                                     const float* __restrict__ w,
                                     const float* __restrict__ ldb,
                                     __half* __restrict__ R) {
    __shared__ float s[88][33];
    __shared__ float wk[NKS];
    int b = blockIdx.x, t0 = blockIdx.y * 64, c0 = blockIdx.z * 32;
    int tid = threadIdx.x;
    if (tid < NKS) wk[tid] = w[tid];
    for (int idx = tid; idx < 88 * 32; idx += 256) {
        int r = idx >> 5, c = idx & 31;
        int tg = t0 + r - 12;
        tg = min(max(tg, 0), NT - 1);
        s[r][c] = inp[((size_t)b * NT + tg) * NC + c0 + c];
    }
    __syncthreads();
    float lb = ldb[0];
    int lane = tid & 31, wy = tid >> 5;
    for (int half = 0; half < 2; ++half) {
        int ti = half * 32 + lane;
        for (int cg = 0; cg < 4; ++cg) {
            int ci = cg * 8 + wy;
            float acc = 0.f;
            #pragma unroll
            for (int k = 0; k < NKS; ++k) acc = fmaf(wk[k], s[ti + k][ci], acc);
            float v = s[ti + 12][ci] - (acc + lb);
            R[((size_t)b * NC + c0 + ci) * NT + t0 + ti] = __float2half(v);
        }
    }
}

// ===========================================================================
// row sums of X (varcor logits)
// ===========================================================================
__global__ void rowsum_kernel(const float* __restrict__ X, float* __restrict__ S) {
    int row = blockIdx.x * 8 + (threadIdx.x >> 5);
    int lane = threadIdx.x & 31;
    const float* xr = X + (size_t)row * NDM;
    float s = 0.f;
    for (int i = lane; i < NDM; i += 32) s += xr[i];
    #pragma unroll
    for (int o = 16; o; o >>= 1) s += __shfl_xor_sync(0xffffffffu, s, o);
    if (!lane) S[row] = s;
}

// ===========================================================================
// varcor softmax weights
// ===========================================================================
__global__ void varcor_w_kernel(const float* __restrict__ S, float* __restrict__ Wt) {
    __shared__ float ss[NC];
    int b = blockIdx.x, d = threadIdx.x;
    ss[d] = S[b * NC + d];
    __syncthreads();
    const float VS = 8.6316746e-05f;            // 1/(512*sqrt(512))
    float sd = ss[d];
    float mx = -1e30f;
    #pragma unroll 8
    for (int e = 0; e < NC; e++) mx = fmaxf(mx, sd * ss[e]);
    float sum = 0.f;
    #pragma unroll 8
    for (int e = 0; e < NC; e++) sum += __expf((sd * ss[e] - mx) * VS);
    float rs = 1.f / sum;
    float* wr = Wt + ((size_t)b * NC + d) * NC;
    #pragma unroll 8
    for (int e = 0; e < NC; e++) wr[e] = __expf((sd * ss[e] - mx) * VS) * rs;
}

// ===========================================================================
// varcor mix + residual + BN -> fp32 + fp16
// ===========================================================================
__global__ __launch_bounds__(512)
void varcor_mix_kernel(const float* __restrict__ X, const float* __restrict__ Wt,
                       const float* __restrict__ bng, const float* __restrict__ bnb,
                       float* __restrict__ Out, __half* __restrict__ hOut) {
    __shared__ float xs[NC][64];
    int b = blockIdx.x, j0 = blockIdx.y * 64;
    int tid = threadIdx.x;
    const float* xb = X + (size_t)b * NC * NDM;
    #pragma unroll
    for (int i = 0; i < 4; i++) {
        int f = tid + i * 512;
        int e = f >> 4, q = f & 15;
        *(float4*)&xs[e][q * 4] = ((const float4*)(xb + (size_t)e * NDM + j0))[q];
    }
    __syncthreads();

    int d = tid >> 2, q = tid & 3, jb = q * 16;
    const float* wr = Wt + ((size_t)b * NC + d) * NC;
    float4 acc[4];
    #pragma unroll
    for (int t = 0; t < 4; t++) acc[t] = make_float4(0.f, 0.f, 0.f, 0.f);
    #pragma unroll 4
    for (int e = 0; e < NC; e++) {
        float w = __ldg(wr + e);
        #pragma unroll
        for (int t = 0; t < 4; t++) {
            float4 xv = *(float4*)&xs[e][jb + t * 4];
            acc[t].x = fmaf(w, xv.x, acc[t].x);
            acc[t].y = fmaf(w, xv.y, acc[t].y);
            acc[t].z = fmaf(w, xv.z, acc[t].z);
            acc[t].w = fmaf(w, xv.w, acc[t].w);
        }
    }
    const float invs = 0.9999950000374997f;
    float bsc = bng[d] * invs, bof = bnb[d];
    size_t base = ((size_t)b * NC + d) * NDM + j0 + jb;
    #pragma unroll
    for (int t = 0; t < 4; t++) {
        float4 xv = *(float4*)&xs[d][jb + t * 4];
        float4 o;
        o.x = (acc[t].x + xv.x) * bsc + bof;
        o.y = (acc[t].y + xv.y) * bsc + bof;
        o.z = (acc[t].z + xv.z) * bsc + bof;
        o.w = (acc[t].w + xv.w) * bsc + bof;
        *(float4*)(Out + base + t * 4) = o;
        *(__half2*)(hOut + base + t * 4)     = h2(o.x, o.y);
        *(__half2*)(hOut + base + t * 4 + 2) = h2(o.z, o.w);
    }
}

// ===========================================================================
// auto-attn shift scores + softmax + weighted shift sum -> fp16
// ===========================================================================
__global__ void autoshift_kernel(const float* __restrict__ X, const float* __restrict__ U,
                                 __half* __restrict__ XW) {
    __shared__ float xr[NDM];
    __shared__ float red[8][4];
    int row = blockIdx.x, tid = threadIdx.x;
    const float4 xv = ((const float4*)(X + (size_t)row * NDM))[tid];
    ((float4*)xr)[tid] = xv;
    const float4 uv = ((const float4*)(U + (size_t)row * NDM))[tid];
    __syncthreads();

    float sc[8];
    #pragma unroll
    for (int s = 0; s < 8; s++) {
        float4 x4 = ((float4*)xr)[(tid + 16 * s) & 127];
        sc[s] = uv.x * x4.x + uv.y * x4.y + uv.z * x4.z + uv.w * x4.w;
    }
    int lane = tid & 31, wid = tid >> 5;
    #pragma unroll
    for (int s = 0; s < 8; s++) {
        float v = sc[s];
        #pragma unroll
        for (int o = 16; o; o >>= 1) v += __shfl_xor_sync(0xffffffffu, v, o);
        if (!lane) red[s][wid] = v;
    }
    __syncthreads();
    const float rsq = 0.04419417382415922f;    // DM^-0.5
    float lg[8], mx = -1e30f;
    #pragma unroll
    for (int s = 0; s < 8; s++) {
        lg[s] = (red[s][0] + red[s][1] + red[s][2] + red[s][3]) * rsq;
        mx = fmaxf(mx, lg[s]);
    }
    float w[8], sum = 0.f;
    #pragma unroll
    for (int s = 0; s < 8; s++) { w[s] = __expf(lg[s] - mx); sum += w[s]; }
    float rs = 1.f / sum;
    float4 o = make_float4(0.f, 0.f, 0.f, 0.f);
    #pragma unroll
    for (int s = 0; s < 8; s++) {
        float4 x4 = ((float4*)xr)[(tid + 16 * s) & 127];
        float ws = w[s] * rs;
        o.x = fmaf(ws, x4.x, o.x); o.y = fmaf(ws, x4.y, o.y);
        o.z = fmaf(ws, x4.z, o.z); o.w = fmaf(ws, x4.w, o.w);
    }
    __half2* op = (__half2*)(XW + (size_t)row * NDM) + tid * 2;
    op[0] = h2(o.x, o.y);
    op[1] = h2(o.z, o.w);
}

// ===========================================================================
// LayerNorm; optional fp16 twin + fused rowsum of output
// ===========================================================================
template<bool SUM, bool H16>
__global__ void layernorm_kernel(const float* __restrict__ In, const float* __restrict__ g,
                                 const float* __restrict__ bb, float* __restrict__ Out,
                                 __half* __restrict__ hOut, float* __restrict__ S) {
    int row = blockIdx.x, tid = threadIdx.x;
    const float4 v = ((const float4*)(In + (size_t)row * NDM))[tid];
    float s  = v.x + v.y + v.z + v.w;
    float s2 = v.x * v.x + v.y * v.y + v.z * v.z + v.w * v.w;
    #pragma unroll
    for (int o = 16; o; o >>= 1) {
        s  += __shfl_xor_sync(0xffffffffu, s, o);
        s2 += __shfl_xor_sync(0xffffffffu, s2, o);
    }
    __shared__ float ws[4], ws2[4], wo[4];
    int lane = tid & 31, wid = tid >> 5;
    if (!lane) { ws[wid] = s; ws2[wid] = s2; }
    __syncthreads();
    s  = ws[0] + ws[1] + ws[2] + ws[3];
    s2 = ws2[0] + ws2[1] + ws2[2] + ws2[3];
    float mean = s * (1.f / NDM);
    float var  = s2 * (1.f / NDM) - mean * mean;
    float inv  = rsqrtf(var + 1e-5f);
    float4 gv = ((const float4*)g)[tid], bv = ((const float4*)bb)[tid];
    float4 o;
    o.x = (v.x - mean) * inv * gv.x + bv.x;
    o.y = (v.y - mean) * inv * gv.y + bv.y;
    o.z = (v.z - mean) * inv * gv.z + bv.z;
    o.w = (v.w - mean) * inv * gv.w + bv.w;
    ((float4*)(Out + (size_t)row * NDM))[tid] = o;
    if (H16) {
        __half2* op = (__half2*)(hOut + (size_t)row * NDM) + tid * 2;
        op[0] = h2(o.x, o.y);
        op[1] = h2(o.z, o.w);
    }
    if (SUM) {
        float os = o.x + o.y + o.z + o.w;
        #pragma unroll
        for (int off = 16; off; off >>= 1) os += __shfl_xor_sync(0xffffffffu, os, off);
        if (!lane) wo[wid] = os;
        __syncthreads();
        if (tid == 0) S[row] = wo[0] + wo[1] + wo[2] + wo[3];
    }
}

// ===========================================================================
extern "C" void kernel_launch(void* const* d_in, const int* in_sizes, int n_in,
                              void* d_out, int out_size) {
    (void)in_sizes; (void)n_in; (void)out_size;
    const float* inp     = (const float*)d_in[0];
    const float* ld_w    = (const float*)d_in[1];
    const float* ld_b    = (const float*)d_in[2];
    const float* emb_W   = (const float*)d_in[3];
    const float* emb_b   = (const float*)d_in[4];
    const float* W_pos   = (const float*)d_in[5];
    const float* vc_bn_g = (const float*)d_in[6];
    const float* vc_bn_b = (const float*)d_in[7];
    const float* vc_ln_g = (const float*)d_in[8];
    const float* vc_ln_b = (const float*)d_in[9];
    const float* vc_W1   = (const float*)d_in[10];
    const float* vc_b1   = (const float*)d_in[11];
    const float* vc_W2   = (const float*)d_in[12];
    const float* vc_b2   = (const float*)d_in[13];
    const float* aa_Wq   = (const float*)d_in[14];
    const float* aa_bq   = (const float*)d_in[15];
    const float* aa_Wk   = (const float*)d_in[16];
    // d_in[17] = aa_bk: cancels in the shift-softmax (constant logit offset)
    const float* aa_Wv   = (const float*)d_in[18];
    const float* aa_bv   = (const float*)d_in[19];
    const float* aa_Wo   = (const float*)d_in[20];
    const float* aa_bo   = (const float*)d_in[21];
    const float* aa_bn_g = (const float*)d_in[22];
    const float* aa_bn_b = (const float*)d_in[23];
    const float* aa_ln_g = (const float*)d_in[24];
    const float* aa_ln_b = (const float*)d_in[25];
    const float* aa_W1   = (const float*)d_in[26];
    const float* aa_b1   = (const float*)d_in[27];
    const float* aa_W2   = (const float*)d_in[28];
    const float* aa_b2   = (const float*)d_in[29];

    float *X, *B2, *B3, *S, *WT, *CV, *BVO;
    __half *hR, *hX, *hB1, *hB2, *hB3;
    __half *hEmb, *hVcW1, *hVcW2, *hAaW1, *hAaW2, *hWo, *hT, *hWQK, *hWvo;
    cudaGetSymbolAddress((void**)&X,    g_X);
    cudaGetSymbolAddress((void**)&B2,   g_B2);
    cudaGetSymbolAddress((void**)&B3,   g_B3);
    cudaGetSymbolAddress((void**)&S,    g_S);
    cudaGetSymbolAddress((void**)&WT,   g_W);
    cudaGetSymbolAddress((void**)&CV,   g_CV);
    cudaGetSymbolAddress((void**)&BVO,  g_BVO);
    cudaGetSymbolAddress((void**)&hR,   g_hR);
    cudaGetSymbolAddress((void**)&hX,   g_hX);
    cudaGetSymbolAddress((void**)&hB1,  g_hB1);
    cudaGetSymbolAddress((void**)&hB2,  g_hB2);
    cudaGetSymbolAddress((void**)&hB3,  g_hB3);
    cudaGetSymbolAddress((void**)&hEmb, g_hEmb);
    cudaGetSymbolAddress((void**)&hVcW1,g_hVcW1);
    cudaGetSymbolAddress((void**)&hVcW2,g_hVcW2);
    cudaGetSymbolAddress((void**)&hAaW1,g_hAaW1);
    cudaGetSymbolAddress((void**)&hAaW2,g_hAaW2);
    cudaGetSymbolAddress((void**)&hWo,  g_hWo);
    cudaGetSymbolAddress((void**)&hT,   g_hT);
    cudaGetSymbolAddress((void**)&hWQK, g_hWQK);
    cudaGetSymbolAddress((void**)&hWvo, g_hWvo);
    float* OUT = (float*)d_out;

    dim3 g512(8, 32);    // N=512 GEMM: 256 blocks
    dim3 g1024(16, 32);  // N=1024 GEMM: 512 blocks
    dim3 gpre(8, 8, 3);  // 512x512x512 precompute, z = layer

    // ---- preamble (x-independent precompute + conversions) ----
    f2h_all<<<7168, 256>>>(emb_W, vc_W1, vc_W2, aa_W1, aa_W2, aa_Wo,
                           hEmb, hVcW1, hVcW2, hAaW1, hAaW2, hWo);
    trans_f2h<<<dim3(16, 16, 9), dim3(32, 8)>>>(aa_Wk, aa_Wq, aa_Wv, hT);
    conv_residual_kernel<<<dim3(NB, NT / 64, NC / 32), 256>>>(inp, ld_w, ld_b, hR);
    cv_pre<<<dim3(NDM / 8, NL), 256>>>(aa_bq, hT, CV);   // after trans_f2h (reads WkT)
    bvo_pre<<<dim3(NDM / 8, NL), 256>>>(aa_bv, aa_bo, aa_Wo, BVO);
    // WQK[l] = WkT[l] x WqT[l] ;  Wvo[l] = Wo[l] x WvT[l]
    cg_gemm<EPI_NONE, OUT_F16><<<gpre, 256>>>(hT, hT + 3 * SSQ, nullptr, nullptr,
                                              nullptr, nullptr, nullptr, hWQK,
                                              NDM, NDM, NDM, SSQ, SSQ, SSQ);
    cg_gemm<EPI_NONE, OUT_F16><<<gpre, 256>>>(hWo, hT + 6 * SSQ, nullptr, nullptr,
                                              nullptr, nullptr, nullptr, hWvo,
                                              NDM, NDM, NDM, SSQ, SSQ, SSQ);
    // embedding: X = R @ emb_W.T + emb_b + W_pos
    cg_gemm<EPI_BIAS_WPOS, OUT_F32><<<g512, 256>>>(hR, hEmb, emb_b, W_pos,
                                                   nullptr, nullptr, X, nullptr,
                                                   NM, NDM, NT, 0, 0, 0);
    rowsum_kernel<<<NM / 8, 256>>>(X, S);

    for (int l = 0; l < NL; ++l) {
        const size_t SH = (size_t)NH * NDM;
        // ---- VarCor block ----
        varcor_w_kernel<<<NB, NC>>>(S, WT);
        varcor_mix_kernel<<<dim3(NB, NDM / 64), 512>>>(X, WT, vc_bn_g + l * NC, vc_bn_b + l * NC,
                                                       B2, hB2);
        cg_gemm<EPI_BIAS_GELU, OUT_F16><<<g1024, 256>>>(hB2, hVcW1 + l * SH, vc_b1 + l * NH,
                                                        nullptr, nullptr, nullptr,
                                                        nullptr, hB1, NM, NH, NDM, 0, 0, 0);
        cg_gemm<EPI_BIAS_RES, OUT_F32><<<g512, 256>>>(hB1, hVcW2 + l * SH, vc_b2 + l * NDM,
                                                      B2, nullptr, nullptr,
                                                      B3, nullptr, NM, NDM, NH, 0, 0, 0);
        layernorm_kernel<false, true><<<NM, 128>>>(B3, vc_ln_g + l * NDM, vc_ln_b + l * NDM,
                                                   X, hX, nullptr);

        // ---- Auto-attention block ----
        cg_gemm<EPI_BIAS, OUT_F32><<<g512, 256>>>(hX, hWQK + (size_t)l * SSQ, CV + l * NDM,
                                                  nullptr, nullptr, nullptr,
                                                  B3, nullptr, NM, NDM, NDM, 0, 0, 0);
        autoshift_kernel<<<NM, 128>>>(X, B3, hB2);
        // fused V+O projection: out = xw @ Wvo^T + bvo ; + x residual ; BN
        cg_gemm<EPI_BIAS_RES_BN, OUT_BOTH><<<g512, 256>>>(hB2, hWvo + (size_t)l * SSQ,
                                                          BVO + l * NDM, X,
                                                          aa_bn_g + l * NC, aa_bn_b + l * NC,
                                                          B2, hB3, NM, NDM, NDM, 0, 0, 0);
        cg_gemm<EPI_BIAS_GELU, OUT_F16><<<g1024, 256>>>(hB3, hAaW1 + l * SH, aa_b1 + l * NH,
                                                        nullptr, nullptr, nullptr,
                                                        nullptr, hB1, NM, NH, NDM, 0, 0, 0);
        cg_gemm<EPI_BIAS_RES, OUT_F32><<<g512, 256>>>(hB1, hAaW2 + l * SH, aa_b2 + l * NDM,
                                                      B2, nullptr, nullptr,
                                                      B3, nullptr, NM, NDM, NH, 0, 0, 0);
        if (l == NL - 1) {
            layernorm_kernel<false, false><<<NM, 128>>>(B3, aa_ln_g + l * NDM, aa_ln_b + l * NDM,
                                                        OUT, nullptr, nullptr);
        } else {
            layernorm_kernel<true, true><<<NM, 128>>>(B3, aa_ln_g + l * NDM, aa_ln_b + l * NDM,
                                                      X, hX, S);
        }
    }
}

// round 15
// speedup vs baseline: 1.5961x; 1.0601x over previous
#include <cuda_runtime.h>
#include <cuda_fp16.h>
#include <math.h>
#include <stdint.h>

// Problem constants
#define NB   16
#define NT   512
#define NC   128
#define NDM  512
#define NL   3
#define NKS  25
#define NM   (NB*NC)       // 2048 rows
#define NH   (2*NDM)       // 1024 FFN hidden
#define SSQ  (NDM*NDM)     // 262144

// fp32 scratch
__device__ float g_X  [NM*NDM];
__device__ float g_B2 [NM*NDM];
__device__ float g_B3 [NM*NDM];
__device__ float g_S  [NM];
__device__ float g_W  [NB*NC*NC];
__device__ float g_CV [NL*NDM];
__device__ float g_BVO[NL*NDM];
// fp16 scratch
__device__ __align__(256) __half g_hR  [NM*NT];
__device__ __align__(256) __half g_hX  [NM*NDM];
__device__ __align__(256) __half g_hB1 [NM*NH];
__device__ __align__(256) __half g_hB2 [NM*NDM];
__device__ __align__(256) __half g_hB3 [NM*NDM];
__device__ __align__(256) __half g_hEmb [NDM*NT];
__device__ __align__(256) __half g_hVcW1[NL*NH*NDM];
__device__ __align__(256) __half g_hVcW2[NL*NDM*NH];
__device__ __align__(256) __half g_hAaW1[NL*NH*NDM];
__device__ __align__(256) __half g_hAaW2[NL*NDM*NH];
__device__ __align__(256) __half g_hWo  [NL*SSQ];
__device__ __align__(256) __half g_hT   [9*SSQ];     // WkT(l0..2), WqT, WvT
__device__ __align__(256) __half g_hWQK [NL*SSQ];
__device__ __align__(256) __half g_hWvo [NL*SSQ];

// ===========================================================================
// helpers
// ===========================================================================
__device__ __forceinline__ uint32_t smem_u32(const void* p) {
    uint32_t a;
    asm("{ .reg .u64 t; cvta.to.shared.u64 t, %1; cvt.u32.u64 %0, t; }" : "=r"(a) : "l"(p));
    return a;
}
__device__ __forceinline__ void cpa16(uint32_t dst, const void* src) {
    asm volatile("cp.async.cg.shared.global [%0], [%1], 16;" :: "r"(dst), "l"(src));
}
#define CPA_COMMIT() asm volatile("cp.async.commit_group;" ::: "memory")
#define CPA_WAIT(n)  asm volatile("cp.async.wait_group %0;" :: "n"(n) : "memory")

__device__ __forceinline__ void ldsm4(uint32_t& r0, uint32_t& r1, uint32_t& r2, uint32_t& r3,
                                      uint32_t addr) {
    asm volatile("ldmatrix.sync.aligned.m8n8.x4.shared.b16 {%0,%1,%2,%3}, [%4];"
                 : "=r"(r0), "=r"(r1), "=r"(r2), "=r"(r3) : "r"(addr));
}
__device__ __forceinline__ void mma16(float (&d)[4], const uint32_t (&a)[4], const uint32_t (&b)[2]) {
    asm volatile("mma.sync.aligned.m16n8k16.row.col.f32.f16.f16.f32 "
                 "{%0,%1,%2,%3}, {%4,%5,%6,%7}, {%8,%9}, {%0,%1,%2,%3};"
                 : "+f"(d[0]), "+f"(d[1]), "+f"(d[2]), "+f"(d[3])
                 : "r"(a[0]), "r"(a[1]), "r"(a[2]), "r"(a[3]), "r"(b[0]), "r"(b[1]));
}
__device__ __forceinline__ __half2 h2(float a, float b) {
    return __float22half2_rn(make_float2(a, b));
}

// ===========================================================================
// fp16 cp.async GEMM, z-batched: C[z;m,n] = sum_k A[z;m,k]*W[z;n,k] + epilogue
// BM=BN=64, BK=32, 4-stage ring, single sync/iter, 256 threads (2Mx4N warps).
// ===========================================================================
enum { EPI_NONE = 0, EPI_BIAS, EPI_BIAS_WPOS, EPI_BIAS_GELU, EPI_BIAS_RES, EPI_BIAS_RES_BN };
enum { OUT_F32 = 0, OUT_F16 = 1, OUT_BOTH = 2 };

#define STAGES 4
#define ROWB  80
#define TILEB (64*ROWB)                // 5120 B
#define STGB  (2*TILEB)                // 10240 B

template<int EPI, int OUTM>
__global__ __launch_bounds__(256, 3)
void cg_gemm(const __half* __restrict__ A, const __half* __restrict__ W,
             const float* __restrict__ bias, const float* __restrict__ extra,
             const float* __restrict__ bng, const float* __restrict__ bnb,
             float* __restrict__ C, __half* __restrict__ Ch,
             int M, int N, int K, int azs, int wzs, int czs) {
    __shared__ __align__(128) char sh[STAGES * STGB];   // 40 KB
    const uint32_t sbase = smem_u32(sh);

    A += (size_t)blockIdx.z * azs;
    W += (size_t)blockIdx.z * wzs;
    if (OUTM == OUT_F32 || OUTM == OUT_BOTH) C  += (size_t)blockIdx.z * czs;
    if (OUTM == OUT_F16 || OUTM == OUT_BOTH) Ch += (size_t)blockIdx.z * czs;

    int tid = threadIdx.x, wid = tid >> 5, lane = tid & 31;
    int g = lane >> 2, tg = lane & 3;
    int wm = wid & 1, wn = wid >> 1;                      // 2 x 4 warps
    int m0 = blockIdx.y * 64, n0 = blockIdx.x * 64;

    float c[2][2][4];
    #pragma unroll
    for (int i = 0; i < 2; i++)
        #pragma unroll
        for (int j = 0; j < 2; j++)
            #pragma unroll
            for (int q = 0; q < 4; q++) c[i][j][q] = 0.f;

    const int r = tid >> 2, cc = tid & 3;
    const uint32_t dOff = (uint32_t)(r * ROWB + cc * 16);
    const __half* ag = A + (size_t)(m0 + r) * K + cc * 8;
    const __half* bg = W + (size_t)(n0 + r) * K + cc * 8;

    const int lt = lane >> 3, lr8 = lane & 7;
    const uint32_t aRowOff = (uint32_t)((wm * 32 + (lt & 1) * 8 + lr8) * ROWB + (lt >> 1) * 16);
    const uint32_t bRowOff = (uint32_t)((wn * 16 + (lt >> 1) * 8 + lr8) * ROWB + (lt & 1) * 16);

    const int KC = K >> 5;

    #pragma unroll
    for (int s = 0; s < STAGES - 1; s++) {
        cpa16(sbase + s * STGB + dOff, ag + s * 32);
        cpa16(sbase + s * STGB + TILEB + dOff, bg + s * 32);
        CPA_COMMIT();
    }

    for (int kc = 0; kc < KC; kc++) {
        CPA_WAIT(STAGES - 2);          // stage kc ready
        __syncthreads();               // all readers of stage (kc-1) done -> safe to refill
        int pf = kc + STAGES - 1;
        if (pf < KC) {
            uint32_t sb = sbase + (pf % STAGES) * STGB;
            cpa16(sb + dOff, ag + (size_t)pf * 32);
            cpa16(sb + TILEB + dOff, bg + (size_t)pf * 32);
        }
        CPA_COMMIT();

        const uint32_t sA = sbase + (kc % STAGES) * STGB;
        const uint32_t sB = sA + TILEB;
        #pragma unroll
        for (int ks = 0; ks < 2; ks++) {
            uint32_t af[2][4], bf[2][2];
            #pragma unroll
            for (int mi = 0; mi < 2; mi++)
                ldsm4(af[mi][0], af[mi][1], af[mi][2], af[mi][3],
                      sA + aRowOff + mi * (16 * ROWB) + ks * 32);
            {
                uint32_t r0, r1, r2, r3;
                ldsm4(r0, r1, r2, r3, sB + bRowOff + ks * 32);
                bf[0][0] = r0; bf[0][1] = r1; bf[1][0] = r2; bf[1][1] = r3;
            }
            #pragma unroll
            for (int mi = 0; mi < 2; mi++)
                #pragma unroll
                for (int nj = 0; nj < 2; nj++) mma16(c[mi][nj], af[mi], bf[nj]);
        }
    }

    // ---- epilogue ----
    const float invs = 0.9999950000374997f;   // 1/sqrt(1+1e-5) eval-mode BN
    int mBase = m0 + wm * 32, nBase = n0 + wn * 16;
    #pragma unroll
    for (int mi = 0; mi < 2; mi++) {
        #pragma unroll
        for (int half = 0; half < 2; half++) {
            int m = mBase + mi * 16 + g + half * 8;
            float bsc = 1.f, bof = 0.f;
            if (EPI == EPI_BIAS_RES_BN) { bsc = bng[m & (NC - 1)] * invs; bof = bnb[m & (NC - 1)]; }
            #pragma unroll
            for (int nj = 0; nj < 2; nj++) {
                int n = nBase + nj * 8 + tg * 2;
                float x0 = c[mi][nj][half * 2 + 0];
                float x1 = c[mi][nj][half * 2 + 1];
                if (EPI != EPI_NONE) { x0 += bias[n]; x1 += bias[n + 1]; }
                if (EPI == EPI_BIAS_WPOS) {
                    const float* e = extra + (size_t)(m & (NC - 1)) * N + n;
                    x0 += e[0]; x1 += e[1];
                }
                if (EPI == EPI_BIAS_RES || EPI == EPI_BIAS_RES_BN) {
                    const float* e = extra + (size_t)m * N + n;
                    x0 += e[0]; x1 += e[1];
                }
                if (EPI == EPI_BIAS_GELU) {
                    x0 = 0.5f * x0 * (1.f + erff(x0 * 0.7071067811865475f));
                    x1 = 0.5f * x1 * (1.f + erff(x1 * 0.7071067811865475f));
                }
                if (EPI == EPI_BIAS_RES_BN) { x0 = x0 * bsc + bof; x1 = x1 * bsc + bof; }
                if (OUTM == OUT_F32 || OUTM == OUT_BOTH)
                    *(float2*)(C + (size_t)m * N + n) = make_float2(x0, x1);
                if (OUTM == OUT_F16 || OUTM == OUT_BOTH)
                    *(__half2*)(Ch + (size_t)m * N + n) = h2(x0, x1);
            }
        }
    }
}

// ===========================================================================
// all weight fp32->fp16 conversions, one launch (segment table, 4 elems/thread)
// ===========================================================================
__global__ void f2h_all(const float* __restrict__ emb, const float* __restrict__ vw1,
                        const float* __restrict__ vw2, const float* __restrict__ aw1,
                        const float* __restrict__ aw2, const float* __restrict__ wo,
                        __half* __restrict__ hEmb, __half* __restrict__ hVw1,
                        __half* __restrict__ hVw2, __half* __restrict__ hAw1,
                        __half* __restrict__ hAw2, __half* __restrict__ hWo) {
    long i = ((long)blockIdx.x * 256 + threadIdx.x) * 4;
    const float* s; __half* d; long off;
    if      (i < 262144L)  { s = emb; d = hEmb; off = i; }
    else if (i < 1835008L) { s = vw1; d = hVw1; off = i - 262144L; }
    else if (i < 3407872L) { s = vw2; d = hVw2; off = i - 1835008L; }
    else if (i < 4980736L) { s = aw1; d = hAw1; off = i - 3407872L; }
    else if (i < 6553600L) { s = aw2; d = hAw2; off = i - 4980736L; }
    else                   { s = wo;  d = hWo;  off = i - 6553600L; }
    float4 v = *(const float4*)(s + off);
    __half2* p = (__half2*)(d + off);
    p[0] = h2(v.x, v.y);
    p[1] = h2(v.z, v.w);
}

// ===========================================================================
// transpose + fp16: hT[z] = transpose(src_z), z: 0..2 Wk(l), 3..5 Wq(l), 6..8 Wv(l)
// ===========================================================================
__global__ void trans_f2h(const float* __restrict__ Wk, const float* __restrict__ Wq,
                          const float* __restrict__ Wv, __half* __restrict__ hT) {
    __shared__ float t[32][33];
    int z = blockIdx.z;
    const float* src = (z < 3) ? Wk + (size_t)z * SSQ
                     : (z < 6) ? Wq + (size_t)(z - 3) * SSQ
                               : Wv + (size_t)(z - 6) * SSQ;
    __half* dst = hT + (size_t)z * SSQ;
    int c0 = blockIdx.x * 32, r0 = blockIdx.y * 32;
    int tx = threadIdx.x, ty = threadIdx.y;
    #pragma unroll
    for (int i = 0; i < 4; i++)
        t[ty + i * 8][tx] = src[(size_t)(r0 + ty + i * 8) * NDM + c0 + tx];
    __syncthreads();
    #pragma unroll
    for (int i = 0; i < 4; i++)
        dst[(size_t)(c0 + ty + i * 8) * NDM + r0 + tx] = __float2half(t[tx][ty + i * 8]);
}

// ===========================================================================
// cv[l,n] = sum_j bq[l,j]*WkT[l; n,j]  (warp per n over contiguous fp16 row)
// ===========================================================================
__global__ void cv_pre(const float* __restrict__ bq, const __half* __restrict__ hT,
                       float* __restrict__ cv) {
    int l = blockIdx.y;
    int w = threadIdx.x >> 5, lane = threadIdx.x & 31;
    int n = blockIdx.x * 8 + w;
    const __half* wk = hT + (size_t)l * SSQ + (size_t)n * NDM;
    const float* b = bq + l * NDM;
    float s = 0.f;
    #pragma unroll 4
    for (int j = lane; j < NDM; j += 32) s = fmaf(__half2float(wk[j]), b[j], s);
    #pragma unroll
    for (int o = 16; o; o >>= 1) s += __shfl_xor_sync(0xffffffffu, s, o);
    if (!lane) cv[l * NDM + n] = s;
}
// ===========================================================================
// bvo[l,n] = Wo[n,:].bv + bo[n]       (warp per n; lanes stride the row)
// ===========================================================================
__global__ void bvo_pre(const float* __restrict__ bv, const float* __restrict__ bo,
                        const float* __restrict__ Wo, float* __restrict__ bvo) {
    int l = blockIdx.y;
    int w = threadIdx.x >> 5, lane = threadIdx.x & 31;
    int n = blockIdx.x * 8 + w;
    const float* wo = Wo + (size_t)l * SSQ + (size_t)n * NDM;
    const float* b  = bv + l * NDM;
    float s = 0.f;
    for (int j = lane; j < NDM; j += 32) s = fmaf(wo[j], b[j], s);
    #pragma unroll
    for (int o = 16; o; o >>= 1) s += __shfl_xor_sync(0xffffffffu, s, o);
    if (!lane) bvo[l * NDM + n] = s + bo[l * NDM + n];
}

// ===========================================================================
// trend conv + residual -> fp16 (B,C,T)
// ===========================================================================
__global__ void conv_residual_kernel(const float* __restrict__ inp,
                                     const float* __restrict__ w,
                                     const float* __restrict__ ldb,
                                     __half* __restrict__ R) {
    __shared__ float s[88][33];
    __shared__ float wk[NKS];
    int b = blockIdx.x, t0 = blockIdx.y * 64, c0 = blockIdx.z * 32;
    int tid = threadIdx.x;
    if (tid < NKS) wk[tid] = w[tid];
    for (int idx = tid; idx < 88 * 32; idx += 256) {
        int r = idx >> 5, c = idx & 31;
        int tg = t0 + r - 12;
        tg = min(max(tg, 0), NT - 1);
        s[r][c] = inp[((size_t)b * NT + tg) * NC + c0 + c];
    }
    __syncthreads();
    float lb = ldb[0];
    int lane = tid & 31, wy = tid >> 5;
    for (int half = 0; half < 2; ++half) {
        int ti = half * 32 + lane;
        for (int cg = 0; cg < 4; ++cg) {
            int ci = cg * 8 + wy;
            float acc = 0.f;
            #pragma unroll
            for (int k = 0; k < NKS; ++k) acc = fmaf(wk[k], s[ti + k][ci], acc);
            float v = s[ti + 12][ci] - (acc + lb);
            R[((size_t)b * NC + c0 + ci) * NT + t0 + ti] = __float2half(v);
        }
    }
}

// ===========================================================================
// row sums of X (varcor logits)
// ===========================================================================
__global__ void rowsum_kernel(const float* __restrict__ X, float* __restrict__ S) {
    int row = blockIdx.x * 8 + (threadIdx.x >> 5);
    int lane = threadIdx.x & 31;
    const float* xr = X + (size_t)row * NDM;
    float s = 0.f;
    for (int i = lane; i < NDM; i += 32) s += xr[i];
    #pragma unroll
    for (int o = 16; o; o >>= 1) s += __shfl_xor_sync(0xffffffffu, s, o);
    if (!lane) S[row] = s;
}

// ===========================================================================
// varcor softmax weights — warp per d, exps kept in regs (computed once).
// grid (NB, NC/8), 256 threads = 8 warps.
// ===========================================================================
__global__ void varcor_w_kernel(const float* __restrict__ S, float* __restrict__ Wt) {
    __shared__ float ss[NC];
    int b = blockIdx.x;
    int tid = threadIdx.x;
    if (tid < NC) ss[tid] = S[b * NC + tid];
    __syncthreads();
    int w = tid >> 5, lane = tid & 31;
    int d = blockIdx.y * 8 + w;
    const float VS = 8.6316746e-05f;            // 1/(512*sqrt(512))
    float sd = ss[d];
    float v4[4], mx = -1e30f;
    #pragma unroll
    for (int i = 0; i < 4; i++) {
        v4[i] = sd * ss[lane + i * 32];
        mx = fmaxf(mx, v4[i]);
    }
    #pragma unroll
    for (int o = 16; o; o >>= 1) mx = fmaxf(mx, __shfl_xor_sync(0xffffffffu, mx, o));
    float e4[4], ps = 0.f;
    #pragma unroll
    for (int i = 0; i < 4; i++) {
        e4[i] = __expf((v4[i] - mx) * VS);
        ps += e4[i];
    }
    #pragma unroll
    for (int o = 16; o; o >>= 1) ps += __shfl_xor_sync(0xffffffffu, ps, o);
    float rs = 1.f / ps;
    float* wr = Wt + ((size_t)b * NC + d) * NC;
    #pragma unroll
    for (int i = 0; i < 4; i++) wr[lane + i * 32] = e4[i] * rs;
}

// ===========================================================================
// varcor mix + residual + BN -> fp32 + fp16
// ===========================================================================
__global__ __launch_bounds__(512)
void varcor_mix_kernel(const float* __restrict__ X, const float* __restrict__ Wt,
                       const float* __restrict__ bng, const float* __restrict__ bnb,
                       float* __restrict__ Out, __half* __restrict__ hOut) {
    __shared__ float xs[NC][64];
    int b = blockIdx.x, j0 = blockIdx.y * 64;
    int tid = threadIdx.x;
    const float* xb = X + (size_t)b * NC * NDM;
    #pragma unroll
    for (int i = 0; i < 4; i++) {
        int f = tid + i * 512;
        int e = f >> 4, q = f & 15;
        *(float4*)&xs[e][q * 4] = ((const float4*)(xb + (size_t)e * NDM + j0))[q];
    }
    __syncthreads();

    int d = tid >> 2, q = tid & 3, jb = q * 16;
    const float* wr = Wt + ((size_t)b * NC + d) * NC;
    float4 acc[4];
    #pragma unroll
    for (int t = 0; t < 4; t++) acc[t] = make_float4(0.f, 0.f, 0.f, 0.f);
    #pragma unroll 4
    for (int e = 0; e < NC; e++) {
        float w = __ldg(wr + e);
        #pragma unroll
        for (int t = 0; t < 4; t++) {
            float4 xv = *(float4*)&xs[e][jb + t * 4];
            acc[t].x = fmaf(w, xv.x, acc[t].x);
            acc[t].y = fmaf(w, xv.y, acc[t].y);
            acc[t].z = fmaf(w, xv.z, acc[t].z);
            acc[t].w = fmaf(w, xv.w, acc[t].w);
        }
    }
    const float invs = 0.9999950000374997f;
    float bsc = bng[d] * invs, bof = bnb[d];
    size_t base = ((size_t)b * NC + d) * NDM + j0 + jb;
    #pragma unroll
    for (int t = 0; t < 4; t++) {
        float4 xv = *(float4*)&xs[d][jb + t * 4];
        float4 o;
        o.x = (acc[t].x + xv.x) * bsc + bof;
        o.y = (acc[t].y + xv.y) * bsc + bof;
        o.z = (acc[t].z + xv.z) * bsc + bof;
        o.w = (acc[t].w + xv.w) * bsc + bof;
        *(float4*)(Out + base + t * 4) = o;
        *(__half2*)(hOut + base + t * 4)     = h2(o.x, o.y);
        *(__half2*)(hOut + base + t * 4 + 2) = h2(o.z, o.w);
    }
}

// ===========================================================================
// auto-attn shift scores + softmax + weighted shift sum -> fp16 (fp32 inputs)
// ===========================================================================
__global__ void autoshift_kernel(const float* __restrict__ X, const float* __restrict__ U,
                                 __half* __restrict__ XW) {
    __shared__ float xr[NDM];
    __shared__ float red[8][4];
    int row = blockIdx.x, tid = threadIdx.x;
    const float4 xv = ((const float4*)(X + (size_t)row * NDM))[tid];
    ((float4*)xr)[tid] = xv;
    const float4 uv = ((const float4*)(U + (size_t)row * NDM))[tid];
    __syncthreads();

    float sc[8];
    #pragma unroll
    for (int s = 0; s < 8; s++) {
        float4 x4 = ((float4*)xr)[(tid + 16 * s) & 127];
        sc[s] = uv.x * x4.x + uv.y * x4.y + uv.z * x4.z + uv.w * x4.w;
    }
    int lane = tid & 31, wid = tid >> 5;
    #pragma unroll
    for (int s = 0; s < 8; s++) {
        float v = sc[s];
        #pragma unroll
        for (int o = 16; o; o >>= 1) v += __shfl_xor_sync(0xffffffffu, v, o);
        if (!lane) red[s][wid] = v;
    }
    __syncthreads();
    const float rsq = 0.04419417382415922f;    // DM^-0.5
    float lg[8], mx = -1e30f;
    #pragma unroll
    for (int s = 0; s < 8; s++) {
        lg[s] = (red[s][0] + red[s][1] + red[s][2] + red[s][3]) * rsq;
        mx = fmaxf(mx, lg[s]);
    }
    float w[8], sum = 0.f;
    #pragma unroll
    for (int s = 0; s < 8; s++) { w[s] = __expf(lg[s] - mx); sum += w[s]; }
    float rs = 1.f / sum;
    float4 o = make_float4(0.f, 0.f, 0.f, 0.f);
    #pragma unroll
    for (int s = 0; s < 8; s++) {
        float4 x4 = ((float4*)xr)[(tid + 16 * s) & 127];
        float ws = w[s] * rs;
        o.x = fmaf(ws, x4.x, o.x); o.y = fmaf(ws, x4.y, o.y);
        o.z = fmaf(ws, x4.z, o.z); o.w = fmaf(ws, x4.w, o.w);
    }
    __half2* op = (__half2*)(XW + (size_t)row * NDM) + tid * 2;
    op[0] = h2(o.x, o.y);
    op[1] = h2(o.z, o.w);
}

// ===========================================================================
// LayerNorm; optional fp16 twin + fused rowsum of output
// ===========================================================================
template<bool SUM, bool H16>
__global__ void layernorm_kernel(const float* __restrict__ In, const float* __restrict__ g,
                                 const float* __restrict__ bb, float* __restrict__ Out,
                                 __half* __restrict__ hOut, float* __restrict__ S) {
    int row = blockIdx.x, tid = threadIdx.x;
    const float4 v = ((const float4*)(In + (size_t)row * NDM))[tid];
    float s  = v.x + v.y + v.z + v.w;
    float s2 = v.x * v.x + v.y * v.y + v.z * v.z + v.w * v.w;
    #pragma unroll
    for (int o = 16; o; o >>= 1) {
        s  += __shfl_xor_sync(0xffffffffu, s, o);
        s2 += __shfl_xor_sync(0xffffffffu, s2, o);
    }
    __shared__ float ws[4], ws2[4], wo[4];
    int lane = tid & 31, wid = tid >> 5;
    if (!lane) { ws[wid] = s; ws2[wid] = s2; }
    __syncthreads();
    s  = ws[0] + ws[1] + ws[2] + ws[3];
    s2 = ws2[0] + ws2[1] + ws2[2] + ws2[3];
    float mean = s * (1.f / NDM);
    float var  = s2 * (1.f / NDM) - mean * mean;
    float inv  = rsqrtf(var + 1e-5f);
    float4 gv = ((const float4*)g)[tid], bv = ((const float4*)bb)[tid];
    float4 o;
    o.x = (v.x - mean) * inv * gv.x + bv.x;
    o.y = (v.y - mean) * inv * gv.y + bv.y;
    o.z = (v.z - mean) * inv * gv.z + bv.z;
    o.w = (v.w - mean) * inv * gv.w + bv.w;
    ((float4*)(Out + (size_t)row * NDM))[tid] = o;
    if (H16) {
        __half2* op = (__half2*)(hOut + (size_t)row * NDM) + tid * 2;
        op[0] = h2(o.x, o.y);
        op[1] = h2(o.z, o.w);
    }
    if (SUM) {
        float os = o.x + o.y + o.z + o.w;
        #pragma unroll
        for (int off = 16; off; off >>= 1) os += __shfl_xor_sync(0xffffffffu, os, off);
        if (!lane) wo[wid] = os;
        __syncthreads();
        if (tid == 0) S[row] = wo[0] + wo[1] + wo[2] + wo[3];
    }
}

// ===========================================================================
extern "C" void kernel_launch(void* const* d_in, const int* in_sizes, int n_in,
                              void* d_out, int out_size) {
    (void)in_sizes; (void)n_in; (void)out_size;
    const float* inp     = (const float*)d_in[0];
    const float* ld_w    = (const float*)d_in[1];
    const float* ld_b    = (const float*)d_in[2];
    const float* emb_W   = (const float*)d_in[3];
    const float* emb_b   = (const float*)d_in[4];
    const float* W_pos   = (const float*)d_in[5];
    const float* vc_bn_g = (const float*)d_in[6];
    const float* vc_bn_b = (const float*)d_in[7];
    const float* vc_ln_g = (const float*)d_in[8];
    const float* vc_ln_b = (const float*)d_in[9];
    const float* vc_W1   = (const float*)d_in[10];
    const float* vc_b1   = (const float*)d_in[11];
    const float* vc_W2   = (const float*)d_in[12];
    const float* vc_b2   = (const float*)d_in[13];
    const float* aa_Wq   = (const float*)d_in[14];
    const float* aa_bq   = (const float*)d_in[15];
    const float* aa_Wk   = (const float*)d_in[16];
    // d_in[17] = aa_bk: cancels in the shift-softmax (constant logit offset)
    const float* aa_Wv   = (const float*)d_in[18];
    const float* aa_bv   = (const float*)d_in[19];
    const float* aa_Wo   = (const float*)d_in[20];
    const float* aa_bo   = (const float*)d_in[21];
    const float* aa_bn_g = (const float*)d_in[22];
    const float* aa_bn_b = (const float*)d_in[23];
    const float* aa_ln_g = (const float*)d_in[24];
    const float* aa_ln_b = (const float*)d_in[25];
    const float* aa_W1   = (const float*)d_in[26];
    const float* aa_b1   = (const float*)d_in[27];
    const float* aa_W2   = (const float*)d_in[28];
    const float* aa_b2   = (const float*)d_in[29];

    float *X, *B2, *B3, *S, *WT, *CV, *BVO;
    __half *hR, *hX, *hB1, *hB2, *hB3;
    __half *hEmb, *hVcW1, *hVcW2, *hAaW1, *hAaW2, *hWo, *hT, *hWQK, *hWvo;
    cudaGetSymbolAddress((void**)&X,    g_X);
    cudaGetSymbolAddress((void**)&B2,   g_B2);
    cudaGetSymbolAddress((void**)&B3,   g_B3);
    cudaGetSymbolAddress((void**)&S,    g_S);
    cudaGetSymbolAddress((void**)&WT,   g_W);
    cudaGetSymbolAddress((void**)&CV,   g_CV);
    cudaGetSymbolAddress((void**)&BVO,  g_BVO);
    cudaGetSymbolAddress((void**)&hR,   g_hR);
    cudaGetSymbolAddress((void**)&hX,   g_hX);
    cudaGetSymbolAddress((void**)&hB1,  g_hB1);
    cudaGetSymbolAddress((void**)&hB2,  g_hB2);
    cudaGetSymbolAddress((void**)&hB3,  g_hB3);
    cudaGetSymbolAddress((void**)&hEmb, g_hEmb);
    cudaGetSymbolAddress((void**)&hVcW1,g_hVcW1);
    cudaGetSymbolAddress((void**)&hVcW2,g_hVcW2);
    cudaGetSymbolAddress((void**)&hAaW1,g_hAaW1);
    cudaGetSymbolAddress((void**)&hAaW2,g_hAaW2);
    cudaGetSymbolAddress((void**)&hWo,  g_hWo);
    cudaGetSymbolAddress((void**)&hT,   g_hT);
    cudaGetSymbolAddress((void**)&hWQK, g_hWQK);
    cudaGetSymbolAddress((void**)&hWvo, g_hWvo);
    float* OUT = (float*)d_out;

    dim3 g512(8, 32);    // N=512 GEMM: 256 blocks
    dim3 g1024(16, 32);  // N=1024 GEMM: 512 blocks
    dim3 gpre(8, 8, 3);  // 512x512x512 precompute, z = layer

    // ---- preamble (x-independent precompute + conversions) ----
    f2h_all<<<7168, 256>>>(emb_W, vc_W1, vc_W2, aa_W1, aa_W2, aa_Wo,
                           hEmb, hVcW1, hVcW2, hAaW1, hAaW2, hWo);
    trans_f2h<<<dim3(16, 16, 9), dim3(32, 8)>>>(aa_Wk, aa_Wq, aa_Wv, hT);
    conv_residual_kernel<<<dim3(NB, NT / 64, NC / 32), 256>>>(inp, ld_w, ld_b, hR);
    cv_pre<<<dim3(NDM / 8, NL), 256>>>(aa_bq, hT, CV);   // after trans_f2h (reads WkT)
    bvo_pre<<<dim3(NDM / 8, NL), 256>>>(aa_bv, aa_bo, aa_Wo, BVO);
    // WQK[l] = WkT[l] x WqT[l] ;  Wvo[l] = Wo[l] x WvT[l]
    cg_gemm<EPI_NONE, OUT_F16><<<gpre, 256>>>(hT, hT + 3 * SSQ, nullptr, nullptr,
                                              nullptr, nullptr, nullptr, hWQK,
                                              NDM, NDM, NDM, SSQ, SSQ, SSQ);
    cg_gemm<EPI_NONE, OUT_F16><<<gpre, 256>>>(hWo, hT + 6 * SSQ, nullptr, nullptr,
                                              nullptr, nullptr, nullptr, hWvo,
                                              NDM, NDM, NDM, SSQ, SSQ, SSQ);
    // embedding: X = R @ emb_W.T + emb_b + W_pos
    cg_gemm<EPI_BIAS_WPOS, OUT_F32><<<g512, 256>>>(hR, hEmb, emb_b, W_pos,
                                                   nullptr, nullptr, X, nullptr,
                                                   NM, NDM, NT, 0, 0, 0);
    rowsum_kernel<<<NM / 8, 256>>>(X, S);

    for (int l = 0; l < NL; ++l) {
        const size_t SH = (size_t)NH * NDM;
        // ---- VarCor block ----
        varcor_w_kernel<<<dim3(NB, NC / 8), 256>>>(S, WT);
        varcor_mix_kernel<<<dim3(NB, NDM / 64), 512>>>(X, WT, vc_bn_g + l * NC, vc_bn_b + l * NC,
                                                       B2, hB2);
        cg_gemm<EPI_BIAS_GELU, OUT_F16><<<g1024, 256>>>(hB2, hVcW1 + l * SH, vc_b1 + l * NH,
                                                        nullptr, nullptr, nullptr,
                                                        nullptr, hB1, NM, NH, NDM, 0, 0, 0);
        cg_gemm<EPI_BIAS_RES, OUT_F32><<<g512, 256>>>(hB1, hVcW2 + l * SH, vc_b2 + l * NDM,
                                                      B2, nullptr, nullptr,
                                                      B3, nullptr, NM, NDM, NH, 0, 0, 0);
        layernorm_kernel<false, true><<<NM, 128>>>(B3, vc_ln_g + l * NDM, vc_ln_b + l * NDM,
                                                   X, hX, nullptr);

        // ---- Auto-attention block ----
        cg_gemm<EPI_BIAS, OUT_F32><<<g512, 256>>>(hX, hWQK + (size_t)l * SSQ, CV + l * NDM,
                                                  nullptr, nullptr, nullptr,
                                                  B3, nullptr, NM, NDM, NDM, 0, 0, 0);
        autoshift_kernel<<<NM, 128>>>(X, B3, hB2);
        // fused V+O projection: out = xw @ Wvo^T + bvo ; + x residual ; BN
        cg_gemm<EPI_BIAS_RES_BN, OUT_BOTH><<<g512, 256>>>(hB2, hWvo + (size_t)l * SSQ,
                                                          BVO + l * NDM, X,
                                                          aa_bn_g + l * NC, aa_bn_b + l * NC,
                                                          B2, hB3, NM, NDM, NDM, 0, 0, 0);
        cg_gemm<EPI_BIAS_GELU, OUT_F16><<<g1024, 256>>>(hB3, hAaW1 + l * SH, aa_b1 + l * NH,
                                                        nullptr, nullptr, nullptr,
                                                        nullptr, hB1, NM, NH, NDM, 0, 0, 0);
        cg_gemm<EPI_BIAS_RES, OUT_F32><<<g512, 256>>>(hB1, hAaW2 + l * SH, aa_b2 + l * NDM,
                                                      B2, nullptr, nullptr,
                                                      B3, nullptr, NM, NDM, NH, 0, 0, 0);
        if (l == NL - 1) {
            layernorm_kernel<false, false><<<NM, 128>>>(B3, aa_ln_g + l * NDM, aa_ln_b + l * NDM,
                                                        OUT, nullptr, nullptr);
        } else {
            layernorm_kernel<true, true><<<NM, 128>>>(B3, aa_ln_g + l * NDM, aa_ln_b + l * NDM,
                                                      X, hX, S);
        }
    }
}

// round 16
// speedup vs baseline: 1.5969x; 1.0005x over previous
#include <cuda_runtime.h>
#include <cuda_fp16.h>
#include <math.h>
#include <stdint.h>

// Problem constants
#define NB   16
#define NT   512
#define NC   128
#define NDM  512
#define NL   3
#define NKS  25
#define NM   (NB*NC)       // 2048 rows
#define NH   (2*NDM)       // 1024 FFN hidden
#define SSQ  (NDM*NDM)     // 262144

// fp32 scratch
__device__ float g_X  [NM*NDM];
__device__ float g_B2 [NM*NDM];
__device__ float g_B3 [NM*NDM];
__device__ float g_S  [NM];
__device__ float g_W  [NB*NC*NC];
__device__ float g_CV [NL*NDM];
__device__ float g_BVO[NL*NDM];
// fp16 scratch
__device__ __align__(256) __half g_hR  [NM*NT];
__device__ __align__(256) __half g_hX  [NM*NDM];
__device__ __align__(256) __half g_hB1 [NM*NH];
__device__ __align__(256) __half g_hB2 [NM*NDM];
__device__ __align__(256) __half g_hB3 [NM*NDM];
__device__ __align__(256) __half g_hEmb [NDM*NT];
__device__ __align__(256) __half g_hVcW1[NL*NH*NDM];
__device__ __align__(256) __half g_hVcW2[NL*NDM*NH];
__device__ __align__(256) __half g_hAaW1[NL*NH*NDM];
__device__ __align__(256) __half g_hAaW2[NL*NDM*NH];
__device__ __align__(256) __half g_hWo  [NL*SSQ];
__device__ __align__(256) __half g_hT   [9*SSQ];     // WkT(l0..2), WqT, WvT
__device__ __align__(256) __half g_hWQK [NL*SSQ];
__device__ __align__(256) __half g_hWvo [NL*SSQ];

// ===========================================================================
// helpers
// ===========================================================================
__device__ __forceinline__ uint32_t smem_u32(const void* p) {
    uint32_t a;
    asm("{ .reg .u64 t; cvta.to.shared.u64 t, %1; cvt.u32.u64 %0, t; }" : "=r"(a) : "l"(p));
    return a;
}
__device__ __forceinline__ void cpa16(uint32_t dst, const void* src) {
    asm volatile("cp.async.cg.shared.global [%0], [%1], 16;" :: "r"(dst), "l"(src));
}
#define CPA_COMMIT() asm volatile("cp.async.commit_group;" ::: "memory")
#define CPA_WAIT(n)  asm volatile("cp.async.wait_group %0;" :: "n"(n) : "memory")

__device__ __forceinline__ void ldsm4(uint32_t& r0, uint32_t& r1, uint32_t& r2, uint32_t& r3,
                                      uint32_t addr) {
    asm volatile("ldmatrix.sync.aligned.m8n8.x4.shared.b16 {%0,%1,%2,%3}, [%4];"
                 : "=r"(r0), "=r"(r1), "=r"(r2), "=r"(r3) : "r"(addr));
}
__device__ __forceinline__ void mma16(float (&d)[4], const uint32_t (&a)[4], const uint32_t (&b)[2]) {
    asm volatile("mma.sync.aligned.m16n8k16.row.col.f32.f16.f16.f32 "
                 "{%0,%1,%2,%3}, {%4,%5,%6,%7}, {%8,%9}, {%0,%1,%2,%3};"
                 : "+f"(d[0]), "+f"(d[1]), "+f"(d[2]), "+f"(d[3])
                 : "r"(a[0]), "r"(a[1]), "r"(a[2]), "r"(a[3]), "r"(b[0]), "r"(b[1]));
}
__device__ __forceinline__ __half2 h2(float a, float b) {
    return __float22half2_rn(make_float2(a, b));
}

// ===========================================================================
// fp16 cp.async GEMM, z-batched: C[z;m,n] = sum_k A[z;m,k]*W[z;n,k] + epilogue
// BM=BN=64, BK=32, 4-stage ring, single sync/iter, 256 threads (2Mx4N warps).
// ===========================================================================
enum { EPI_NONE = 0, EPI_BIAS, EPI_BIAS_WPOS, EPI_BIAS_GELU, EPI_BIAS_RES, EPI_BIAS_RES_BN };
enum { OUT_F32 = 0, OUT_F16 = 1, OUT_BOTH = 2 };

#define STAGES 4
#define ROWB  80
#define TILEB (64*ROWB)                // 5120 B
#define STGB  (2*TILEB)                // 10240 B

template<int EPI, int OUTM>
__global__ __launch_bounds__(256, 3)
void cg_gemm(const __half* __restrict__ A, const __half* __restrict__ W,
             const float* __restrict__ bias, const float* __restrict__ extra,
             const float* __restrict__ bng, const float* __restrict__ bnb,
             float* __restrict__ C, __half* __restrict__ Ch,
             int M, int N, int K, int azs, int wzs, int czs) {
    __shared__ __align__(128) char sh[STAGES * STGB];   // 40 KB
    const uint32_t sbase = smem_u32(sh);

    A += (size_t)blockIdx.z * azs;
    W += (size_t)blockIdx.z * wzs;
    if (OUTM == OUT_F32 || OUTM == OUT_BOTH) C  += (size_t)blockIdx.z * czs;
    if (OUTM == OUT_F16 || OUTM == OUT_BOTH) Ch += (size_t)blockIdx.z * czs;

    int tid = threadIdx.x, wid = tid >> 5, lane = tid & 31;
    int g = lane >> 2, tg = lane & 3;
    int wm = wid & 1, wn = wid >> 1;                      // 2 x 4 warps
    int m0 = blockIdx.y * 64, n0 = blockIdx.x * 64;

    float c[2][2][4];
    #pragma unroll
    for (int i = 0; i < 2; i++)
        #pragma unroll
        for (int j = 0; j < 2; j++)
            #pragma unroll
            for (int q = 0; q < 4; q++) c[i][j][q] = 0.f;

    const int r = tid >> 2, cc = tid & 3;
    const uint32_t dOff = (uint32_t)(r * ROWB + cc * 16);
    const __half* ag = A + (size_t)(m0 + r) * K + cc * 8;
    const __half* bg = W + (size_t)(n0 + r) * K + cc * 8;

    const int lt = lane >> 3, lr8 = lane & 7;
    const uint32_t aRowOff = (uint32_t)((wm * 32 + (lt & 1) * 8 + lr8) * ROWB + (lt >> 1) * 16);
    const uint32_t bRowOff = (uint32_t)((wn * 16 + (lt >> 1) * 8 + lr8) * ROWB + (lt & 1) * 16);

    const int KC = K >> 5;

    #pragma unroll
    for (int s = 0; s < STAGES - 1; s++) {
        cpa16(sbase + s * STGB + dOff, ag + s * 32);
        cpa16(sbase + s * STGB + TILEB + dOff, bg + s * 32);
        CPA_COMMIT();
    }

    for (int kc = 0; kc < KC; kc++) {
        CPA_WAIT(STAGES - 2);          // stage kc ready
        __syncthreads();               // all readers of stage (kc-1) done -> safe to refill
        int pf = kc + STAGES - 1;
        if (pf < KC) {
            uint32_t sb = sbase + (pf % STAGES) * STGB;
            cpa16(sb + dOff, ag + (size_t)pf * 32);
            cpa16(sb + TILEB + dOff, bg + (size_t)pf * 32);
        }
        CPA_COMMIT();

        const uint32_t sA = sbase + (kc % STAGES) * STGB;
        const uint32_t sB = sA + TILEB;
        #pragma unroll
        for (int ks = 0; ks < 2; ks++) {
            uint32_t af[2][4], bf[2][2];
            #pragma unroll
            for (int mi = 0; mi < 2; mi++)
                ldsm4(af[mi][0], af[mi][1], af[mi][2], af[mi][3],
                      sA + aRowOff + mi * (16 * ROWB) + ks * 32);
            {
                uint32_t r0, r1, r2, r3;
                ldsm4(r0, r1, r2, r3, sB + bRowOff + ks * 32);
                bf[0][0] = r0; bf[0][1] = r1; bf[1][0] = r2; bf[1][1] = r3;
            }
            #pragma unroll
            for (int mi = 0; mi < 2; mi++)
                #pragma unroll
                for (int nj = 0; nj < 2; nj++) mma16(c[mi][nj], af[mi], bf[nj]);
        }
    }

    // ---- epilogue ----
    const float invs = 0.9999950000374997f;   // 1/sqrt(1+1e-5) eval-mode BN
    int mBase = m0 + wm * 32, nBase = n0 + wn * 16;
    #pragma unroll
    for (int mi = 0; mi < 2; mi++) {
        #pragma unroll
        for (int half = 0; half < 2; half++) {
            int m = mBase + mi * 16 + g + half * 8;
            float bsc = 1.f, bof = 0.f;
            if (EPI == EPI_BIAS_RES_BN) { bsc = bng[m & (NC - 1)] * invs; bof = bnb[m & (NC - 1)]; }
            #pragma unroll
            for (int nj = 0; nj < 2; nj++) {
                int n = nBase + nj * 8 + tg * 2;
                float x0 = c[mi][nj][half * 2 + 0];
                float x1 = c[mi][nj][half * 2 + 1];
                if (EPI != EPI_NONE) { x0 += bias[n]; x1 += bias[n + 1]; }
                if (EPI == EPI_BIAS_WPOS) {
                    const float* e = extra + (size_t)(m & (NC - 1)) * N + n;
                    x0 += e[0]; x1 += e[1];
                }
                if (EPI == EPI_BIAS_RES || EPI == EPI_BIAS_RES_BN) {
                    const float* e = extra + (size_t)m * N + n;
                    x0 += e[0]; x1 += e[1];
                }
                if (EPI == EPI_BIAS_GELU) {
                    x0 = 0.5f * x0 * (1.f + erff(x0 * 0.7071067811865475f));
                    x1 = 0.5f * x1 * (1.f + erff(x1 * 0.7071067811865475f));
                }
                if (EPI == EPI_BIAS_RES_BN) { x0 = x0 * bsc + bof; x1 = x1 * bsc + bof; }
                if (OUTM == OUT_F32 || OUTM == OUT_BOTH)
                    *(float2*)(C + (size_t)m * N + n) = make_float2(x0, x1);
                if (OUTM == OUT_F16 || OUTM == OUT_BOTH)
                    *(__half2*)(Ch + (size_t)m * N + n) = h2(x0, x1);
            }
        }
    }
}

// ===========================================================================
// all weight fp32->fp16 conversions, one launch (segment table, 4 elems/thread)
// ===========================================================================
__global__ void f2h_all(const float* __restrict__ emb, const float* __restrict__ vw1,
                        const float* __restrict__ vw2, const float* __restrict__ aw1,
                        const float* __restrict__ aw2, const float* __restrict__ wo,
                        __half* __restrict__ hEmb, __half* __restrict__ hVw1,
                        __half* __restrict__ hVw2, __half* __restrict__ hAw1,
                        __half* __restrict__ hAw2, __half* __restrict__ hWo) {
    long i = ((long)blockIdx.x * 256 + threadIdx.x) * 4;
    const float* s; __half* d; long off;
    if      (i < 262144L)  { s = emb; d = hEmb; off = i; }
    else if (i < 1835008L) { s = vw1; d = hVw1; off = i - 262144L; }
    else if (i < 3407872L) { s = vw2; d = hVw2; off = i - 1835008L; }
    else if (i < 4980736L) { s = aw1; d = hAw1; off = i - 3407872L; }
    else if (i < 6553600L) { s = aw2; d = hAw2; off = i - 4980736L; }
    else                   { s = wo;  d = hWo;  off = i - 6553600L; }
    float4 v = *(const float4*)(s + off);
    __half2* p = (__half2*)(d + off);
    p[0] = h2(v.x, v.y);
    p[1] = h2(v.z, v.w);
}

// ===========================================================================
// transpose + fp16: hT[z] = transpose(src_z), z: 0..2 Wk(l), 3..5 Wq(l), 6..8 Wv(l)
// ===========================================================================
__global__ void trans_f2h(const float* __restrict__ Wk, const float* __restrict__ Wq,
                          const float* __restrict__ Wv, __half* __restrict__ hT) {
    __shared__ float t[32][33];
    int z = blockIdx.z;
    const float* src = (z < 3) ? Wk + (size_t)z * SSQ
                     : (z < 6) ? Wq + (size_t)(z - 3) * SSQ
                               : Wv + (size_t)(z - 6) * SSQ;
    __half* dst = hT + (size_t)z * SSQ;
    int c0 = blockIdx.x * 32, r0 = blockIdx.y * 32;
    int tx = threadIdx.x, ty = threadIdx.y;
    #pragma unroll
    for (int i = 0; i < 4; i++)
        t[ty + i * 8][tx] = src[(size_t)(r0 + ty + i * 8) * NDM + c0 + tx];
    __syncthreads();
    #pragma unroll
    for (int i = 0; i < 4; i++)
        dst[(size_t)(c0 + ty + i * 8) * NDM + r0 + tx] = __float2half(t[tx][ty + i * 8]);
}

// ===========================================================================
// cv[l,n] = sum_j bq[l,j]*WkT[l; n,j]  (warp per n over contiguous fp16 row)
// ===========================================================================
__global__ void cv_pre(const float* __restrict__ bq, const __half* __restrict__ hT,
                       float* __restrict__ cv) {
    int l = blockIdx.y;
    int w = threadIdx.x >> 5, lane = threadIdx.x & 31;
    int n = blockIdx.x * 8 + w;
    const __half* wk = hT + (size_t)l * SSQ + (size_t)n * NDM;
    const float* b = bq + l * NDM;
    float s = 0.f;
    #pragma unroll 4
    for (int j = lane; j < NDM; j += 32) s = fmaf(__half2float(wk[j]), b[j], s);
    #pragma unroll
    for (int o = 16; o; o >>= 1) s += __shfl_xor_sync(0xffffffffu, s, o);
    if (!lane) cv[l * NDM + n] = s;
}
// ===========================================================================
// bvo[l,n] = Wo[n,:].bv + bo[n]       (warp per n; lanes stride the row)
// ===========================================================================
__global__ void bvo_pre(const float* __restrict__ bv, const float* __restrict__ bo,
                        const float* __restrict__ Wo, float* __restrict__ bvo) {
    int l = blockIdx.y;
    int w = threadIdx.x >> 5, lane = threadIdx.x & 31;
    int n = blockIdx.x * 8 + w;
    const float* wo = Wo + (size_t)l * SSQ + (size_t)n * NDM;
    const float* b  = bv + l * NDM;
    float s = 0.f;
    for (int j = lane; j < NDM; j += 32) s = fmaf(wo[j], b[j], s);
    #pragma unroll
    for (int o = 16; o; o >>= 1) s += __shfl_xor_sync(0xffffffffu, s, o);
    if (!lane) bvo[l * NDM + n] = s + bo[l * NDM + n];
}

// ===========================================================================
// trend conv + residual -> fp16 (B,C,T)
// ===========================================================================
__global__ void conv_residual_kernel(const float* __restrict__ inp,
                                     const float* __restrict__ w,
                                     const float* __restrict__ ldb,
                                     __half* __restrict__ R) {
    __shared__ float s[88][33];
    __shared__ float wk[NKS];
    int b = blockIdx.x, t0 = blockIdx.y * 64, c0 = blockIdx.z * 32;
    int tid = threadIdx.x;
    if (tid < NKS) wk[tid] = w[tid];
    for (int idx = tid; idx < 88 * 32; idx += 256) {
        int r = idx >> 5, c = idx & 31;
        int tg = t0 + r - 12;
        tg = min(max(tg, 0), NT - 1);
        s[r][c] = inp[((size_t)b * NT + tg) * NC + c0 + c];
    }
    __syncthreads();
    float lb = ldb[0];
    int lane = tid & 31, wy = tid >> 5;
    for (int half = 0; half < 2; ++half) {
        int ti = half * 32 + lane;
        for (int cg = 0; cg < 4; ++cg) {
            int ci = cg * 8 + wy;
            float acc = 0.f;
            #pragma unroll
            for (int k = 0; k < NKS; ++k) acc = fmaf(wk[k], s[ti + k][ci], acc);
            float v = s[ti + 12][ci] - (acc + lb);
            R[((size_t)b * NC + c0 + ci) * NT + t0 + ti] = __float2half(v);
        }
    }
}

// ===========================================================================
// row sums of X (varcor logits)
// ===========================================================================
__global__ void rowsum_kernel(const float* __restrict__ X, float* __restrict__ S) {
    int row = blockIdx.x * 8 + (threadIdx.x >> 5);
    int lane = threadIdx.x & 31;
    const float* xr = X + (size_t)row * NDM;
    float s = 0.f;
    for (int i = lane; i < NDM; i += 32) s += xr[i];
    #pragma unroll
    for (int o = 16; o; o >>= 1) s += __shfl_xor_sync(0xffffffffu, s, o);
    if (!lane) S[row] = s;
}

// ===========================================================================
// varcor softmax weights — warp per d, exps kept in regs (computed once).
// grid (NB, NC/8), 256 threads = 8 warps.
// ===========================================================================
__global__ void varcor_w_kernel(const float* __restrict__ S, float* __restrict__ Wt) {
    __shared__ float ss[NC];
    int b = blockIdx.x;
    int tid = threadIdx.x;
    if (tid < NC) ss[tid] = S[b * NC + tid];
    __syncthreads();
    int w = tid >> 5, lane = tid & 31;
    int d = blockIdx.y * 8 + w;
    const float VS = 8.6316746e-05f;            // 1/(512*sqrt(512))
    float sd = ss[d];
    float v4[4], mx = -1e30f;
    #pragma unroll
    for (int i = 0; i < 4; i++) {
        v4[i] = sd * ss[lane + i * 32];
        mx = fmaxf(mx, v4[i]);
    }
    #pragma unroll
    for (int o = 16; o; o >>= 1) mx = fmaxf(mx, __shfl_xor_sync(0xffffffffu, mx, o));
    float e4[4], ps = 0.f;
    #pragma unroll
    for (int i = 0; i < 4; i++) {
        e4[i] = __expf((v4[i] - mx) * VS);
        ps += e4[i];
    }
    #pragma unroll
    for (int o = 16; o; o >>= 1) ps += __shfl_xor_sync(0xffffffffu, ps, o);
    float rs = 1.f / ps;
    float* wr = Wt + ((size_t)b * NC + d) * NC;
    #pragma unroll
    for (int i = 0; i < 4; i++) wr[lane + i * 32] = e4[i] * rs;
}

// ===========================================================================
// varcor mix + residual + BN -> fp32 + fp16
// ===========================================================================
__global__ __launch_bounds__(512)
void varcor_mix_kernel(const float* __restrict__ X, const float* __restrict__ Wt,
                       const float* __restrict__ bng, const float* __restrict__ bnb,
                       float* __restrict__ Out, __half* __restrict__ hOut) {
    __shared__ float xs[NC][64];
    int b = blockIdx.x, j0 = blockIdx.y * 64;
    int tid = threadIdx.x;
    const float* xb = X + (size_t)b * NC * NDM;
    #pragma unroll
    for (int i = 0; i < 4; i++) {
        int f = tid + i * 512;
        int e = f >> 4, q = f & 15;
        *(float4*)&xs[e][q * 4] = ((const float4*)(xb + (size_t)e * NDM + j0))[q];
    }
    __syncthreads();

    int d = tid >> 2, q = tid & 3, jb = q * 16;
    const float* wr = Wt + ((size_t)b * NC + d) * NC;
    float4 acc[4];
    #pragma unroll
    for (int t = 0; t < 4; t++) acc[t] = make_float4(0.f, 0.f, 0.f, 0.f);
    #pragma unroll 4
    for (int e = 0; e < NC; e++) {
        float w = __ldg(wr + e);
        #pragma unroll
        for (int t = 0; t < 4; t++) {
            float4 xv = *(float4*)&xs[e][jb + t * 4];
            acc[t].x = fmaf(w, xv.x, acc[t].x);
            acc[t].y = fmaf(w, xv.y, acc[t].y);
            acc[t].z = fmaf(w, xv.z, acc[t].z);
            acc[t].w = fmaf(w, xv.w, acc[t].w);
        }
    }
    const float invs = 0.9999950000374997f;
    float bsc = bng[d] * invs, bof = bnb[d];
    size_t base = ((size_t)b * NC + d) * NDM + j0 + jb;
    #pragma unroll
    for (int t = 0; t < 4; t++) {
        float4 xv = *(float4*)&xs[d][jb + t * 4];
        float4 o;
        o.x = (acc[t].x + xv.x) * bsc + bof;
        o.y = (acc[t].y + xv.y) * bsc + bof;
        o.z = (acc[t].z + xv.z) * bsc + bof;
        o.w = (acc[t].w + xv.w) * bsc + bof;
        *(float4*)(Out + base + t * 4) = o;
        *(__half2*)(hOut + base + t * 4)     = h2(o.x, o.y);
        *(__half2*)(hOut + base + t * 4 + 2) = h2(o.z, o.w);
    }
}

// ===========================================================================
// auto-attn shift scores + softmax + weighted shift sum, fp16 in -> fp16 out
// ===========================================================================
__global__ void autoshift_kernel(const __half* __restrict__ hX, const __half* __restrict__ hU,
                                 __half* __restrict__ XW) {
    __shared__ float xr[NDM];
    __shared__ float red[8][4];
    int row = blockIdx.x, tid = threadIdx.x;
    // load x row (fp16 -> fp32 smem)
    {
        const __half2* xp = (const __half2*)(hX + (size_t)row * NDM) + tid * 2;
        float2 a = __half22float2(xp[0]);
        float2 b = __half22float2(xp[1]);
        ((float4*)xr)[tid] = make_float4(a.x, a.y, b.x, b.y);
    }
    float4 uv;
    {
        const __half2* up = (const __half2*)(hU + (size_t)row * NDM) + tid * 2;
        float2 a = __half22float2(up[0]);
        float2 b = __half22float2(up[1]);
        uv = make_float4(a.x, a.y, b.x, b.y);
    }
    __syncthreads();

    float sc[8];
    #pragma unroll
    for (int s = 0; s < 8; s++) {
        float4 x4 = ((float4*)xr)[(tid + 16 * s) & 127];
        sc[s] = uv.x * x4.x + uv.y * x4.y + uv.z * x4.z + uv.w * x4.w;
    }
    int lane = tid & 31, wid = tid >> 5;
    #pragma unroll
    for (int s = 0; s < 8; s++) {
        float v = sc[s];
        #pragma unroll
        for (int o = 16; o; o >>= 1) v += __shfl_xor_sync(0xffffffffu, v, o);
        if (!lane) red[s][wid] = v;
    }
    __syncthreads();
    const float rsq = 0.04419417382415922f;    // DM^-0.5
    float lg[8], mx = -1e30f;
    #pragma unroll
    for (int s = 0; s < 8; s++) {
        lg[s] = (red[s][0] + red[s][1] + red[s][2] + red[s][3]) * rsq;
        mx = fmaxf(mx, lg[s]);
    }
    float w[8], sum = 0.f;
    #pragma unroll
    for (int s = 0; s < 8; s++) { w[s] = __expf(lg[s] - mx); sum += w[s]; }
    float rs = 1.f / sum;
    float4 o = make_float4(0.f, 0.f, 0.f, 0.f);
    #pragma unroll
    for (int s = 0; s < 8; s++) {
        float4 x4 = ((float4*)xr)[(tid + 16 * s) & 127];
        float ws = w[s] * rs;
        o.x = fmaf(ws, x4.x, o.x); o.y = fmaf(ws, x4.y, o.y);
        o.z = fmaf(ws, x4.z, o.z); o.w = fmaf(ws, x4.w, o.w);
    }
    __half2* op = (__half2*)(XW + (size_t)row * NDM) + tid * 2;
    op[0] = h2(o.x, o.y);
    op[1] = h2(o.z, o.w);
}

// ===========================================================================
// LayerNorm; optional fp16 twin + fused rowsum of output
// ===========================================================================
template<bool SUM, bool H16>
__global__ void layernorm_kernel(const float* __restrict__ In, const float* __restrict__ g,
                                 const float* __restrict__ bb, float* __restrict__ Out,
                                 __half* __restrict__ hOut, float* __restrict__ S) {
    int row = blockIdx.x, tid = threadIdx.x;
    const float4 v = ((const float4*)(In + (size_t)row * NDM))[tid];
    float s  = v.x + v.y + v.z + v.w;
    float s2 = v.x * v.x + v.y * v.y + v.z * v.z + v.w * v.w;
    #pragma unroll
    for (int o = 16; o; o >>= 1) {
        s  += __shfl_xor_sync(0xffffffffu, s, o);
        s2 += __shfl_xor_sync(0xffffffffu, s2, o);
    }
    __shared__ float ws[4], ws2[4], wo[4];
    int lane = tid & 31, wid = tid >> 5;
    if (!lane) { ws[wid] = s; ws2[wid] = s2; }
    __syncthreads();
    s  = ws[0] + ws[1] + ws[2] + ws[3];
    s2 = ws2[0] + ws2[1] + ws2[2] + ws2[3];
    float mean = s * (1.f / NDM);
    float var  = s2 * (1.f / NDM) - mean * mean;
    float inv  = rsqrtf(var + 1e-5f);
    float4 gv = ((const float4*)g)[tid], bv = ((const float4*)bb)[tid];
    float4 o;
    o.x = (v.x - mean) * inv * gv.x + bv.x;
    o.y = (v.y - mean) * inv * gv.y + bv.y;
    o.z = (v.z - mean) * inv * gv.z + bv.z;
    o.w = (v.w - mean) * inv * gv.w + bv.w;
    ((float4*)(Out + (size_t)row * NDM))[tid] = o;
    if (H16) {
        __half2* op = (__half2*)(hOut + (size_t)row * NDM) + tid * 2;
        op[0] = h2(o.x, o.y);
        op[1] = h2(o.z, o.w);
    }
    if (SUM) {
        float os = o.x + o.y + o.z + o.w;
        #pragma unroll
        for (int off = 16; off; off >>= 1) os += __shfl_xor_sync(0xffffffffu, os, off);
        if (!lane) wo[wid] = os;
        __syncthreads();
        if (tid == 0) S[row] = wo[0] + wo[1] + wo[2] + wo[3];
    }
}

// ===========================================================================
extern "C" void kernel_launch(void* const* d_in, const int* in_sizes, int n_in,
                              void* d_out, int out_size) {
    (void)in_sizes; (void)n_in; (void)out_size;
    const float* inp     = (const float*)d_in[0];
    const float* ld_w    = (const float*)d_in[1];
    const float* ld_b    = (const float*)d_in[2];
    const float* emb_W   = (const float*)d_in[3];
    const float* emb_b   = (const float*)d_in[4];
    const float* W_pos   = (const float*)d_in[5];
    const float* vc_bn_g = (const float*)d_in[6];
    const float* vc_bn_b = (const float*)d_in[7];
    const float* vc_ln_g = (const float*)d_in[8];
    const float* vc_ln_b = (const float*)d_in[9];
    const float* vc_W1   = (const float*)d_in[10];
    const float* vc_b1   = (const float*)d_in[11];
    const float* vc_W2   = (const float*)d_in[12];
    const float* vc_b2   = (const float*)d_in[13];
    const float* aa_Wq   = (const float*)d_in[14];
    const float* aa_bq   = (const float*)d_in[15];
    const float* aa_Wk   = (const float*)d_in[16];
    // d_in[17] = aa_bk: cancels in the shift-softmax (constant logit offset)
    const float* aa_Wv   = (const float*)d_in[18];
    const float* aa_bv   = (const float*)d_in[19];
    const float* aa_Wo   = (const float*)d_in[20];
    const float* aa_bo   = (const float*)d_in[21];
    const float* aa_bn_g = (const float*)d_in[22];
    const float* aa_bn_b = (const float*)d_in[23];
    const float* aa_ln_g = (const float*)d_in[24];
    const float* aa_ln_b = (const float*)d_in[25];
    const float* aa_W1   = (const float*)d_in[26];
    const float* aa_b1   = (const float*)d_in[27];
    const float* aa_W2   = (const float*)d_in[28];
    const float* aa_b2   = (const float*)d_in[29];

    float *X, *B2, *B3, *S, *WT, *CV, *BVO;
    __half *hR, *hX, *hB1, *hB2, *hB3;
    __half *hEmb, *hVcW1, *hVcW2, *hAaW1, *hAaW2, *hWo, *hT, *hWQK, *hWvo;
    cudaGetSymbolAddress((void**)&X,    g_X);
    cudaGetSymbolAddress((void**)&B2,   g_B2);
    cudaGetSymbolAddress((void**)&B3,   g_B3);
    cudaGetSymbolAddress((void**)&S,    g_S);
    cudaGetSymbolAddress((void**)&WT,   g_W);
    cudaGetSymbolAddress((void**)&CV,   g_CV);
    cudaGetSymbolAddress((void**)&BVO,  g_BVO);
    cudaGetSymbolAddress((void**)&hR,   g_hR);
    cudaGetSymbolAddress((void**)&hX,   g_hX);
    cudaGetSymbolAddress((void**)&hB1,  g_hB1);
    cudaGetSymbolAddress((void**)&hB2,  g_hB2);
    cudaGetSymbolAddress((void**)&hB3,  g_hB3);
    cudaGetSymbolAddress((void**)&hEmb, g_hEmb);
    cudaGetSymbolAddress((void**)&hVcW1,g_hVcW1);
    cudaGetSymbolAddress((void**)&hVcW2,g_hVcW2);
    cudaGetSymbolAddress((void**)&hAaW1,g_hAaW1);
    cudaGetSymbolAddress((void**)&hAaW2,g_hAaW2);
    cudaGetSymbolAddress((void**)&hWo,  g_hWo);
    cudaGetSymbolAddress((void**)&hT,   g_hT);
    cudaGetSymbolAddress((void**)&hWQK, g_hWQK);
    cudaGetSymbolAddress((void**)&hWvo, g_hWvo);
    float* OUT = (float*)d_out;

    dim3 g512(8, 32);    // N=512 GEMM: 256 blocks
    dim3 g1024(16, 32);  // N=1024 GEMM: 512 blocks
    dim3 gpre(8, 8, 3);  // 512x512x512 precompute, z = layer

    // ---- preamble (x-independent precompute + conversions) ----
    f2h_all<<<7168, 256>>>(emb_W, vc_W1, vc_W2, aa_W1, aa_W2, aa_Wo,
                           hEmb, hVcW1, hVcW2, hAaW1, hAaW2, hWo);
    trans_f2h<<<dim3(16, 16, 9), dim3(32, 8)>>>(aa_Wk, aa_Wq, aa_Wv, hT);
    conv_residual_kernel<<<dim3(NB, NT / 64, NC / 32), 256>>>(inp, ld_w, ld_b, hR);
    cv_pre<<<dim3(NDM / 8, NL), 256>>>(aa_bq, hT, CV);   // after trans_f2h (reads WkT)
    bvo_pre<<<dim3(NDM / 8, NL), 256>>>(aa_bv, aa_bo, aa_Wo, BVO);
    // WQK[l] = WkT[l] x WqT[l] ;  Wvo[l] = Wo[l] x WvT[l]
    cg_gemm<EPI_NONE, OUT_F16><<<gpre, 256>>>(hT, hT + 3 * SSQ, nullptr, nullptr,
                                              nullptr, nullptr, nullptr, hWQK,
                                              NDM, NDM, NDM, SSQ, SSQ, SSQ);
    cg_gemm<EPI_NONE, OUT_F16><<<gpre, 256>>>(hWo, hT + 6 * SSQ, nullptr, nullptr,
                                              nullptr, nullptr, nullptr, hWvo,
                                              NDM, NDM, NDM, SSQ, SSQ, SSQ);
    // embedding: X = R @ emb_W.T + emb_b + W_pos
    cg_gemm<EPI_BIAS_WPOS, OUT_F32><<<g512, 256>>>(hR, hEmb, emb_b, W_pos,
                                                   nullptr, nullptr, X, nullptr,
                                                   NM, NDM, NT, 0, 0, 0);
    rowsum_kernel<<<NM / 8, 256>>>(X, S);

    for (int l = 0; l < NL; ++l) {
        const size_t SH = (size_t)NH * NDM;
        // ---- VarCor block ----
        varcor_w_kernel<<<dim3(NB, NC / 8), 256>>>(S, WT);
        varcor_mix_kernel<<<dim3(NB, NDM / 64), 512>>>(X, WT, vc_bn_g + l * NC, vc_bn_b + l * NC,
                                                       B2, hB2);
        cg_gemm<EPI_BIAS_GELU, OUT_F16><<<g1024, 256>>>(hB2, hVcW1 + l * SH, vc_b1 + l * NH,
                                                        nullptr, nullptr, nullptr,
                                                        nullptr, hB1, NM, NH, NDM, 0, 0, 0);
        cg_gemm<EPI_BIAS_RES, OUT_F32><<<g512, 256>>>(hB1, hVcW2 + l * SH, vc_b2 + l * NDM,
                                                      B2, nullptr, nullptr,
                                                      B3, nullptr, NM, NDM, NH, 0, 0, 0);
        layernorm_kernel<false, true><<<NM, 128>>>(B3, vc_ln_g + l * NDM, vc_ln_b + l * NDM,
                                                   X, hX, nullptr);

        // ---- Auto-attention block ----
        // u = x @ WQK^T + cv  -> fp16
        cg_gemm<EPI_BIAS, OUT_F16><<<g512, 256>>>(hX, hWQK + (size_t)l * SSQ, CV + l * NDM,
                                                  nullptr, nullptr, nullptr,
                                                  nullptr, hB3, NM, NDM, NDM, 0, 0, 0);
        autoshift_kernel<<<NM, 128>>>(hX, hB3, hB2);
        // fused V+O projection: out = xw @ Wvo^T + bvo ; + x residual ; BN
        cg_gemm<EPI_BIAS_RES_BN, OUT_BOTH><<<g512, 256>>>(hB2, hWvo + (size_t)l * SSQ,
                                                          BVO + l * NDM, X,
                                                          aa_bn_g + l * NC, aa_bn_b + l * NC,
                                                          B2, hB3, NM, NDM, NDM, 0, 0, 0);
        cg_gemm<EPI_BIAS_GELU, OUT_F16><<<g1024, 256>>>(hB3, hAaW1 + l * SH, aa_b1 + l * NH,
                                                        nullptr, nullptr, nullptr,
                                                        nullptr, hB1, NM, NH, NDM, 0, 0, 0);
        cg_gemm<EPI_BIAS_RES, OUT_F32><<<g512, 256>>>(hB1, hAaW2 + l * SH, aa_b2 + l * NDM,
                                                      B2, nullptr, nullptr,
                                                      B3, nullptr, NM, NDM, NH, 0, 0, 0);
        if (l == NL - 1) {
            layernorm_kernel<false, false><<<NM, 128>>>(B3, aa_ln_g + l * NDM, aa_ln_b + l * NDM,
                                                        OUT, nullptr, nullptr);
        } else {
            layernorm_kernel<true, true><<<NM, 128>>>(B3, aa_ln_g + l * NDM, aa_ln_b + l * NDM,
                                                      X, hX, S);
        }
    }
}